// round 1
// baseline (speedup 1.0000x reference)
#include <cuda_runtime.h>
#include <cstdint>

#define BATCH 2
#define SEQ   1024
#define HID   4096
#define NH    32
#define NKV   8
#define HD    128
#define NREP  4

// ---------------- scratch (device globals; no allocation allowed) ----------------
__device__ float g_q[BATCH * SEQ * NH * HD];      // [b, s, h, d]
__device__ float g_k[BATCH * SEQ * NKV * HD];     // [b, s, kh, d]
__device__ float g_v[BATCH * SEQ * NKV * HD];
__device__ float g_attn[BATCH * SEQ * NH * HD];   // [b, s, h, d]

// ---------------- helpers ----------------
__device__ __forceinline__ float f2tf32(float x) {
    uint32_t u;
    asm("cvt.rna.tf32.f32 %0, %1;" : "=r"(u) : "f"(x));
    return __uint_as_float(u);
}
__device__ __forceinline__ uint32_t fu(float x) { return __float_as_uint(x); }

// mma.sync m16n8k8 tf32: D(16x8,f32) += A(16x8,row) * B(8x8,col)
__device__ __forceinline__ void mma8(float* d, const uint32_t* a, const uint32_t* b) {
    asm volatile(
        "mma.sync.aligned.m16n8k8.row.col.f32.tf32.tf32.f32 "
        "{%0,%1,%2,%3}, {%4,%5,%6,%7}, {%8,%9}, {%0,%1,%2,%3};\n"
        : "+f"(d[0]), "+f"(d[1]), "+f"(d[2]), "+f"(d[3])
        : "r"(a[0]), "r"(a[1]), "r"(a[2]), "r"(a[3]), "r"(b[0]), "r"(b[1]));
}

// ---------------- GEMM: C[M,N] = A[M,K] @ W[K,N], all row-major fp32, tf32 mma ----
#define GBM 128
#define GBN 128
#define GBK 32
#define ASTR (GBK + 4)   // 36
#define BSTR (GBN + 4)   // 132
#define ASZ  (GBM * ASTR)
#define BSZ  (GBK * BSTR)
#define GEMM_SMEM ((2 * ASZ + 2 * BSZ) * 4)

__global__ __launch_bounds__(256)
void gemm_tf32(const float* __restrict__ A, const float* __restrict__ W,
               float* __restrict__ C, int M, int N, int K)
{
    extern __shared__ float sm[];
    float* As = sm;               // [2][128][36]
    float* Bs = sm + 2 * ASZ;     // [2][32][132]

    const int tid  = threadIdx.x;
    const int lane = tid & 31, warp = tid >> 5;
    const int wm = warp >> 2, wn = warp & 3;   // warp grid 2(m) x 4(n)
    const int g = lane >> 2, t = lane & 3;
    const int m0 = blockIdx.y * GBM, n0 = blockIdx.x * GBN;

    float acc[4][4][4];
#pragma unroll
    for (int i = 0; i < 4; i++)
#pragma unroll
        for (int j = 0; j < 4; j++)
#pragma unroll
            for (int r = 0; r < 4; r++) acc[i][j][r] = 0.f;

    auto loadTiles = [&](int st, int kt) {
        const float* Ag = A + (size_t)m0 * K + kt * GBK;
#pragma unroll
        for (int i = 0; i < 4; i++) {
            int l = i * 256 + tid;
            int r = l >> 3, c = (l & 7) << 2;
            float4 v = *reinterpret_cast<const float4*>(Ag + (size_t)r * K + c);
            float4 w4;
            w4.x = f2tf32(v.x); w4.y = f2tf32(v.y); w4.z = f2tf32(v.z); w4.w = f2tf32(v.w);
            *reinterpret_cast<float4*>(&As[st * ASZ + r * ASTR + c]) = w4;
        }
        const float* Wg = W + (size_t)(kt * GBK) * N + n0;
#pragma unroll
        for (int i = 0; i < 4; i++) {
            int l = i * 256 + tid;
            int r = l >> 5, c = (l & 31) << 2;
            float4 v = *reinterpret_cast<const float4*>(Wg + (size_t)r * N + c);
            float4 w4;
            w4.x = f2tf32(v.x); w4.y = f2tf32(v.y); w4.z = f2tf32(v.z); w4.w = f2tf32(v.w);
            *reinterpret_cast<float4*>(&Bs[st * BSZ + r * BSTR + c]) = w4;
        }
    };

    loadTiles(0, 0);
    __syncthreads();
    const int KT = K / GBK;
    for (int kt = 0; kt < KT; kt++) {
        int cur = kt & 1;
        if (kt + 1 < KT) loadTiles(cur ^ 1, kt + 1);
        const float* Asc = As + cur * ASZ;
        const float* Bsc = Bs + cur * BSZ;
#pragma unroll
        for (int kk = 0; kk < GBK / 8; kk++) {
            uint32_t af[4][4];
#pragma unroll
            for (int mi = 0; mi < 4; mi++) {
                int r = wm * 64 + mi * 16 + g;
                int c = kk * 8 + t;
                af[mi][0] = fu(Asc[r * ASTR + c]);
                af[mi][1] = fu(Asc[(r + 8) * ASTR + c]);
                af[mi][2] = fu(Asc[r * ASTR + c + 4]);
                af[mi][3] = fu(Asc[(r + 8) * ASTR + c + 4]);
            }
            uint32_t bf[4][2];
#pragma unroll
            for (int ni = 0; ni < 4; ni++) {
                int c = wn * 32 + ni * 8 + g;
                int r = kk * 8 + t;
                bf[ni][0] = fu(Bsc[r * BSTR + c]);
                bf[ni][1] = fu(Bsc[(r + 4) * BSTR + c]);
            }
#pragma unroll
            for (int mi = 0; mi < 4; mi++)
#pragma unroll
                for (int ni = 0; ni < 4; ni++)
                    mma8(acc[mi][ni], af[mi], bf[ni]);
        }
        __syncthreads();
    }

#pragma unroll
    for (int mi = 0; mi < 4; mi++) {
        int row = m0 + wm * 64 + mi * 16 + g;
#pragma unroll
        for (int ni = 0; ni < 4; ni++) {
            int col = n0 + wn * 32 + ni * 8 + t * 2;
            *reinterpret_cast<float2*>(&C[(size_t)row * N + col]) =
                make_float2(acc[mi][ni][0], acc[mi][ni][1]);
            *reinterpret_cast<float2*>(&C[(size_t)(row + 8) * N + col]) =
                make_float2(acc[mi][ni][2], acc[mi][ni][3]);
        }
    }
}

// ---------------- RoPE (in place) ----------------
__global__ void rope_kernel(float* __restrict__ x, const float* __restrict__ cosb,
                            const float* __restrict__ sinb, int nheads, int total)
{
    int i = blockIdx.x * blockDim.x + threadIdx.x;
    if (i >= total) return;
    int dh = i & 63;
    int h  = (i >> 6) % nheads;
    int bs = (i >> 6) / nheads;                 // b*SEQ + s
    float* p = x + ((size_t)bs * nheads + h) * HD + dh;
    float x1 = p[0], x2 = p[64];
    const float* cb = cosb + (size_t)bs * HD;
    const float* sb = sinb + (size_t)bs * HD;
    p[0]  = x1 * cb[dh]      - x2 * sb[dh];
    p[64] = x2 * cb[dh + 64] + x1 * sb[dh + 64];
}

// ---------------- flash attention (causal, GQA, online softmax, tf32 mma) --------
#define FBQ 128
#define FBK 64
#define QSTR 132
#define KSTR 132
#define VSTR 132
#define PSTR 68
#define FLASH_SMEM ((FBQ * QSTR + FBK * KSTR + FBK * VSTR + FBQ * PSTR) * 4)

__global__ __launch_bounds__(256)
void flash_kernel()
{
    extern __shared__ float sm[];
    float* Qs = sm;                     // [128][132]
    float* Ks = Qs + FBQ * QSTR;        // [64][132]
    float* Vs = Ks + FBK * KSTR;        // [64][132]
    float* Ps = Vs + FBK * VSTR;        // [128][68]

    const int tid  = threadIdx.x;
    const int lane = tid & 31, warp = tid >> 5;
    const int g = lane >> 2, t = lane & 3;
    const int qt = blockIdx.x, h = blockIdx.y, b = blockIdx.z;
    const int q0 = qt * FBQ;
    const int kh = h / NREP;
    const int r0 = warp * 16;   // warp owns rows [r0, r0+16)

    // load Q tile (tf32)
    const float* Qg = g_q + (((size_t)b * SEQ + q0) * NH + h) * HD;
#pragma unroll
    for (int i = 0; i < 16; i++) {
        int l = i * 256 + tid;
        int r = l >> 5, c = (l & 31) << 2;
        float4 v = *reinterpret_cast<const float4*>(Qg + (size_t)r * NH * HD + c);
        v.x = f2tf32(v.x); v.y = f2tf32(v.y); v.z = f2tf32(v.z); v.w = f2tf32(v.w);
        *reinterpret_cast<float4*>(&Qs[r * QSTR + c]) = v;
    }

    float o[16][4];
#pragma unroll
    for (int n = 0; n < 16; n++)
#pragma unroll
        for (int r = 0; r < 4; r++) o[n][r] = 0.f;
    float mrow[2] = {-1e30f, -1e30f};
    float lrow[2] = {0.f, 0.f};

    const int nkt = qt * 2 + 2;   // tiles up to and including the diagonal
    for (int kt = 0; kt < nkt; kt++) {
        const int k0 = kt * FBK;
        __syncthreads();  // prior Ks/Vs use done (and Qs ready on first iter)

        const float* Kg = g_k + (((size_t)b * SEQ + k0) * NKV + kh) * HD;
        const float* Vg = g_v + (((size_t)b * SEQ + k0) * NKV + kh) * HD;
#pragma unroll
        for (int i = 0; i < 8; i++) {
            int l = i * 256 + tid;
            int r = l >> 5, c = (l & 31) << 2;
            float4 v = *reinterpret_cast<const float4*>(Kg + (size_t)r * NKV * HD + c);
            v.x = f2tf32(v.x); v.y = f2tf32(v.y); v.z = f2tf32(v.z); v.w = f2tf32(v.w);
            *reinterpret_cast<float4*>(&Ks[r * KSTR + c]) = v;
            float4 w = *reinterpret_cast<const float4*>(Vg + (size_t)r * NKV * HD + c);
            w.x = f2tf32(w.x); w.y = f2tf32(w.y); w.z = f2tf32(w.z); w.w = f2tf32(w.w);
            *reinterpret_cast<float4*>(&Vs[r * VSTR + c]) = w;
        }
        __syncthreads();

        // S = Q @ K^T   (warp: 16 x 64, k-dim = 128)
        float s[8][4];
#pragma unroll
        for (int j = 0; j < 8; j++)
#pragma unroll
            for (int r = 0; r < 4; r++) s[j][r] = 0.f;
#pragma unroll
        for (int kk = 0; kk < 16; kk++) {
            uint32_t af[4];
            int rr = r0 + g, cc = kk * 8 + t;
            af[0] = fu(Qs[rr * QSTR + cc]);
            af[1] = fu(Qs[(rr + 8) * QSTR + cc]);
            af[2] = fu(Qs[rr * QSTR + cc + 4]);
            af[3] = fu(Qs[(rr + 8) * QSTR + cc + 4]);
#pragma unroll
            for (int j = 0; j < 8; j++) {
                uint32_t bf[2];
                int kr = j * 8 + g;
                bf[0] = fu(Ks[kr * KSTR + cc]);
                bf[1] = fu(Ks[kr * KSTR + cc + 4]);
                mma8(s[j], af, bf);
            }
        }

        // online softmax (rows warp-local; reduce over 4 lanes sharing a row)
        const float SCALE = 0.08838834764831845f;  // 1/sqrt(128)
        const int row_lo = q0 + r0 + g;
        float nm[2] = {mrow[0], mrow[1]};
#pragma unroll
        for (int j = 0; j < 8; j++) {
            int col = k0 + j * 8 + 2 * t;
            s[j][0] = (col     <= row_lo)     ? s[j][0] * SCALE : -1e30f;
            s[j][1] = (col + 1 <= row_lo)     ? s[j][1] * SCALE : -1e30f;
            s[j][2] = (col     <= row_lo + 8) ? s[j][2] * SCALE : -1e30f;
            s[j][3] = (col + 1 <= row_lo + 8) ? s[j][3] * SCALE : -1e30f;
            nm[0] = fmaxf(nm[0], fmaxf(s[j][0], s[j][1]));
            nm[1] = fmaxf(nm[1], fmaxf(s[j][2], s[j][3]));
        }
#pragma unroll
        for (int d = 1; d < 4; d <<= 1) {
            nm[0] = fmaxf(nm[0], __shfl_xor_sync(0xffffffffu, nm[0], d));
            nm[1] = fmaxf(nm[1], __shfl_xor_sync(0xffffffffu, nm[1], d));
        }
        float alpha0 = __expf(mrow[0] - nm[0]);
        float alpha1 = __expf(mrow[1] - nm[1]);
        mrow[0] = nm[0]; mrow[1] = nm[1];
        float rs0 = 0.f, rs1 = 0.f;
#pragma unroll
        for (int j = 0; j < 8; j++) {
            s[j][0] = __expf(s[j][0] - nm[0]);
            s[j][1] = __expf(s[j][1] - nm[0]);
            s[j][2] = __expf(s[j][2] - nm[1]);
            s[j][3] = __expf(s[j][3] - nm[1]);
            rs0 += s[j][0] + s[j][1];
            rs1 += s[j][2] + s[j][3];
            int pr = r0 + g, pc = j * 8 + 2 * t;
            *reinterpret_cast<float2*>(&Ps[pr * PSTR + pc]) =
                make_float2(f2tf32(s[j][0]), f2tf32(s[j][1]));
            *reinterpret_cast<float2*>(&Ps[(pr + 8) * PSTR + pc]) =
                make_float2(f2tf32(s[j][2]), f2tf32(s[j][3]));
        }
#pragma unroll
        for (int d = 1; d < 4; d <<= 1) {
            rs0 += __shfl_xor_sync(0xffffffffu, rs0, d);
            rs1 += __shfl_xor_sync(0xffffffffu, rs1, d);
        }
        lrow[0] = lrow[0] * alpha0 + rs0;
        lrow[1] = lrow[1] * alpha1 + rs1;
#pragma unroll
        for (int n = 0; n < 16; n++) {
            o[n][0] *= alpha0; o[n][1] *= alpha0;
            o[n][2] *= alpha1; o[n][3] *= alpha1;
        }
        __syncwarp();   // make Ps writes visible across the warp

        // O += P @ V   (warp: 16 x 128, k-dim = 64)
#pragma unroll
        for (int kk = 0; kk < 8; kk++) {
            uint32_t af[4];
            int pr = r0 + g, pc = kk * 8 + t;
            af[0] = fu(Ps[pr * PSTR + pc]);
            af[1] = fu(Ps[(pr + 8) * PSTR + pc]);
            af[2] = fu(Ps[pr * PSTR + pc + 4]);
            af[3] = fu(Ps[(pr + 8) * PSTR + pc + 4]);
#pragma unroll
            for (int n = 0; n < 16; n++) {
                uint32_t bf[2];
                int vr = kk * 8 + t, vc = n * 8 + g;
                bf[0] = fu(Vs[vr * VSTR + vc]);
                bf[1] = fu(Vs[(vr + 4) * VSTR + vc]);
                mma8(o[n], af, bf);
            }
        }
    }

    // normalize and write [b, s, h, d]
    float inv0 = 1.f / lrow[0], inv1 = 1.f / lrow[1];
    int srow = q0 + r0 + g;
    float* Og = g_attn + (((size_t)b * SEQ + srow) * NH + h) * HD;
#pragma unroll
    for (int n = 0; n < 16; n++) {
        int c = n * 8 + 2 * t;
        *reinterpret_cast<float2*>(&Og[c]) =
            make_float2(o[n][0] * inv0, o[n][1] * inv0);
        *reinterpret_cast<float2*>(&Og[(size_t)8 * NH * HD + c]) =
            make_float2(o[n][2] * inv1, o[n][3] * inv1);
    }
}

// ---------------- launch ----------------
extern "C" void kernel_launch(void* const* d_in, const int* in_sizes, int n_in,
                              void* d_out, int out_size)
{
    const float* hs   = (const float*)d_in[0];
    const float* cosb = (const float*)d_in[1];
    const float* sinb = (const float*)d_in[2];
    // d_in[3] = attention_mask (pure causal; applied analytically in-kernel)
    const float* Wq = (const float*)d_in[4];
    const float* Wk = (const float*)d_in[5];
    const float* Wv = (const float*)d_in[6];
    const float* Wo = (const float*)d_in[7];
    float* out = (float*)d_out;

    float *qp, *kp, *vp, *ap;
    cudaGetSymbolAddress((void**)&qp, g_q);
    cudaGetSymbolAddress((void**)&kp, g_k);
    cudaGetSymbolAddress((void**)&vp, g_v);
    cudaGetSymbolAddress((void**)&ap, g_attn);

    cudaFuncSetAttribute(gemm_tf32, cudaFuncAttributeMaxDynamicSharedMemorySize, GEMM_SMEM);
    cudaFuncSetAttribute(flash_kernel, cudaFuncAttributeMaxDynamicSharedMemorySize, FLASH_SMEM);

    const int M = BATCH * SEQ;

    gemm_tf32<<<dim3((NH * HD) / GBN, M / GBM), 256, GEMM_SMEM>>>(hs, Wq, qp, M, NH * HD, HID);
    gemm_tf32<<<dim3((NKV * HD) / GBN, M / GBM), 256, GEMM_SMEM>>>(hs, Wk, kp, M, NKV * HD, HID);
    gemm_tf32<<<dim3((NKV * HD) / GBN, M / GBM), 256, GEMM_SMEM>>>(hs, Wv, vp, M, NKV * HD, HID);

    int totq = BATCH * SEQ * NH * 64;
    rope_kernel<<<(totq + 255) / 256, 256>>>(qp, cosb, sinb, NH, totq);
    int totk = BATCH * SEQ * NKV * 64;
    rope_kernel<<<(totk + 255) / 256, 256>>>(kp, cosb, sinb, NKV, totk);

    flash_kernel<<<dim3(SEQ / FBQ, NH, BATCH), 256, FLASH_SMEM>>>();

    gemm_tf32<<<dim3(HID / GBN, M / GBM), 256, GEMM_SMEM>>>(ap, Wo, out, M, HID, HID);
}

// round 3
// speedup vs baseline: 1.1255x; 1.1255x over previous
#include <cuda_runtime.h>
#include <cstdint>

#define BATCH 2
#define SEQ   1024
#define HID   4096
#define NH    32
#define NKV   8
#define HD    128
#define NREP  4
#define QKV_N (NH * HD + 2 * NKV * HD)   // 6144
#define QKV_LD QKV_N
#define KDIM  4096

// ---------------- scratch (device globals; no allocation allowed) ----------------
__device__ float g_hs  [BATCH * SEQ * HID];        // hidden_states, tf32-rounded
__device__ float g_wqkv[KDIM * QKV_N];             // [K, 6144] = [Wq|Wk|Wv], tf32
__device__ float g_wo  [KDIM * HID];               // Wo [K,N], tf32
__device__ float g_qkv [BATCH * SEQ * QKV_N];      // per row: q(4096)|k(1024)|v(1024), tf32
__device__ float g_attn[BATCH * SEQ * NH * HD];    // [b*s, 4096], tf32

// ---------------- helpers ----------------
__device__ __forceinline__ float f2tf32(float x) {
    uint32_t u;
    asm("cvt.rna.tf32.f32 %0, %1;" : "=r"(u) : "f"(x));
    return __uint_as_float(u);
}
__device__ __forceinline__ uint32_t fu(float x) { return __float_as_uint(x); }

__device__ __forceinline__ uint32_t smem_u32(const void* p) {
    uint32_t a;
    asm("{ .reg .u64 t; cvta.to.shared.u64 t, %1; cvt.u32.u64 %0, t; }" : "=r"(a) : "l"(p));
    return a;
}
__device__ __forceinline__ void cp16(uint32_t dst, const void* src) {
    asm volatile("cp.async.cg.shared.global [%0], [%1], 16;" :: "r"(dst), "l"(src));
}
__device__ __forceinline__ void cp8(uint32_t dst, const void* src) {
    asm volatile("cp.async.ca.shared.global [%0], [%1], 8;" :: "r"(dst), "l"(src));
}
#define CP_COMMIT() asm volatile("cp.async.commit_group;" ::: "memory")
#define CP_WAIT(n)  asm volatile("cp.async.wait_group %0;" :: "n"(n) : "memory")

// mma.sync m16n8k8 tf32: D(16x8,f32) += A(16x8,row) * B(8x8,col)
__device__ __forceinline__ void mma8(float* d, const uint32_t* a, const uint32_t* b) {
    asm volatile(
        "mma.sync.aligned.m16n8k8.row.col.f32.tf32.tf32.f32 "
        "{%0,%1,%2,%3}, {%4,%5,%6,%7}, {%8,%9}, {%0,%1,%2,%3};\n"
        : "+f"(d[0]), "+f"(d[1]), "+f"(d[2]), "+f"(d[3])
        : "r"(a[0]), "r"(a[1]), "r"(a[2]), "r"(a[3]), "r"(b[0]), "r"(b[1]));
}

// ---------------- prep kernels (tf32 rounding / packing) ----------------
__global__ void tf32_copy(const float* __restrict__ src, float* __restrict__ dst, int n4) {
    int i = blockIdx.x * blockDim.x + threadIdx.x;
    if (i >= n4) return;
    float4 v = reinterpret_cast<const float4*>(src)[i];
    v.x = f2tf32(v.x); v.y = f2tf32(v.y); v.z = f2tf32(v.z); v.w = f2tf32(v.w);
    reinterpret_cast<float4*>(dst)[i] = v;
}

// pack [Wq|Wk|Wv] (each [K, nq/nk/nv]) into g_wqkv [K, 6144], tf32-rounded
__global__ void pack_wqkv(const float* __restrict__ Wq, const float* __restrict__ Wk,
                          const float* __restrict__ Wv, float* __restrict__ dst)
{
    int i = blockIdx.x * blockDim.x + threadIdx.x;     // over K*6144/4
    int n4 = KDIM * QKV_N / 4;
    if (i >= n4) return;
    int col4 = i % (QKV_N / 4), k = i / (QKV_N / 4);
    int col = col4 * 4;
    const float* src;
    if (col < NH * HD)                src = Wq + (size_t)k * (NH * HD) + col;
    else if (col < NH * HD + NKV * HD) src = Wk + (size_t)k * (NKV * HD) + (col - NH * HD);
    else                               src = Wv + (size_t)k * (NKV * HD) + (col - NH * HD - NKV * HD);
    float4 v = *reinterpret_cast<const float4*>(src);
    v.x = f2tf32(v.x); v.y = f2tf32(v.y); v.z = f2tf32(v.z); v.w = f2tf32(v.w);
    reinterpret_cast<float4*>(dst)[i] = v;
}

// ---------------- GEMM: C[M,N] = A[M,4096] @ W[4096,N], tf32 mma, cp.async x3 ----
#define GBM 128
#define GBN 128
#define GBK 32
#define ASTR 36
#define BSTR 132
#define ASZ  (GBM * ASTR)        // 4608 floats
#define BSZ  (GBK * BSTR)        // 4224 floats
#define STG  (ASZ + BSZ)         // 8832 floats per stage
#define NSTAGE 3
#define GEMM_SMEM (NSTAGE * STG * 4)   // 105984 B
#define KT (KDIM / GBK)          // 128

__global__ __launch_bounds__(256, 2)
void gemm_tc(const float* __restrict__ A, const float* __restrict__ W,
             float* __restrict__ C, int ldb, int ldc, int round_out)
{
    extern __shared__ float sm[];
    const int tid  = threadIdx.x;
    const int lane = tid & 31, warp = tid >> 5;
    const int wm = warp >> 2, wn = warp & 3;   // 2(m) x 4(n)
    const int g = lane >> 2, t = lane & 3;
    const int m0 = blockIdx.y * GBM, n0 = blockIdx.x * GBN;

    float acc[4][4][4];
#pragma unroll
    for (int i = 0; i < 4; i++)
#pragma unroll
        for (int j = 0; j < 4; j++)
#pragma unroll
            for (int r = 0; r < 4; r++) acc[i][j][r] = 0.f;

    auto loadChunk = [&](int st, int kt) {
        float* As = sm + st * STG;
        const float* Ag = A + (size_t)m0 * KDIM + kt * GBK;
#pragma unroll
        for (int i = 0; i < 8; i++) {                   // 2048 8B-ops for A
            int l = i * 256 + tid;
            int r = l >> 4, c2 = (l & 15) << 1;
            cp8(smem_u32(&As[r * ASTR + c2]), Ag + (size_t)r * KDIM + c2);
        }
        float* Bs = sm + st * STG + ASZ;
        const float* Wg = W + (size_t)(kt * GBK) * ldb + n0;
#pragma unroll
        for (int i = 0; i < 8; i++) {                   // 2048 8B-ops for B
            int l = i * 256 + tid;
            int r = l >> 6, c2 = (l & 63) << 1;
            cp8(smem_u32(&Bs[r * BSTR + c2]), Wg + (size_t)r * ldb + c2);
        }
    };

    loadChunk(0, 0); CP_COMMIT();
    loadChunk(1, 1); CP_COMMIT();

    for (int c = 0; c < KT; c++) {
        CP_WAIT(1);
        __syncthreads();
        // prefetch stage c+2 (buffer (c+2)%3 — freed: computed at iter c-1)
        if (c + 2 < KT) loadChunk((c + 2) % NSTAGE, c + 2);
        CP_COMMIT();

        const float* Asc = sm + (c % NSTAGE) * STG;
        const float* Bsc = Asc + ASZ;
#pragma unroll
        for (int kk = 0; kk < GBK / 8; kk++) {
            uint32_t af[4][4];
#pragma unroll
            for (int mi = 0; mi < 4; mi++) {
                int r = wm * 64 + mi * 16 + g;
                int cc = kk * 8 + t;
                af[mi][0] = fu(Asc[r * ASTR + cc]);
                af[mi][1] = fu(Asc[(r + 8) * ASTR + cc]);
                af[mi][2] = fu(Asc[r * ASTR + cc + 4]);
                af[mi][3] = fu(Asc[(r + 8) * ASTR + cc + 4]);
            }
            uint32_t bf[4][2];
#pragma unroll
            for (int ni = 0; ni < 4; ni++) {
                int cc = wn * 32 + ni * 8 + g;
                int r = kk * 8 + t;
                bf[ni][0] = fu(Bsc[r * BSTR + cc]);
                bf[ni][1] = fu(Bsc[(r + 4) * BSTR + cc]);
            }
#pragma unroll
            for (int mi = 0; mi < 4; mi++)
#pragma unroll
                for (int ni = 0; ni < 4; ni++)
                    mma8(acc[mi][ni], af[mi], bf[ni]);
        }
        __syncthreads();
    }

#pragma unroll
    for (int mi = 0; mi < 4; mi++) {
        int row = m0 + wm * 64 + mi * 16 + g;
#pragma unroll
        for (int ni = 0; ni < 4; ni++) {
            int col = n0 + wn * 32 + ni * 8 + t * 2;
            float4 dummy;
            float v0 = acc[mi][ni][0], v1 = acc[mi][ni][1];
            float v2 = acc[mi][ni][2], v3 = acc[mi][ni][3];
            if (round_out) { v0 = f2tf32(v0); v1 = f2tf32(v1); v2 = f2tf32(v2); v3 = f2tf32(v3); }
            *reinterpret_cast<float2*>(&C[(size_t)row * ldc + col]) = make_float2(v0, v1);
            *reinterpret_cast<float2*>(&C[(size_t)(row + 8) * ldc + col]) = make_float2(v2, v3);
            (void)dummy;
        }
    }
}

// ---------------- RoPE (in place on g_qkv, outputs tf32-rounded) ----------------
__global__ void rope_kernel(float* __restrict__ x, const float* __restrict__ cosb,
                            const float* __restrict__ sinb, int nheads, int total)
{
    int i = blockIdx.x * blockDim.x + threadIdx.x;
    if (i >= total) return;
    int dh = i & 63;
    int h  = (i >> 6) % nheads;
    int bs = (i >> 6) / nheads;                 // b*SEQ + s
    float* p = x + (size_t)bs * QKV_LD + h * HD + dh;
    float x1 = p[0], x2 = p[64];
    const float* cb = cosb + (size_t)bs * HD;
    const float* sb = sinb + (size_t)bs * HD;
    p[0]  = f2tf32(x1 * cb[dh]      - x2 * sb[dh]);
    p[64] = f2tf32(x2 * cb[dh + 64] + x1 * sb[dh + 64]);
}

// ---------------- flash attention (causal, GQA, online softmax, tf32 mma) --------
#define FBQ 128
#define FBK 64
#define QSTR 132
#define KSTR 132
#define VSTR 132
#define PSTR 68
#define FLASH_SMEM ((FBQ * QSTR + FBK * KSTR + FBK * VSTR + FBQ * PSTR) * 4)

__global__ __launch_bounds__(256)
void flash_kernel()
{
    extern __shared__ float sm[];
    float* Qs = sm;                     // [128][132]
    float* Ks = Qs + FBQ * QSTR;        // [64][132]
    float* Vs = Ks + FBK * KSTR;        // [64][132]
    float* Ps = Vs + FBK * VSTR;        // [128][68]

    const int tid  = threadIdx.x;
    const int lane = tid & 31, warp = tid >> 5;
    const int g = lane >> 2, t = lane & 3;
    const int qt = blockIdx.x, h = blockIdx.y, b = blockIdx.z;
    const int q0 = qt * FBQ;
    const int kh = h / NREP;
    const int r0 = warp * 16;   // warp owns rows [r0, r0+16)

    const float* Qg = g_qkv + ((size_t)(b * SEQ + q0)) * QKV_LD + h * HD;
    const float* Kbase = g_qkv + (size_t)b * SEQ * QKV_LD + NH * HD + kh * HD;

    auto issueKV = [&](int kt) {
        const float* Kg = Kbase + (size_t)(kt * FBK) * QKV_LD;
        const float* Vg = Kg + NKV * HD;
#pragma unroll
        for (int i = 0; i < 8; i++) {
            int l = i * 256 + tid;
            int r = l >> 5, c = (l & 31) << 2;
            cp16(smem_u32(&Ks[r * KSTR + c]), Kg + (size_t)r * QKV_LD + c);
            cp16(smem_u32(&Vs[r * VSTR + c]), Vg + (size_t)r * QKV_LD + c);
        }
    };

    // issue Q tile + first K/V tile
#pragma unroll
    for (int i = 0; i < 16; i++) {
        int l = i * 256 + tid;
        int r = l >> 5, c = (l & 31) << 2;
        cp16(smem_u32(&Qs[r * QSTR + c]), Qg + (size_t)r * QKV_LD + c);
    }
    issueKV(0);
    CP_COMMIT();

    float o[16][4];
#pragma unroll
    for (int n = 0; n < 16; n++)
#pragma unroll
        for (int r = 0; r < 4; r++) o[n][r] = 0.f;
    float mrow[2] = {-1e30f, -1e30f};
    float lrow[2] = {0.f, 0.f};

    const int nkt = qt * 2 + 2;   // tiles up to and including the diagonal
    for (int kt = 0; kt < nkt; kt++) {
        const int k0 = kt * FBK;
        CP_WAIT(0);
        __syncthreads();

        // S = Q @ K^T   (warp: 16 x 64, k-dim = 128)
        float s[8][4];
#pragma unroll
        for (int j = 0; j < 8; j++)
#pragma unroll
            for (int r = 0; r < 4; r++) s[j][r] = 0.f;
#pragma unroll
        for (int kk = 0; kk < 16; kk++) {
            uint32_t af[4];
            int rr = r0 + g, cc = kk * 8 + t;
            af[0] = fu(Qs[rr * QSTR + cc]);
            af[1] = fu(Qs[(rr + 8) * QSTR + cc]);
            af[2] = fu(Qs[rr * QSTR + cc + 4]);
            af[3] = fu(Qs[(rr + 8) * QSTR + cc + 4]);
#pragma unroll
            for (int j = 0; j < 8; j++) {
                uint32_t bf[2];
                int kr = j * 8 + g;
                bf[0] = fu(Ks[kr * KSTR + cc]);
                bf[1] = fu(Ks[kr * KSTR + cc + 4]);
                mma8(s[j], af, bf);
            }
        }

        // online softmax (rows warp-local; reduce over 4 lanes sharing a row)
        const float SCALE = 0.08838834764831845f;  // 1/sqrt(128)
        const int row_lo = q0 + r0 + g;
        float nm[2] = {mrow[0], mrow[1]};
#pragma unroll
        for (int j = 0; j < 8; j++) {
            int col = k0 + j * 8 + 2 * t;
            s[j][0] = (col     <= row_lo)     ? s[j][0] * SCALE : -1e30f;
            s[j][1] = (col + 1 <= row_lo)     ? s[j][1] * SCALE : -1e30f;
            s[j][2] = (col     <= row_lo + 8) ? s[j][2] * SCALE : -1e30f;
            s[j][3] = (col + 1 <= row_lo + 8) ? s[j][3] * SCALE : -1e30f;
            nm[0] = fmaxf(nm[0], fmaxf(s[j][0], s[j][1]));
            nm[1] = fmaxf(nm[1], fmaxf(s[j][2], s[j][3]));
        }
#pragma unroll
        for (int d = 1; d < 4; d <<= 1) {
            nm[0] = fmaxf(nm[0], __shfl_xor_sync(0xffffffffu, nm[0], d));
            nm[1] = fmaxf(nm[1], __shfl_xor_sync(0xffffffffu, nm[1], d));
        }
        float alpha0 = __expf(mrow[0] - nm[0]);
        float alpha1 = __expf(mrow[1] - nm[1]);
        mrow[0] = nm[0]; mrow[1] = nm[1];
        float rs0 = 0.f, rs1 = 0.f;
#pragma unroll
        for (int j = 0; j < 8; j++) {
            s[j][0] = __expf(s[j][0] - nm[0]);
            s[j][1] = __expf(s[j][1] - nm[0]);
            s[j][2] = __expf(s[j][2] - nm[1]);
            s[j][3] = __expf(s[j][3] - nm[1]);
            rs0 += s[j][0] + s[j][1];
            rs1 += s[j][2] + s[j][3];
            int pr = r0 + g, pc = j * 8 + 2 * t;
            *reinterpret_cast<float2*>(&Ps[pr * PSTR + pc]) =
                make_float2(f2tf32(s[j][0]), f2tf32(s[j][1]));
            *reinterpret_cast<float2*>(&Ps[(pr + 8) * PSTR + pc]) =
                make_float2(f2tf32(s[j][2]), f2tf32(s[j][3]));
        }
#pragma unroll
        for (int d = 1; d < 4; d <<= 1) {
            rs0 += __shfl_xor_sync(0xffffffffu, rs0, d);
            rs1 += __shfl_xor_sync(0xffffffffu, rs1, d);
        }
        lrow[0] = lrow[0] * alpha0 + rs0;
        lrow[1] = lrow[1] * alpha1 + rs1;
#pragma unroll
        for (int n = 0; n < 16; n++) {
            o[n][0] *= alpha0; o[n][1] *= alpha0;
            o[n][2] *= alpha1; o[n][3] *= alpha1;
        }
        __syncwarp();   // Ps visible within warp

        // O += P @ V   (warp: 16 x 128, k-dim = 64)
#pragma unroll
        for (int kk = 0; kk < 8; kk++) {
            uint32_t af[4];
            int pr = r0 + g, pc = kk * 8 + t;
            af[0] = fu(Ps[pr * PSTR + pc]);
            af[1] = fu(Ps[(pr + 8) * PSTR + pc]);
            af[2] = fu(Ps[pr * PSTR + pc + 4]);
            af[3] = fu(Ps[(pr + 8) * PSTR + pc + 4]);
#pragma unroll
            for (int n = 0; n < 16; n++) {
                uint32_t bf[2];
                int vr = kk * 8 + t, vc = n * 8 + g;
                bf[0] = fu(Vs[vr * VSTR + vc]);
                bf[1] = fu(Vs[(vr + 4) * VSTR + vc]);
                mma8(o[n], af, bf);
            }
        }

        __syncthreads();               // all warps done reading Ks/Vs
        if (kt + 1 < nkt) issueKV(kt + 1);
        CP_COMMIT();
    }

    // normalize + tf32-round and write [b*s, 4096]
    float inv0 = 1.f / lrow[0], inv1 = 1.f / lrow[1];
    int srow = q0 + r0 + g;
    float* Og = g_attn + ((size_t)(b * SEQ + srow)) * (NH * HD) + h * HD;
#pragma unroll
    for (int n = 0; n < 16; n++) {
        int c = n * 8 + 2 * t;
        *reinterpret_cast<float2*>(&Og[c]) =
            make_float2(f2tf32(o[n][0] * inv0), f2tf32(o[n][1] * inv0));
        *reinterpret_cast<float2*>(&Og[(size_t)8 * NH * HD + c]) =
            make_float2(f2tf32(o[n][2] * inv1), f2tf32(o[n][3] * inv1));
    }
}

// ---------------- launch ----------------
extern "C" void kernel_launch(void* const* d_in, const int* in_sizes, int n_in,
                              void* d_out, int out_size)
{
    const float* hs   = (const float*)d_in[0];
    const float* cosb = (const float*)d_in[1];
    const float* sinb = (const float*)d_in[2];
    // d_in[3] = attention_mask (pure causal; applied analytically in-kernel)
    const float* Wq = (const float*)d_in[4];
    const float* Wk = (const float*)d_in[5];
    const float* Wv = (const float*)d_in[6];
    const float* Wo = (const float*)d_in[7];
    float* out = (float*)d_out;

    float *hsp, *wqkvp, *wop, *qkvp, *ap;
    cudaGetSymbolAddress((void**)&hsp,   g_hs);
    cudaGetSymbolAddress((void**)&wqkvp, g_wqkv);
    cudaGetSymbolAddress((void**)&wop,   g_wo);
    cudaGetSymbolAddress((void**)&qkvp,  g_qkv);
    cudaGetSymbolAddress((void**)&ap,    g_attn);

    cudaFuncSetAttribute(gemm_tc, cudaFuncAttributeMaxDynamicSharedMemorySize, GEMM_SMEM);
    cudaFuncSetAttribute(flash_kernel, cudaFuncAttributeMaxDynamicSharedMemorySize, FLASH_SMEM);

    const int M = BATCH * SEQ;

    // prep: tf32-round hidden states, pack+round weights
    int n4 = M * HID / 4;
    tf32_copy<<<(n4 + 255) / 256, 256>>>(hs, hsp, n4);
    int nw4 = KDIM * QKV_N / 4;
    pack_wqkv<<<(nw4 + 255) / 256, 256>>>(Wq, Wk, Wv, wqkvp);
    int no4 = KDIM * HID / 4;
    tf32_copy<<<(no4 + 255) / 256, 256>>>(Wo, wop, no4);

    // fused QKV projection: [M, 6144] = g_hs @ g_wqkv   (outputs tf32-rounded)
    gemm_tc<<<dim3(QKV_N / GBN, M / GBM), 256, GEMM_SMEM>>>(hsp, wqkvp, qkvp, QKV_N, QKV_LD, 1);

    // RoPE on q (32 heads) and k (8 heads)
    int totq = BATCH * SEQ * NH * 64;
    rope_kernel<<<(totq + 255) / 256, 256>>>(qkvp, cosb, sinb, NH, totq);
    int totk = BATCH * SEQ * NKV * 64;
    rope_kernel<<<(totk + 255) / 256, 256>>>(qkvp + NH * HD, cosb, sinb, NKV, totk);

    flash_kernel<<<dim3(SEQ / FBQ, NH, BATCH), 256, FLASH_SMEM>>>();

    // output projection: out = g_attn @ g_wo   (fp32 output, no rounding)
    gemm_tc<<<dim3(HID / GBN, M / GBM), 256, GEMM_SMEM>>>(ap, wop, out, HID, HID, 0);
}

// round 4
// speedup vs baseline: 1.4764x; 1.3118x over previous
#include <cuda_runtime.h>
#include <cstdint>

#define BATCH 2
#define SEQ   1024
#define HID   4096
#define NH    32
#define NKV   8
#define HD    128
#define NREP  4
#define QKV_N (NH * HD + 2 * NKV * HD)   // 6144
#define QKV_LD QKV_N
#define KDIM  4096
#define KT    (KDIM / 32)                // 128 k-chunks

// ---------------- scratch (device globals; no allocation allowed) ----------------
// fragment-packed A for QKV gemm: [M/128][KT][4096 floats]
__device__ float g_hsp [BATCH * SEQ * HID];
// fragment-packed B: [N/128][KT][4096]
__device__ float g_wqkv[KDIM * QKV_N];
__device__ float g_wo  [KDIM * HID];
__device__ float g_qkv [BATCH * SEQ * QKV_N];      // row-major: q(4096)|k(1024)|v(1024), tf32
__device__ float g_attn[BATCH * SEQ * NH * HD];    // fragment-packed A for O-proj

// ---------------- helpers ----------------
__device__ __forceinline__ float f2tf32(float x) {
    uint32_t u;
    asm("cvt.rna.tf32.f32 %0, %1;" : "=r"(u) : "f"(x));
    return __uint_as_float(u);
}
__device__ __forceinline__ uint32_t fu(float x) { return __float_as_uint(x); }

__device__ __forceinline__ uint32_t smem_u32(const void* p) {
    uint32_t a;
    asm("{ .reg .u64 t; cvta.to.shared.u64 t, %1; cvt.u32.u64 %0, t; }" : "=r"(a) : "l"(p));
    return a;
}
__device__ __forceinline__ void cp16(uint32_t dst, const void* src) {
    asm volatile("cp.async.cg.shared.global [%0], [%1], 16;" :: "r"(dst), "l"(src));
}
#define CP_COMMIT() asm volatile("cp.async.commit_group;" ::: "memory")
#define CP_WAIT(n)  asm volatile("cp.async.wait_group %0;" :: "n"(n) : "memory")

// mma.sync m16n8k8 tf32
__device__ __forceinline__ void mma8(float* d, const uint32_t* a, const uint32_t* b) {
    asm volatile(
        "mma.sync.aligned.m16n8k8.row.col.f32.tf32.tf32.f32 "
        "{%0,%1,%2,%3}, {%4,%5,%6,%7}, {%8,%9}, {%0,%1,%2,%3};\n"
        : "+f"(d[0]), "+f"(d[1]), "+f"(d[2]), "+f"(d[3])
        : "r"(a[0]), "r"(a[1]), "r"(a[2]), "r"(a[3]), "r"(b[0]), "r"(b[1]));
}

// ---------------- prep: pack A (activations) into fragment order -----------------
// src: [M][K] row-major. dst: [M/128][K/32][1024 lanes x 4] ; per 16x8 fragment,
// lane l=(g*4+t) holds {A(g,t), A(g+8,t), A(g,t+4), A(g+8,t+4)} contiguously.
__global__ __launch_bounds__(256)
void pack_a(const float* __restrict__ src, float* __restrict__ dst, int K)
{
    __shared__ float sm[128][36];
    const int tid = threadIdx.x;
    const int kc = blockIdx.x, mt = blockIdx.y;
    const float* S = src + (size_t)(mt * 128) * K + kc * 32;
#pragma unroll
    for (int i = 0; i < 4; i++) {
        int idx = i * 256 + tid;
        int r = idx >> 3, c4 = (idx & 7) << 2;
        float4 v = *reinterpret_cast<const float4*>(S + (size_t)r * K + c4);
        v.x = f2tf32(v.x); v.y = f2tf32(v.y); v.z = f2tf32(v.z); v.w = f2tf32(v.w);
        *reinterpret_cast<float4*>(&sm[r][c4]) = v;
    }
    __syncthreads();
    float* D = dst + ((size_t)(mt * (K / 32)) + kc) * 4096;
#pragma unroll
    for (int i = 0; i < 4; i++) {
        int e = i * 256 + tid;             // 1024 fragment-lane entries
        int mg = e >> 7, kg = (e >> 5) & 3, ln = e & 31;
        int g = ln >> 2, t = ln & 3;
        float4 v = make_float4(sm[mg * 16 + g][kg * 8 + t],
                               sm[mg * 16 + g + 8][kg * 8 + t],
                               sm[mg * 16 + g][kg * 8 + t + 4],
                               sm[mg * 16 + g + 8][kg * 8 + t + 4]);
        *reinterpret_cast<float4*>(D + e * 4) = v;
    }
}

// ---------------- prep: pack W [K][N] (n-contig) into fragment order -------------
// dst block [ntile][kchunk][2048 x 2]: lane l=(g*4+t) of (ngrp,kgrp) holds
// {W(t, n), W(t+4, n)} with n = ngrp*8+g, contiguously (8B).
__global__ __launch_bounds__(256)
void pack_w(const float* __restrict__ W, float* __restrict__ dst, int N)
{
    __shared__ float sm[32][132];
    const int tid = threadIdx.x;
    const int kc = blockIdx.x, nt = blockIdx.y;
    const float* S = W + (size_t)(kc * 32) * N + nt * 128;
#pragma unroll
    for (int i = 0; i < 4; i++) {
        int idx = i * 256 + tid;
        int r = idx >> 5, c4 = (idx & 31) << 2;
        float4 v = *reinterpret_cast<const float4*>(S + (size_t)r * N + c4);
        v.x = f2tf32(v.x); v.y = f2tf32(v.y); v.z = f2tf32(v.z); v.w = f2tf32(v.w);
        *reinterpret_cast<float4*>(&sm[r][c4]) = v;
    }
    __syncthreads();
    float* D = dst + ((size_t)(nt * KT) + kc) * 4096;
#pragma unroll
    for (int i = 0; i < 8; i++) {
        int e = i * 256 + tid;             // 2048 fragment-lane entries
        int ng = e >> 7, kg = (e >> 5) & 3, ln = e & 31;
        int g = ln >> 2, t = ln & 3;
        float2 v = make_float2(sm[kg * 8 + t][ng * 8 + g],
                               sm[kg * 8 + t + 4][ng * 8 + g]);
        *reinterpret_cast<float2*>(D + e * 2) = v;
    }
}

// ---------------- GEMM on packed operands: C[M,N] = A @ W --------------------
// grid: (N/128, M/128). Warp grid 2(m) x 4(n), warp tile 64x32.
#define STG_F 8192                          // floats per stage (A 4096 + B 4096)
#define NSTAGE 3
#define GEMM_SMEM (NSTAGE * STG_F * 4)      // 98304 B

__global__ __launch_bounds__(256, 2)
void gemm_tc(const float* __restrict__ Ap, const float* __restrict__ Bp,
             float* __restrict__ C, int ldc, int round_out)
{
    extern __shared__ float sm[];
    const int tid  = threadIdx.x;
    const int lane = tid & 31, warp = tid >> 5;
    const int wm = warp >> 2, wn = warp & 3;
    const int g = lane >> 2, t = lane & 3;

    float acc[4][4][4];
#pragma unroll
    for (int i = 0; i < 4; i++)
#pragma unroll
        for (int j = 0; j < 4; j++)
#pragma unroll
            for (int r = 0; r < 4; r++) acc[i][j][r] = 0.f;

    auto loadChunk = [&](int st, int kt) {
        const float* Ag = Ap + ((size_t)(blockIdx.y * KT) + kt) * 4096;
        const float* Bg = Bp + ((size_t)(blockIdx.x * KT) + kt) * 4096;
        float* As = sm + st * STG_F;
        float* Bs = As + 4096;
#pragma unroll
        for (int i = 0; i < 4; i++) {
            int off = (i * 256 + tid) * 4;
            cp16(smem_u32(As + off), Ag + off);
        }
#pragma unroll
        for (int i = 0; i < 4; i++) {
            int off = (i * 256 + tid) * 4;
            cp16(smem_u32(Bs + off), Bg + off);
        }
    };

    loadChunk(0, 0); CP_COMMIT();
    loadChunk(1, 1); CP_COMMIT();

    for (int c = 0; c < KT; c++) {
        CP_WAIT(1);
        __syncthreads();
        if (c + 2 < KT) loadChunk((c + 2) % NSTAGE, c + 2);
        CP_COMMIT();

        const float* As = sm + (c % NSTAGE) * STG_F;
        const float* Bs = As + 4096;
#pragma unroll
        for (int kk = 0; kk < 4; kk++) {
            uint32_t af[4][4];
#pragma unroll
            for (int mi = 0; mi < 4; mi++) {
                const float4 v = *reinterpret_cast<const float4*>(
                    As + (((wm * 4 + mi) * 4 + kk) * 32 + lane) * 4);
                af[mi][0] = fu(v.x); af[mi][1] = fu(v.y);
                af[mi][2] = fu(v.z); af[mi][3] = fu(v.w);
            }
            uint32_t bf[4][2];
#pragma unroll
            for (int ni = 0; ni < 4; ni++) {
                const float2 v = *reinterpret_cast<const float2*>(
                    Bs + (((wn * 4 + ni) * 4 + kk) * 32 + lane) * 2);
                bf[ni][0] = fu(v.x); bf[ni][1] = fu(v.y);
            }
#pragma unroll
            for (int mi = 0; mi < 4; mi++)
#pragma unroll
                for (int ni = 0; ni < 4; ni++)
                    mma8(acc[mi][ni], af[mi], bf[ni]);
        }
        __syncthreads();
    }

    const int m0 = blockIdx.y * 128, n0 = blockIdx.x * 128;
#pragma unroll
    for (int mi = 0; mi < 4; mi++) {
        int row = m0 + wm * 64 + mi * 16 + g;
#pragma unroll
        for (int ni = 0; ni < 4; ni++) {
            int col = n0 + wn * 32 + ni * 8 + t * 2;
            float v0 = acc[mi][ni][0], v1 = acc[mi][ni][1];
            float v2 = acc[mi][ni][2], v3 = acc[mi][ni][3];
            if (round_out) { v0 = f2tf32(v0); v1 = f2tf32(v1); v2 = f2tf32(v2); v3 = f2tf32(v3); }
            *reinterpret_cast<float2*>(&C[(size_t)row * ldc + col]) = make_float2(v0, v1);
            *reinterpret_cast<float2*>(&C[(size_t)(row + 8) * ldc + col]) = make_float2(v2, v3);
        }
    }
}

// ---------------- RoPE (in place on g_qkv, outputs tf32-rounded) ----------------
__global__ void rope_kernel(float* __restrict__ x, const float* __restrict__ cosb,
                            const float* __restrict__ sinb, int nheads, int total)
{
    int i = blockIdx.x * blockDim.x + threadIdx.x;
    if (i >= total) return;
    int dh = i & 63;
    int h  = (i >> 6) % nheads;
    int bs = (i >> 6) / nheads;
    float* p = x + (size_t)bs * QKV_LD + h * HD + dh;
    float x1 = p[0], x2 = p[64];
    const float* cb = cosb + (size_t)bs * HD;
    const float* sb = sinb + (size_t)bs * HD;
    p[0]  = f2tf32(x1 * cb[dh]      - x2 * sb[dh]);
    p[64] = f2tf32(x2 * cb[dh + 64] + x1 * sb[dh + 64]);
}

// ---------------- flash attention (causal, GQA, online softmax, tf32 mma) --------
#define FBQ 128
#define FBK 64
#define QSTR 132
#define KSTR 132
#define VSTR 132
#define PSTR 68
#define FLASH_SMEM ((FBQ * QSTR + FBK * KSTR + FBK * VSTR + FBQ * PSTR) * 4)

__global__ __launch_bounds__(256)
void flash_kernel()
{
    extern __shared__ float sm[];
    float* Qs = sm;
    float* Ks = Qs + FBQ * QSTR;
    float* Vs = Ks + FBK * KSTR;
    float* Ps = Vs + FBK * VSTR;

    const int tid  = threadIdx.x;
    const int lane = tid & 31, warp = tid >> 5;
    const int g = lane >> 2, t = lane & 3;
    const int qt = blockIdx.x, h = blockIdx.y, b = blockIdx.z;
    const int q0 = qt * FBQ;
    const int kh = h / NREP;
    const int r0 = warp * 16;

    const float* Qg = g_qkv + ((size_t)(b * SEQ + q0)) * QKV_LD + h * HD;
    const float* Kbase = g_qkv + (size_t)b * SEQ * QKV_LD + NH * HD + kh * HD;

    auto issueKV = [&](int kt) {
        const float* Kg = Kbase + (size_t)(kt * FBK) * QKV_LD;
        const float* Vg = Kg + NKV * HD;
#pragma unroll
        for (int i = 0; i < 8; i++) {
            int l = i * 256 + tid;
            int r = l >> 5, c = (l & 31) << 2;
            cp16(smem_u32(&Ks[r * KSTR + c]), Kg + (size_t)r * QKV_LD + c);
            cp16(smem_u32(&Vs[r * VSTR + c]), Vg + (size_t)r * QKV_LD + c);
        }
    };

#pragma unroll
    for (int i = 0; i < 16; i++) {
        int l = i * 256 + tid;
        int r = l >> 5, c = (l & 31) << 2;
        cp16(smem_u32(&Qs[r * QSTR + c]), Qg + (size_t)r * QKV_LD + c);
    }
    issueKV(0);
    CP_COMMIT();

    float o[16][4];
#pragma unroll
    for (int n = 0; n < 16; n++)
#pragma unroll
        for (int r = 0; r < 4; r++) o[n][r] = 0.f;
    float mrow[2] = {-1e30f, -1e30f};
    float lrow[2] = {0.f, 0.f};

    const int nkt = qt * 2 + 2;
    for (int kt = 0; kt < nkt; kt++) {
        const int k0 = kt * FBK;
        CP_WAIT(0);
        __syncthreads();

        float s[8][4];
#pragma unroll
        for (int j = 0; j < 8; j++)
#pragma unroll
            for (int r = 0; r < 4; r++) s[j][r] = 0.f;
#pragma unroll
        for (int kk = 0; kk < 16; kk++) {
            uint32_t af[4];
            int rr = r0 + g, cc = kk * 8 + t;
            af[0] = fu(Qs[rr * QSTR + cc]);
            af[1] = fu(Qs[(rr + 8) * QSTR + cc]);
            af[2] = fu(Qs[rr * QSTR + cc + 4]);
            af[3] = fu(Qs[(rr + 8) * QSTR + cc + 4]);
#pragma unroll
            for (int j = 0; j < 8; j++) {
                uint32_t bf[2];
                int kr = j * 8 + g;
                bf[0] = fu(Ks[kr * KSTR + cc]);
                bf[1] = fu(Ks[kr * KSTR + cc + 4]);
                mma8(s[j], af, bf);
            }
        }

        const float SCALE = 0.08838834764831845f;
        const int row_lo = q0 + r0 + g;
        float nm[2] = {mrow[0], mrow[1]};
#pragma unroll
        for (int j = 0; j < 8; j++) {
            int col = k0 + j * 8 + 2 * t;
            s[j][0] = (col     <= row_lo)     ? s[j][0] * SCALE : -1e30f;
            s[j][1] = (col + 1 <= row_lo)     ? s[j][1] * SCALE : -1e30f;
            s[j][2] = (col     <= row_lo + 8) ? s[j][2] * SCALE : -1e30f;
            s[j][3] = (col + 1 <= row_lo + 8) ? s[j][3] * SCALE : -1e30f;
            nm[0] = fmaxf(nm[0], fmaxf(s[j][0], s[j][1]));
            nm[1] = fmaxf(nm[1], fmaxf(s[j][2], s[j][3]));
        }
#pragma unroll
        for (int d = 1; d < 4; d <<= 1) {
            nm[0] = fmaxf(nm[0], __shfl_xor_sync(0xffffffffu, nm[0], d));
            nm[1] = fmaxf(nm[1], __shfl_xor_sync(0xffffffffu, nm[1], d));
        }
        float alpha0 = __expf(mrow[0] - nm[0]);
        float alpha1 = __expf(mrow[1] - nm[1]);
        mrow[0] = nm[0]; mrow[1] = nm[1];
        float rs0 = 0.f, rs1 = 0.f;
#pragma unroll
        for (int j = 0; j < 8; j++) {
            s[j][0] = __expf(s[j][0] - nm[0]);
            s[j][1] = __expf(s[j][1] - nm[0]);
            s[j][2] = __expf(s[j][2] - nm[1]);
            s[j][3] = __expf(s[j][3] - nm[1]);
            rs0 += s[j][0] + s[j][1];
            rs1 += s[j][2] + s[j][3];
            int pr = r0 + g, pc = j * 8 + 2 * t;
            *reinterpret_cast<float2*>(&Ps[pr * PSTR + pc]) =
                make_float2(f2tf32(s[j][0]), f2tf32(s[j][1]));
            *reinterpret_cast<float2*>(&Ps[(pr + 8) * PSTR + pc]) =
                make_float2(f2tf32(s[j][2]), f2tf32(s[j][3]));
        }
#pragma unroll
        for (int d = 1; d < 4; d <<= 1) {
            rs0 += __shfl_xor_sync(0xffffffffu, rs0, d);
            rs1 += __shfl_xor_sync(0xffffffffu, rs1, d);
        }
        lrow[0] = lrow[0] * alpha0 + rs0;
        lrow[1] = lrow[1] * alpha1 + rs1;
#pragma unroll
        for (int n = 0; n < 16; n++) {
            o[n][0] *= alpha0; o[n][1] *= alpha0;
            o[n][2] *= alpha1; o[n][3] *= alpha1;
        }
        __syncwarp();

#pragma unroll
        for (int kk = 0; kk < 8; kk++) {
            uint32_t af[4];
            int pr = r0 + g, pc = kk * 8 + t;
            af[0] = fu(Ps[pr * PSTR + pc]);
            af[1] = fu(Ps[(pr + 8) * PSTR + pc]);
            af[2] = fu(Ps[pr * PSTR + pc + 4]);
            af[3] = fu(Ps[(pr + 8) * PSTR + pc + 4]);
#pragma unroll
            for (int n = 0; n < 16; n++) {
                uint32_t bf[2];
                int vr = kk * 8 + t, vc = n * 8 + g;
                bf[0] = fu(Vs[vr * VSTR + vc]);
                bf[1] = fu(Vs[(vr + 4) * VSTR + vc]);
                mma8(o[n], af, bf);
            }
        }

        __syncthreads();
        if (kt + 1 < nkt) issueKV(kt + 1);
        CP_COMMIT();
    }

    // normalize + write g_attn in FRAGMENT-PACKED layout for the O-proj GEMM.
    // O-proj A element (m = b*SEQ + q0 + r0 + rr, k = h*128 + n*8 + cc):
    //   mtile = b*8 + qt, mgrp = warp, kchunk = h*4 + (n>>2), kgrp = n&3,
    //   lane' = (rr&7)*4 + (cc&3), reg = (cc>>2)*2 + (rr>>3).
    float inv0 = 1.f / lrow[0], inv1 = 1.f / lrow[1];
    const int mtile = b * 8 + qt;
#pragma unroll
    for (int n = 0; n < 16; n++) {
        int kchunk = h * 4 + (n >> 2);
        int kgrp = n & 3;
        float* base = g_attn + ((size_t)(mtile * KT) + kchunk) * 4096
                    + ((warp * 4 + kgrp) * 32) * 4;
        int cc0 = 2 * t, cc1 = 2 * t + 1;
        int l0 = g * 4 + (cc0 & 3), rA = (cc0 >> 2) * 2;
        int l1 = g * 4 + (cc1 & 3), rB = (cc1 >> 2) * 2;
        base[l0 * 4 + rA]     = f2tf32(o[n][0] * inv0);
        base[l1 * 4 + rB]     = f2tf32(o[n][1] * inv0);
        base[l0 * 4 + rA + 1] = f2tf32(o[n][2] * inv1);
        base[l1 * 4 + rB + 1] = f2tf32(o[n][3] * inv1);
    }
}

// ---------------- launch ----------------
extern "C" void kernel_launch(void* const* d_in, const int* in_sizes, int n_in,
                              void* d_out, int out_size)
{
    const float* hs   = (const float*)d_in[0];
    const float* cosb = (const float*)d_in[1];
    const float* sinb = (const float*)d_in[2];
    // d_in[3] = attention_mask (pure causal; applied analytically in-kernel)
    const float* Wq = (const float*)d_in[4];
    const float* Wk = (const float*)d_in[5];
    const float* Wv = (const float*)d_in[6];
    const float* Wo = (const float*)d_in[7];
    float* out = (float*)d_out;

    float *hsp, *wqkvp, *wop, *qkvp, *ap;
    cudaGetSymbolAddress((void**)&hsp,   g_hsp);
    cudaGetSymbolAddress((void**)&wqkvp, g_wqkv);
    cudaGetSymbolAddress((void**)&wop,   g_wo);
    cudaGetSymbolAddress((void**)&qkvp,  g_qkv);
    cudaGetSymbolAddress((void**)&ap,    g_attn);

    cudaFuncSetAttribute(gemm_tc, cudaFuncAttributeMaxDynamicSharedMemorySize, GEMM_SMEM);
    cudaFuncSetAttribute(flash_kernel, cudaFuncAttributeMaxDynamicSharedMemorySize, FLASH_SMEM);

    const int M = BATCH * SEQ;

    // prep: pack activations + weights into fragment order (tf32-rounded)
    pack_a<<<dim3(KT, M / 128), 256>>>(hs, hsp, KDIM);
    pack_w<<<dim3(KT, (NH * HD) / 128), 256>>>(Wq, wqkvp, NH * HD);
    pack_w<<<dim3(KT, (NKV * HD) / 128), 256>>>(Wk, wqkvp + (size_t)32 * KT * 4096, NKV * HD);
    pack_w<<<dim3(KT, (NKV * HD) / 128), 256>>>(Wv, wqkvp + (size_t)40 * KT * 4096, NKV * HD);
    pack_w<<<dim3(KT, HID / 128), 256>>>(Wo, wop, HID);

    // fused QKV projection (output row-major tf32 for rope/flash)
    gemm_tc<<<dim3(QKV_N / 128, M / 128), 256, GEMM_SMEM>>>(hsp, wqkvp, qkvp, QKV_LD, 1);

    // RoPE on q (32 heads) and k (8 heads)
    int totq = BATCH * SEQ * NH * 64;
    rope_kernel<<<(totq + 255) / 256, 256>>>(qkvp, cosb, sinb, NH, totq);
    int totk = BATCH * SEQ * NKV * 64;
    rope_kernel<<<(totk + 255) / 256, 256>>>(qkvp + NH * HD, cosb, sinb, NKV, totk);

    flash_kernel<<<dim3(SEQ / FBQ, NH, BATCH), 256, FLASH_SMEM>>>();

    // output projection: out = g_attn(packed) @ Wo(packed), fp32 output
    gemm_tc<<<dim3(HID / 128, M / 128), 256, GEMM_SMEM>>>(ap, wop, out, HID, 0);
}

// round 5
// speedup vs baseline: 1.4967x; 1.0137x over previous
#include <cuda_runtime.h>
#include <cstdint>

#define BATCH 2
#define SEQ   1024
#define HID   4096
#define NH    32
#define NKV   8
#define HD    128
#define NREP  4
#define QKV_N (NH * HD + 2 * NKV * HD)   // 6144
#define QKV_LD QKV_N
#define KDIM  4096
#define KT    (KDIM / 32)                // 128 k-chunks

// ---------------- scratch (device globals; no allocation allowed) ----------------
__device__ float g_hsp [BATCH * SEQ * HID];        // fragment-packed A [M/128][KT][4096]
__device__ float g_wqkv[KDIM * QKV_N];             // fragment-packed B [N/128][KT][4096]
__device__ float g_wo  [KDIM * HID];
__device__ float g_qkv [BATCH * SEQ * QKV_N];      // row-major: q|k|v, tf32
__device__ float g_attn[BATCH * SEQ * NH * HD];    // fragment-packed A for O-proj

// ---------------- helpers ----------------
__device__ __forceinline__ float f2tf32(float x) {
    uint32_t u;
    asm("cvt.rna.tf32.f32 %0, %1;" : "=r"(u) : "f"(x));
    return __uint_as_float(u);
}
__device__ __forceinline__ uint32_t fu(float x) { return __float_as_uint(x); }

__device__ __forceinline__ uint32_t smem_u32(const void* p) {
    uint32_t a;
    asm("{ .reg .u64 t; cvta.to.shared.u64 t, %1; cvt.u32.u64 %0, t; }" : "=r"(a) : "l"(p));
    return a;
}
__device__ __forceinline__ void cp16(uint32_t dst, const void* src) {
    asm volatile("cp.async.cg.shared.global [%0], [%1], 16;" :: "r"(dst), "l"(src));
}
#define CP_COMMIT() asm volatile("cp.async.commit_group;" ::: "memory")
#define CP_WAIT(n)  asm volatile("cp.async.wait_group %0;" :: "n"(n) : "memory")

// mma.sync m16n8k8 tf32
__device__ __forceinline__ void mma8(float* d, const uint32_t* a, const uint32_t* b) {
    asm volatile(
        "mma.sync.aligned.m16n8k8.row.col.f32.tf32.tf32.f32 "
        "{%0,%1,%2,%3}, {%4,%5,%6,%7}, {%8,%9}, {%0,%1,%2,%3};\n"
        : "+f"(d[0]), "+f"(d[1]), "+f"(d[2]), "+f"(d[3])
        : "r"(a[0]), "r"(a[1]), "r"(a[2]), "r"(a[3]), "r"(b[0]), "r"(b[1]));
}

// ---------------- prep: pack A (activations) into fragment order -----------------
__global__ __launch_bounds__(256)
void pack_a(const float* __restrict__ src, float* __restrict__ dst, int K)
{
    __shared__ float sm[128][36];
    const int tid = threadIdx.x;
    const int kc = blockIdx.x, mt = blockIdx.y;
    const float* S = src + (size_t)(mt * 128) * K + kc * 32;
#pragma unroll
    for (int i = 0; i < 4; i++) {
        int idx = i * 256 + tid;
        int r = idx >> 3, c4 = (idx & 7) << 2;
        float4 v = *reinterpret_cast<const float4*>(S + (size_t)r * K + c4);
        v.x = f2tf32(v.x); v.y = f2tf32(v.y); v.z = f2tf32(v.z); v.w = f2tf32(v.w);
        *reinterpret_cast<float4*>(&sm[r][c4]) = v;
    }
    __syncthreads();
    float* D = dst + ((size_t)(mt * (K / 32)) + kc) * 4096;
#pragma unroll
    for (int i = 0; i < 4; i++) {
        int e = i * 256 + tid;
        int mg = e >> 7, kg = (e >> 5) & 3, ln = e & 31;
        int g = ln >> 2, t = ln & 3;
        float4 v = make_float4(sm[mg * 16 + g][kg * 8 + t],
                               sm[mg * 16 + g + 8][kg * 8 + t],
                               sm[mg * 16 + g][kg * 8 + t + 4],
                               sm[mg * 16 + g + 8][kg * 8 + t + 4]);
        *reinterpret_cast<float4*>(D + e * 4) = v;
    }
}

// ---------------- prep: pack W [K][N] into fragment order ------------------------
__global__ __launch_bounds__(256)
void pack_w(const float* __restrict__ W, float* __restrict__ dst, int N)
{
    __shared__ float sm[32][132];
    const int tid = threadIdx.x;
    const int kc = blockIdx.x, nt = blockIdx.y;
    const float* S = W + (size_t)(kc * 32) * N + nt * 128;
#pragma unroll
    for (int i = 0; i < 4; i++) {
        int idx = i * 256 + tid;
        int r = idx >> 5, c4 = (idx & 31) << 2;
        float4 v = *reinterpret_cast<const float4*>(S + (size_t)r * N + c4);
        v.x = f2tf32(v.x); v.y = f2tf32(v.y); v.z = f2tf32(v.z); v.w = f2tf32(v.w);
        *reinterpret_cast<float4*>(&sm[r][c4]) = v;
    }
    __syncthreads();
    float* D = dst + ((size_t)(nt * KT) + kc) * 4096;
#pragma unroll
    for (int i = 0; i < 8; i++) {
        int e = i * 256 + tid;
        int ng = e >> 7, kg = (e >> 5) & 3, ln = e & 31;
        int g = ln >> 2, t = ln & 3;
        float2 v = make_float2(sm[kg * 8 + t][ng * 8 + g],
                               sm[kg * 8 + t + 4][ng * 8 + g]);
        *reinterpret_cast<float2*>(D + e * 2) = v;
    }
}

// ---------------- GEMM on packed operands: block 128x256, warp 64x64 -------------
#define STG_F 12288                         // A 4096 + B 8192 floats per stage
#define NSTAGE 3
#define GEMM_SMEM (NSTAGE * STG_F * 4)      // 147456 B

__global__ __launch_bounds__(256, 1)
void gemm_tc(const float* __restrict__ Ap, const float* __restrict__ Bp,
             float* __restrict__ C, int ldc, int round_out)
{
    extern __shared__ float sm[];
    const int tid  = threadIdx.x;
    const int lane = tid & 31, warp = tid >> 5;
    const int wm = warp >> 2, wn = warp & 3;   // 2(m) x 4(n), warp tile 64x64
    const int g = lane >> 2, t = lane & 3;

    float acc[4][8][4];
#pragma unroll
    for (int i = 0; i < 4; i++)
#pragma unroll
        for (int j = 0; j < 8; j++)
#pragma unroll
            for (int r = 0; r < 4; r++) acc[i][j][r] = 0.f;

    auto loadChunk = [&](int st, int kt) {
        float* As = sm + st * STG_F;
        float* Bs = As + 4096;
        const float* Ag = Ap + ((size_t)(blockIdx.y * KT) + kt) * 4096;
#pragma unroll
        for (int i = 0; i < 4; i++) {
            int off = (i * 256 + tid) * 4;
            cp16(smem_u32(As + off), Ag + off);
        }
        const float* Bg0 = Bp + ((size_t)((2 * blockIdx.x) * KT) + kt) * 4096;
        const float* Bg1 = Bp + ((size_t)((2 * blockIdx.x + 1) * KT) + kt) * 4096;
#pragma unroll
        for (int i = 0; i < 4; i++) {
            int off = (i * 256 + tid) * 4;
            cp16(smem_u32(Bs + off), Bg0 + off);
        }
#pragma unroll
        for (int i = 0; i < 4; i++) {
            int off = (i * 256 + tid) * 4;
            cp16(smem_u32(Bs + 4096 + off), Bg1 + off);
        }
    };

    loadChunk(0, 0); CP_COMMIT();
    loadChunk(1, 1); CP_COMMIT();

    for (int c = 0; c < KT; c++) {
        CP_WAIT(1);
        __syncthreads();   // stage c ready; buffer (c+2)%3 drained (computed at c-1)
        if (c + 2 < KT) loadChunk((c + 2) % NSTAGE, c + 2);
        CP_COMMIT();

        const float* As = sm + (c % NSTAGE) * STG_F;
        const float* Bs = As + 4096 + (wn >> 1) * 4096;
        const int nsub = (wn & 1) * 8;
#pragma unroll
        for (int kk = 0; kk < 4; kk++) {
            uint32_t af[4][4];
#pragma unroll
            for (int mi = 0; mi < 4; mi++) {
                const float4 v = *reinterpret_cast<const float4*>(
                    As + (((wm * 4 + mi) * 4 + kk) * 32 + lane) * 4);
                af[mi][0] = fu(v.x); af[mi][1] = fu(v.y);
                af[mi][2] = fu(v.z); af[mi][3] = fu(v.w);
            }
            uint32_t bf[8][2];
#pragma unroll
            for (int ni = 0; ni < 8; ni++) {
                const float2 v = *reinterpret_cast<const float2*>(
                    Bs + (((nsub + ni) * 4 + kk) * 32 + lane) * 2);
                bf[ni][0] = fu(v.x); bf[ni][1] = fu(v.y);
            }
#pragma unroll
            for (int mi = 0; mi < 4; mi++)
#pragma unroll
                for (int ni = 0; ni < 8; ni++)
                    mma8(acc[mi][ni], af[mi], bf[ni]);
        }
    }

    const int m0 = blockIdx.y * 128, n0 = blockIdx.x * 256;
#pragma unroll
    for (int mi = 0; mi < 4; mi++) {
        int row = m0 + wm * 64 + mi * 16 + g;
#pragma unroll
        for (int ni = 0; ni < 8; ni++) {
            int col = n0 + wn * 64 + ni * 8 + t * 2;
            float v0 = acc[mi][ni][0], v1 = acc[mi][ni][1];
            float v2 = acc[mi][ni][2], v3 = acc[mi][ni][3];
            if (round_out) { v0 = f2tf32(v0); v1 = f2tf32(v1); v2 = f2tf32(v2); v3 = f2tf32(v3); }
            *reinterpret_cast<float2*>(&C[(size_t)row * ldc + col]) = make_float2(v0, v1);
            *reinterpret_cast<float2*>(&C[(size_t)(row + 8) * ldc + col]) = make_float2(v2, v3);
        }
    }
}

// ---------------- RoPE (fused q+k, in place on g_qkv) ----------------------------
__global__ void rope_kernel(float* __restrict__ x, const float* __restrict__ cosb,
                            const float* __restrict__ sinb)
{
    int i = blockIdx.x * blockDim.x + threadIdx.x;
    const int total = BATCH * SEQ * (NH + NKV) * 64;
    if (i >= total) return;
    int dh = i & 63;
    int h  = (i >> 6) % (NH + NKV);
    int bs = (i >> 6) / (NH + NKV);
    float* p = x + (size_t)bs * QKV_LD + h * HD + dh;   // h<NH: q heads; else k heads
    float x1 = p[0], x2 = p[64];
    const float* cb = cosb + (size_t)bs * HD;
    const float* sb = sinb + (size_t)bs * HD;
    p[0]  = f2tf32(x1 * cb[dh]      - x2 * sb[dh]);
    p[64] = f2tf32(x2 * cb[dh + 64] + x1 * sb[dh + 64]);
}

// ---------------- flash attention (causal, GQA, online softmax, tf32 mma) --------
#define FBQ 128
#define FBK 64
#define QSTR 132
#define KSTR 132
#define VSTR 132
#define PSTR 68
#define FLASH_SMEM ((FBQ * QSTR + FBK * KSTR + FBK * VSTR + FBQ * PSTR) * 4)

__global__ __launch_bounds__(256)
void flash_kernel()
{
    extern __shared__ float sm[];
    float* Qs = sm;
    float* Ks = Qs + FBQ * QSTR;
    float* Vs = Ks + FBK * KSTR;
    float* Ps = Vs + FBK * VSTR;

    const int tid  = threadIdx.x;
    const int lane = tid & 31, warp = tid >> 5;
    const int g = lane >> 2, t = lane & 3;
    const int qt = blockIdx.x, h = blockIdx.y, b = blockIdx.z;
    const int q0 = qt * FBQ;
    const int kh = h / NREP;
    const int r0 = warp * 16;

    const float* Qg = g_qkv + ((size_t)(b * SEQ + q0)) * QKV_LD + h * HD;
    const float* Kbase = g_qkv + (size_t)b * SEQ * QKV_LD + NH * HD + kh * HD;

    auto issueKV = [&](int kt) {
        const float* Kg = Kbase + (size_t)(kt * FBK) * QKV_LD;
        const float* Vg = Kg + NKV * HD;
#pragma unroll
        for (int i = 0; i < 8; i++) {
            int l = i * 256 + tid;
            int r = l >> 5, c = (l & 31) << 2;
            cp16(smem_u32(&Ks[r * KSTR + c]), Kg + (size_t)r * QKV_LD + c);
            cp16(smem_u32(&Vs[r * VSTR + c]), Vg + (size_t)r * QKV_LD + c);
        }
    };

#pragma unroll
    for (int i = 0; i < 16; i++) {
        int l = i * 256 + tid;
        int r = l >> 5, c = (l & 31) << 2;
        cp16(smem_u32(&Qs[r * QSTR + c]), Qg + (size_t)r * QKV_LD + c);
    }
    issueKV(0);
    CP_COMMIT();

    float o[16][4];
#pragma unroll
    for (int n = 0; n < 16; n++)
#pragma unroll
        for (int r = 0; r < 4; r++) o[n][r] = 0.f;
    float mrow[2] = {-1e30f, -1e30f};
    float lrow[2] = {0.f, 0.f};

    const int nkt = qt * 2 + 2;
    for (int kt = 0; kt < nkt; kt++) {
        const int k0 = kt * FBK;
        CP_WAIT(0);
        __syncthreads();

        float s[8][4];
#pragma unroll
        for (int j = 0; j < 8; j++)
#pragma unroll
            for (int r = 0; r < 4; r++) s[j][r] = 0.f;
#pragma unroll
        for (int kk = 0; kk < 16; kk++) {
            uint32_t af[4];
            int rr = r0 + g, cc = kk * 8 + t;
            af[0] = fu(Qs[rr * QSTR + cc]);
            af[1] = fu(Qs[(rr + 8) * QSTR + cc]);
            af[2] = fu(Qs[rr * QSTR + cc + 4]);
            af[3] = fu(Qs[(rr + 8) * QSTR + cc + 4]);
#pragma unroll
            for (int j = 0; j < 8; j++) {
                uint32_t bf[2];
                int kr = j * 8 + g;
                bf[0] = fu(Ks[kr * KSTR + cc]);
                bf[1] = fu(Ks[kr * KSTR + cc + 4]);
                mma8(s[j], af, bf);
            }
        }

        const float SCALE = 0.08838834764831845f;
        const int row_lo = q0 + r0 + g;
        float nm[2] = {mrow[0], mrow[1]};
#pragma unroll
        for (int j = 0; j < 8; j++) {
            int col = k0 + j * 8 + 2 * t;
            s[j][0] = (col     <= row_lo)     ? s[j][0] * SCALE : -1e30f;
            s[j][1] = (col + 1 <= row_lo)     ? s[j][1] * SCALE : -1e30f;
            s[j][2] = (col     <= row_lo + 8) ? s[j][2] * SCALE : -1e30f;
            s[j][3] = (col + 1 <= row_lo + 8) ? s[j][3] * SCALE : -1e30f;
            nm[0] = fmaxf(nm[0], fmaxf(s[j][0], s[j][1]));
            nm[1] = fmaxf(nm[1], fmaxf(s[j][2], s[j][3]));
        }
#pragma unroll
        for (int d = 1; d < 4; d <<= 1) {
            nm[0] = fmaxf(nm[0], __shfl_xor_sync(0xffffffffu, nm[0], d));
            nm[1] = fmaxf(nm[1], __shfl_xor_sync(0xffffffffu, nm[1], d));
        }
        float alpha0 = __expf(mrow[0] - nm[0]);
        float alpha1 = __expf(mrow[1] - nm[1]);
        mrow[0] = nm[0]; mrow[1] = nm[1];
        float rs0 = 0.f, rs1 = 0.f;
#pragma unroll
        for (int j = 0; j < 8; j++) {
            s[j][0] = __expf(s[j][0] - nm[0]);
            s[j][1] = __expf(s[j][1] - nm[0]);
            s[j][2] = __expf(s[j][2] - nm[1]);
            s[j][3] = __expf(s[j][3] - nm[1]);
            rs0 += s[j][0] + s[j][1];
            rs1 += s[j][2] + s[j][3];
            int pr = r0 + g, pc = j * 8 + 2 * t;
            *reinterpret_cast<float2*>(&Ps[pr * PSTR + pc]) =
                make_float2(f2tf32(s[j][0]), f2tf32(s[j][1]));
            *reinterpret_cast<float2*>(&Ps[(pr + 8) * PSTR + pc]) =
                make_float2(f2tf32(s[j][2]), f2tf32(s[j][3]));
        }
#pragma unroll
        for (int d = 1; d < 4; d <<= 1) {
            rs0 += __shfl_xor_sync(0xffffffffu, rs0, d);
            rs1 += __shfl_xor_sync(0xffffffffu, rs1, d);
        }
        lrow[0] = lrow[0] * alpha0 + rs0;
        lrow[1] = lrow[1] * alpha1 + rs1;
#pragma unroll
        for (int n = 0; n < 16; n++) {
            o[n][0] *= alpha0; o[n][1] *= alpha0;
            o[n][2] *= alpha1; o[n][3] *= alpha1;
        }
        __syncwarp();

#pragma unroll
        for (int kk = 0; kk < 8; kk++) {
            uint32_t af[4];
            int pr = r0 + g, pc = kk * 8 + t;
            af[0] = fu(Ps[pr * PSTR + pc]);
            af[1] = fu(Ps[(pr + 8) * PSTR + pc]);
            af[2] = fu(Ps[pr * PSTR + pc + 4]);
            af[3] = fu(Ps[(pr + 8) * PSTR + pc + 4]);
#pragma unroll
            for (int n = 0; n < 16; n++) {
                uint32_t bf[2];
                int vr = kk * 8 + t, vc = n * 8 + g;
                bf[0] = fu(Vs[vr * VSTR + vc]);
                bf[1] = fu(Vs[(vr + 4) * VSTR + vc]);
                mma8(o[n], af, bf);
            }
        }

        __syncthreads();
        if (kt + 1 < nkt) issueKV(kt + 1);
        CP_COMMIT();
    }

    // normalize + write g_attn in fragment-packed layout for the O-proj GEMM
    float inv0 = 1.f / lrow[0], inv1 = 1.f / lrow[1];
    const int mtile = b * 8 + qt;
#pragma unroll
    for (int n = 0; n < 16; n++) {
        int kchunk = h * 4 + (n >> 2);
        int kgrp = n & 3;
        float* base = g_attn + ((size_t)(mtile * KT) + kchunk) * 4096
                    + ((warp * 4 + kgrp) * 32) * 4;
        int cc0 = 2 * t, cc1 = 2 * t + 1;
        int l0 = g * 4 + (cc0 & 3), rA = (cc0 >> 2) * 2;
        int l1 = g * 4 + (cc1 & 3), rB = (cc1 >> 2) * 2;
        base[l0 * 4 + rA]     = f2tf32(o[n][0] * inv0);
        base[l1 * 4 + rB]     = f2tf32(o[n][1] * inv0);
        base[l0 * 4 + rA + 1] = f2tf32(o[n][2] * inv1);
        base[l1 * 4 + rB + 1] = f2tf32(o[n][3] * inv1);
    }
}

// ---------------- launch ----------------
extern "C" void kernel_launch(void* const* d_in, const int* in_sizes, int n_in,
                              void* d_out, int out_size)
{
    const float* hs   = (const float*)d_in[0];
    const float* cosb = (const float*)d_in[1];
    const float* sinb = (const float*)d_in[2];
    // d_in[3] = attention_mask (pure causal; applied analytically in-kernel)
    const float* Wq = (const float*)d_in[4];
    const float* Wk = (const float*)d_in[5];
    const float* Wv = (const float*)d_in[6];
    const float* Wo = (const float*)d_in[7];
    float* out = (float*)d_out;

    float *hsp, *wqkvp, *wop, *qkvp, *ap;
    cudaGetSymbolAddress((void**)&hsp,   g_hsp);
    cudaGetSymbolAddress((void**)&wqkvp, g_wqkv);
    cudaGetSymbolAddress((void**)&wop,   g_wo);
    cudaGetSymbolAddress((void**)&qkvp,  g_qkv);
    cudaGetSymbolAddress((void**)&ap,    g_attn);

    cudaFuncSetAttribute(gemm_tc, cudaFuncAttributeMaxDynamicSharedMemorySize, GEMM_SMEM);
    cudaFuncSetAttribute(flash_kernel, cudaFuncAttributeMaxDynamicSharedMemorySize, FLASH_SMEM);

    const int M = BATCH * SEQ;

    // prep: pack activations + weights into fragment order (tf32-rounded)
    pack_a<<<dim3(KT, M / 128), 256>>>(hs, hsp, KDIM);
    pack_w<<<dim3(KT, (NH * HD) / 128), 256>>>(Wq, wqkvp, NH * HD);
    pack_w<<<dim3(KT, (NKV * HD) / 128), 256>>>(Wk, wqkvp + (size_t)32 * KT * 4096, NKV * HD);
    pack_w<<<dim3(KT, (NKV * HD) / 128), 256>>>(Wv, wqkvp + (size_t)40 * KT * 4096, NKV * HD);
    pack_w<<<dim3(KT, HID / 128), 256>>>(Wo, wop, HID);

    // fused QKV projection (output row-major tf32 for rope/flash)
    gemm_tc<<<dim3(QKV_N / 256, M / 128), 256, GEMM_SMEM>>>(hsp, wqkvp, qkvp, QKV_LD, 1);

    // RoPE on q+k heads (fused)
    int tot = BATCH * SEQ * (NH + NKV) * 64;
    rope_kernel<<<(tot + 255) / 256, 256>>>(qkvp, cosb, sinb);

    flash_kernel<<<dim3(SEQ / FBQ, NH, BATCH), 256, FLASH_SMEM>>>();

    // output projection: out = g_attn(packed) @ Wo(packed), fp32 output
    gemm_tc<<<dim3(HID / 256, M / 128), 256, GEMM_SMEM>>>(ap, wop, out, HID, 0);
}

// round 7
// speedup vs baseline: 2.3564x; 1.5744x over previous
#include <cuda_runtime.h>
#include <cuda_fp16.h>
#include <cstdint>

#define BATCH 2
#define SEQ   1024
#define HID   4096
#define NH    32
#define NKV   8
#define HD    128
#define NREP  4
#define QKV_N (NH * HD + 2 * NKV * HD)   // 6144
#define QKV_LD QKV_N
#define KDIM  4096
#define KC    (KDIM / 64)                // 64 k-chunks of 64

// ---------------- scratch (device globals; no allocation allowed) ----------------
__device__ uint32_t g_hsp [16 * KC * 4096];        // packed fp16 A [M/128][KC][4096 u32]
__device__ uint32_t g_wqkv[48 * KC * 4096];        // packed fp16 B [48 ntiles][KC][4096]
__device__ uint32_t g_wo  [32 * KC * 4096];        // packed fp16 B for O-proj
__device__ float    g_qkv [BATCH * SEQ * QKV_N];   // row-major fp32(tf32): q|k|v
__device__ uint32_t g_attn[16 * KC * 4096];        // packed fp16 A for O-proj

// ---------------- helpers ----------------
__device__ __forceinline__ float f2tf32(float x) {
    uint32_t u;
    asm("cvt.rna.tf32.f32 %0, %1;" : "=r"(u) : "f"(x));
    return __uint_as_float(u);
}
__device__ __forceinline__ uint32_t fu(float x) { return __float_as_uint(x); }
__device__ __forceinline__ uint32_t fp2h2(float lo, float hi) {
    __half2 h = __floats2half2_rn(lo, hi);
    return *reinterpret_cast<uint32_t*>(&h);
}

__device__ __forceinline__ uint32_t smem_u32(const void* p) {
    uint32_t a;
    asm("{ .reg .u64 t; cvta.to.shared.u64 t, %1; cvt.u32.u64 %0, t; }" : "=r"(a) : "l"(p));
    return a;
}
__device__ __forceinline__ void cp16(uint32_t dst, const void* src) {
    asm volatile("cp.async.cg.shared.global [%0], [%1], 16;" :: "r"(dst), "l"(src));
}
#define CP_COMMIT() asm volatile("cp.async.commit_group;" ::: "memory")
#define CP_WAIT(n)  asm volatile("cp.async.wait_group %0;" :: "n"(n) : "memory")

// fp16 mma m16n8k16, fp32 accum
__device__ __forceinline__ void mma16h(float* d, const uint32_t* a, const uint32_t* b) {
    asm volatile(
        "mma.sync.aligned.m16n8k16.row.col.f32.f16.f16.f32 "
        "{%0,%1,%2,%3}, {%4,%5,%6,%7}, {%8,%9}, {%0,%1,%2,%3};\n"
        : "+f"(d[0]), "+f"(d[1]), "+f"(d[2]), "+f"(d[3])
        : "r"(a[0]), "r"(a[1]), "r"(a[2]), "r"(a[3]), "r"(b[0]), "r"(b[1]));
}
// tf32 mma m16n8k8 (flash)
__device__ __forceinline__ void mma8(float* d, const uint32_t* a, const uint32_t* b) {
    asm volatile(
        "mma.sync.aligned.m16n8k8.row.col.f32.tf32.tf32.f32 "
        "{%0,%1,%2,%3}, {%4,%5,%6,%7}, {%8,%9}, {%0,%1,%2,%3};\n"
        : "+f"(d[0]), "+f"(d[1]), "+f"(d[2]), "+f"(d[3])
        : "r"(a[0]), "r"(a[1]), "r"(a[2]), "r"(a[3]), "r"(b[0]), "r"(b[1]));
}

// ---------------- prep: pack A (activations) into fp16 fragment order ------------
// src [M][K] fp32 -> dst [M/128][KC][8 mg][4 ks][32 ln][4 regs]
__global__ __launch_bounds__(256)
void pack_a_h(const float* __restrict__ src, uint32_t* __restrict__ dst, int K)
{
    __shared__ float sm[128][68];   // 68*4 = 272 B row stride: 16B-aligned
    const int tid = threadIdx.x;
    const int kc = blockIdx.x, mt = blockIdx.y;
    const float* S = src + (size_t)(mt * 128) * K + kc * 64;
#pragma unroll
    for (int i = 0; i < 8; i++) {
        int idx = i * 256 + tid;
        int r = idx >> 4, c4 = (idx & 15) << 2;
        float4 v = *reinterpret_cast<const float4*>(S + (size_t)r * K + c4);
        *reinterpret_cast<float4*>(&sm[r][c4]) = v;
    }
    __syncthreads();
    uint32_t* D = dst + ((size_t)(mt * KC) + kc) * 4096;
#pragma unroll
    for (int i = 0; i < 4; i++) {
        int p = i * 256 + tid;                 // 1024 fragment-lane positions
        int mg = p >> 7, ks = (p >> 5) & 3, ln = p & 31;
        int g = ln >> 2, t = ln & 3;
        int r = mg * 16 + g, k0 = ks * 16 + 2 * t;
        uint4 v;
        v.x = fp2h2(sm[r][k0],         sm[r][k0 + 1]);
        v.y = fp2h2(sm[r + 8][k0],     sm[r + 8][k0 + 1]);
        v.z = fp2h2(sm[r][k0 + 8],     sm[r][k0 + 9]);
        v.w = fp2h2(sm[r + 8][k0 + 8], sm[r + 8][k0 + 9]);
        *reinterpret_cast<uint4*>(D + p * 4) = v;
    }
}

// ---------------- prep: pack W [K][N] into fp16 fragment order -------------------
// dst [ntile][KC][16 ng][4 ks][32 ln][2 regs]
__global__ __launch_bounds__(256)
void pack_w_h(const float* __restrict__ W, uint32_t* __restrict__ dst, int N)
{
    __shared__ float sm[64][132];   // 132*4 = 528 B row stride: 16B-aligned
    const int tid = threadIdx.x;
    const int kc = blockIdx.x, nt = blockIdx.y;
    const float* S = W + (size_t)(kc * 64) * N + nt * 128;
#pragma unroll
    for (int i = 0; i < 8; i++) {
        int idx = i * 256 + tid;
        int r = idx >> 5, c4 = (idx & 31) << 2;
        float4 v = *reinterpret_cast<const float4*>(S + (size_t)r * N + c4);
        *reinterpret_cast<float4*>(&sm[r][c4]) = v;
    }
    __syncthreads();
    uint32_t* D = dst + ((size_t)(nt * KC) + kc) * 4096;
#pragma unroll
    for (int i = 0; i < 8; i++) {
        int p = i * 256 + tid;                 // 2048 positions x 2 regs
        int ng = p >> 7, ks = (p >> 5) & 3, ln = p & 31;
        int g = ln >> 2, t = ln & 3;
        int n = ng * 8 + g, k0 = ks * 16 + 2 * t;
        uint2 v;
        v.x = fp2h2(sm[k0][n],     sm[k0 + 1][n]);
        v.y = fp2h2(sm[k0 + 8][n], sm[k0 + 9][n]);
        *reinterpret_cast<uint2*>(D + p * 2) = v;
    }
}

// ---------------- fp16 GEMM: block 128x256, warp 64x64, 3-stage cp.async ---------
#define STG_U 12288                         // u32/stage: A 4096 + B 8192
#define NSTAGE 3
#define GEMM_SMEM (NSTAGE * STG_U * 4)      // 147456 B

__global__ __launch_bounds__(256, 1)
void gemm_h(const uint32_t* __restrict__ Ap, const uint32_t* __restrict__ Bp,
            float* __restrict__ C, int ldc, int round_out)
{
    extern __shared__ uint32_t sm[];
    const int tid  = threadIdx.x;
    const int lane = tid & 31, warp = tid >> 5;
    const int wm = warp >> 2, wn = warp & 3;   // 2(m) x 4(n), warp tile 64x64
    const int g = lane >> 2, t = lane & 3;

    float acc[4][8][4];
#pragma unroll
    for (int i = 0; i < 4; i++)
#pragma unroll
        for (int j = 0; j < 8; j++)
#pragma unroll
            for (int r = 0; r < 4; r++) acc[i][j][r] = 0.f;

    auto loadChunk = [&](int st, int kt) {
        uint32_t* As = sm + st * STG_U;
        uint32_t* Bs = As + 4096;
        const uint32_t* Ag = Ap + ((size_t)(blockIdx.y * KC) + kt) * 4096;
#pragma unroll
        for (int i = 0; i < 4; i++) {
            int off = (i * 256 + tid) * 4;
            cp16(smem_u32(As + off), Ag + off);
        }
        const uint32_t* Bg0 = Bp + ((size_t)((2 * blockIdx.x) * KC) + kt) * 4096;
        const uint32_t* Bg1 = Bp + ((size_t)((2 * blockIdx.x + 1) * KC) + kt) * 4096;
#pragma unroll
        for (int i = 0; i < 4; i++) {
            int off = (i * 256 + tid) * 4;
            cp16(smem_u32(Bs + off), Bg0 + off);
        }
#pragma unroll
        for (int i = 0; i < 4; i++) {
            int off = (i * 256 + tid) * 4;
            cp16(smem_u32(Bs + 4096 + off), Bg1 + off);
        }
    };

    loadChunk(0, 0); CP_COMMIT();
    loadChunk(1, 1); CP_COMMIT();

    for (int c = 0; c < KC; c++) {
        CP_WAIT(1);
        __syncthreads();
        if (c + 2 < KC) loadChunk((c + 2) % NSTAGE, c + 2);
        CP_COMMIT();

        const uint32_t* As = sm + (c % NSTAGE) * STG_U;
        const uint32_t* Bs = As + 4096 + (wn >> 1) * 4096;
        const int nsub = (wn & 1) * 8;
#pragma unroll
        for (int ks = 0; ks < 4; ks++) {
            uint32_t af[4][4];
#pragma unroll
            for (int mi = 0; mi < 4; mi++) {
                const uint4 v = *reinterpret_cast<const uint4*>(
                    As + ((wm * 4 + mi) * 4 + ks) * 128 + lane * 4);
                af[mi][0] = v.x; af[mi][1] = v.y; af[mi][2] = v.z; af[mi][3] = v.w;
            }
            uint32_t bf[8][2];
#pragma unroll
            for (int ni = 0; ni < 8; ni++) {
                const uint2 v = *reinterpret_cast<const uint2*>(
                    Bs + ((nsub + ni) * 4 + ks) * 64 + lane * 2);
                bf[ni][0] = v.x; bf[ni][1] = v.y;
            }
#pragma unroll
            for (int mi = 0; mi < 4; mi++)
#pragma unroll
                for (int ni = 0; ni < 8; ni++)
                    mma16h(acc[mi][ni], af[mi], bf[ni]);
        }
    }

    const int m0 = blockIdx.y * 128, n0 = blockIdx.x * 256;
#pragma unroll
    for (int mi = 0; mi < 4; mi++) {
        int row = m0 + wm * 64 + mi * 16 + g;
#pragma unroll
        for (int ni = 0; ni < 8; ni++) {
            int col = n0 + wn * 64 + ni * 8 + t * 2;
            float v0 = acc[mi][ni][0], v1 = acc[mi][ni][1];
            float v2 = acc[mi][ni][2], v3 = acc[mi][ni][3];
            if (round_out) { v0 = f2tf32(v0); v1 = f2tf32(v1); v2 = f2tf32(v2); v3 = f2tf32(v3); }
            *reinterpret_cast<float2*>(&C[(size_t)row * ldc + col]) = make_float2(v0, v1);
            *reinterpret_cast<float2*>(&C[(size_t)(row + 8) * ldc + col]) = make_float2(v2, v3);
        }
    }
}

// ---------------- RoPE (fused q+k, in place on g_qkv) ----------------------------
__global__ void rope_kernel(float* __restrict__ x, const float* __restrict__ cosb,
                            const float* __restrict__ sinb)
{
    int i = blockIdx.x * blockDim.x + threadIdx.x;
    const int total = BATCH * SEQ * (NH + NKV) * 64;
    if (i >= total) return;
    int dh = i & 63;
    int h  = (i >> 6) % (NH + NKV);
    int bs = (i >> 6) / (NH + NKV);
    float* p = x + (size_t)bs * QKV_LD + h * HD + dh;
    float x1 = p[0], x2 = p[64];
    const float* cb = cosb + (size_t)bs * HD;
    const float* sb = sinb + (size_t)bs * HD;
    p[0]  = f2tf32(x1 * cb[dh]      - x2 * sb[dh]);
    p[64] = f2tf32(x2 * cb[dh + 64] + x1 * sb[dh + 64]);
}

// ---------------- flash attention (tf32, causal, GQA, online softmax) ------------
#define FBQ 128
#define FBK 64
#define QSTR 132
#define KSTR 132
#define VSTR 132
#define PSTR 68
#define FLASH_SMEM ((FBQ * QSTR + FBK * KSTR + FBK * VSTR + FBQ * PSTR) * 4)

__global__ __launch_bounds__(256)
void flash_kernel()
{
    extern __shared__ float smf[];
    float* Qs = smf;
    float* Ks = Qs + FBQ * QSTR;
    float* Vs = Ks + FBK * KSTR;
    float* Ps = Vs + FBK * VSTR;

    const int tid  = threadIdx.x;
    const int lane = tid & 31, warp = tid >> 5;
    const int g = lane >> 2, t = lane & 3;
    const int qt = blockIdx.x, h = blockIdx.y, b = blockIdx.z;
    const int q0 = qt * FBQ;
    const int kh = h / NREP;
    const int r0 = warp * 16;

    const float* Qg = g_qkv + ((size_t)(b * SEQ + q0)) * QKV_LD + h * HD;
    const float* Kbase = g_qkv + (size_t)b * SEQ * QKV_LD + NH * HD + kh * HD;

    auto issueKV = [&](int kt) {
        const float* Kg = Kbase + (size_t)(kt * FBK) * QKV_LD;
        const float* Vg = Kg + NKV * HD;
#pragma unroll
        for (int i = 0; i < 8; i++) {
            int l = i * 256 + tid;
            int r = l >> 5, c = (l & 31) << 2;
            cp16(smem_u32(&Ks[r * KSTR + c]), Kg + (size_t)r * QKV_LD + c);
            cp16(smem_u32(&Vs[r * VSTR + c]), Vg + (size_t)r * QKV_LD + c);
        }
    };

#pragma unroll
    for (int i = 0; i < 16; i++) {
        int l = i * 256 + tid;
        int r = l >> 5, c = (l & 31) << 2;
        cp16(smem_u32(&Qs[r * QSTR + c]), Qg + (size_t)r * QKV_LD + c);
    }
    issueKV(0);
    CP_COMMIT();

    float o[16][4];
#pragma unroll
    for (int n = 0; n < 16; n++)
#pragma unroll
        for (int r = 0; r < 4; r++) o[n][r] = 0.f;
    float mrow[2] = {-1e30f, -1e30f};
    float lrow[2] = {0.f, 0.f};

    const int nkt = qt * 2 + 2;
    for (int kt = 0; kt < nkt; kt++) {
        const int k0 = kt * FBK;
        CP_WAIT(0);
        __syncthreads();

        float s[8][4];
#pragma unroll
        for (int j = 0; j < 8; j++)
#pragma unroll
            for (int r = 0; r < 4; r++) s[j][r] = 0.f;
#pragma unroll
        for (int kk = 0; kk < 16; kk++) {
            uint32_t af[4];
            int rr = r0 + g, cc = kk * 8 + t;
            af[0] = fu(Qs[rr * QSTR + cc]);
            af[1] = fu(Qs[(rr + 8) * QSTR + cc]);
            af[2] = fu(Qs[rr * QSTR + cc + 4]);
            af[3] = fu(Qs[(rr + 8) * QSTR + cc + 4]);
#pragma unroll
            for (int j = 0; j < 8; j++) {
                uint32_t bf[2];
                int kr = j * 8 + g;
                bf[0] = fu(Ks[kr * KSTR + cc]);
                bf[1] = fu(Ks[kr * KSTR + cc + 4]);
                mma8(s[j], af, bf);
            }
        }

        const float SCALE = 0.08838834764831845f;
        const int row_lo = q0 + r0 + g;
        float nm[2] = {mrow[0], mrow[1]};
#pragma unroll
        for (int j = 0; j < 8; j++) {
            int col = k0 + j * 8 + 2 * t;
            s[j][0] = (col     <= row_lo)     ? s[j][0] * SCALE : -1e30f;
            s[j][1] = (col + 1 <= row_lo)     ? s[j][1] * SCALE : -1e30f;
            s[j][2] = (col     <= row_lo + 8) ? s[j][2] * SCALE : -1e30f;
            s[j][3] = (col + 1 <= row_lo + 8) ? s[j][3] * SCALE : -1e30f;
            nm[0] = fmaxf(nm[0], fmaxf(s[j][0], s[j][1]));
            nm[1] = fmaxf(nm[1], fmaxf(s[j][2], s[j][3]));
        }
#pragma unroll
        for (int d = 1; d < 4; d <<= 1) {
            nm[0] = fmaxf(nm[0], __shfl_xor_sync(0xffffffffu, nm[0], d));
            nm[1] = fmaxf(nm[1], __shfl_xor_sync(0xffffffffu, nm[1], d));
        }
        float alpha0 = __expf(mrow[0] - nm[0]);
        float alpha1 = __expf(mrow[1] - nm[1]);
        mrow[0] = nm[0]; mrow[1] = nm[1];
        float rs0 = 0.f, rs1 = 0.f;
#pragma unroll
        for (int j = 0; j < 8; j++) {
            s[j][0] = __expf(s[j][0] - nm[0]);
            s[j][1] = __expf(s[j][1] - nm[0]);
            s[j][2] = __expf(s[j][2] - nm[1]);
            s[j][3] = __expf(s[j][3] - nm[1]);
            rs0 += s[j][0] + s[j][1];
            rs1 += s[j][2] + s[j][3];
            int pr = r0 + g, pc = j * 8 + 2 * t;
            *reinterpret_cast<float2*>(&Ps[pr * PSTR + pc]) =
                make_float2(f2tf32(s[j][0]), f2tf32(s[j][1]));
            *reinterpret_cast<float2*>(&Ps[(pr + 8) * PSTR + pc]) =
                make_float2(f2tf32(s[j][2]), f2tf32(s[j][3]));
        }
#pragma unroll
        for (int d = 1; d < 4; d <<= 1) {
            rs0 += __shfl_xor_sync(0xffffffffu, rs0, d);
            rs1 += __shfl_xor_sync(0xffffffffu, rs1, d);
        }
        lrow[0] = lrow[0] * alpha0 + rs0;
        lrow[1] = lrow[1] * alpha1 + rs1;
#pragma unroll
        for (int n = 0; n < 16; n++) {
            o[n][0] *= alpha0; o[n][1] *= alpha0;
            o[n][2] *= alpha1; o[n][3] *= alpha1;
        }
        __syncwarp();

#pragma unroll
        for (int kk = 0; kk < 8; kk++) {
            uint32_t af[4];
            int pr = r0 + g, pc = kk * 8 + t;
            af[0] = fu(Ps[pr * PSTR + pc]);
            af[1] = fu(Ps[(pr + 8) * PSTR + pc]);
            af[2] = fu(Ps[pr * PSTR + pc + 4]);
            af[3] = fu(Ps[(pr + 8) * PSTR + pc + 4]);
#pragma unroll
            for (int n = 0; n < 16; n++) {
                uint32_t bf[2];
                int vr = kk * 8 + t, vc = n * 8 + g;
                bf[0] = fu(Vs[vr * VSTR + vc]);
                bf[1] = fu(Vs[(vr + 4) * VSTR + vc]);
                mma8(o[n], af, bf);
            }
        }

        __syncthreads();
        if (kt + 1 < nkt) issueKV(kt + 1);
        CP_COMMIT();
    }

    // normalize + write g_attn as packed fp16 fragments for the fp16 O-proj GEMM.
    // k_global = h*128 + n*8 + cc; kchunk = h*2 + (n>>3); kstep = ((n&7)*4+t)>>3;
    // lane' = lane; reg = (n&1)*2 + (row>>3); half-pair = (cc, cc+1) = (2t, 2t+1).
    float inv0 = 1.f / lrow[0], inv1 = 1.f / lrow[1];
    const int mtile = b * 8 + qt;
    uint32_t* base_mt = g_attn + (size_t)mtile * KC * 4096;
#pragma unroll
    for (int n = 0; n < 16; n++) {
        int kchunk = h * 2 + (n >> 3);
        int kstep = (((n & 7) * 4) + t) >> 3;
        uint32_t* e = base_mt + (size_t)kchunk * 4096 + ((warp * 4 + kstep) * 32 + lane) * 4;
        int rb = (n & 1) * 2;
        e[rb]     = fp2h2(o[n][0] * inv0, o[n][1] * inv0);
        e[rb + 1] = fp2h2(o[n][2] * inv1, o[n][3] * inv1);
    }
}

// ---------------- launch ----------------
extern "C" void kernel_launch(void* const* d_in, const int* in_sizes, int n_in,
                              void* d_out, int out_size)
{
    const float* hs   = (const float*)d_in[0];
    const float* cosb = (const float*)d_in[1];
    const float* sinb = (const float*)d_in[2];
    // d_in[3] = attention_mask (pure causal; applied analytically in-kernel)
    const float* Wq = (const float*)d_in[4];
    const float* Wk = (const float*)d_in[5];
    const float* Wv = (const float*)d_in[6];
    const float* Wo = (const float*)d_in[7];
    float* out = (float*)d_out;

    uint32_t *hsp, *wqkvp, *wop, *ap;
    float *qkvp;
    cudaGetSymbolAddress((void**)&hsp,   g_hsp);
    cudaGetSymbolAddress((void**)&wqkvp, g_wqkv);
    cudaGetSymbolAddress((void**)&wop,   g_wo);
    cudaGetSymbolAddress((void**)&qkvp,  g_qkv);
    cudaGetSymbolAddress((void**)&ap,    g_attn);

    cudaFuncSetAttribute(gemm_h, cudaFuncAttributeMaxDynamicSharedMemorySize, GEMM_SMEM);
    cudaFuncSetAttribute(flash_kernel, cudaFuncAttributeMaxDynamicSharedMemorySize, FLASH_SMEM);

    const int M = BATCH * SEQ;

    // prep: pack activations + weights into fp16 fragment order
    pack_a_h<<<dim3(KC, M / 128), 256>>>(hs, hsp, KDIM);
    pack_w_h<<<dim3(KC, (NH * HD) / 128), 256>>>(Wq, wqkvp, NH * HD);
    pack_w_h<<<dim3(KC, (NKV * HD) / 128), 256>>>(Wk, wqkvp + (size_t)32 * KC * 4096, NKV * HD);
    pack_w_h<<<dim3(KC, (NKV * HD) / 128), 256>>>(Wv, wqkvp + (size_t)40 * KC * 4096, NKV * HD);
    pack_w_h<<<dim3(KC, HID / 128), 256>>>(Wo, wop, HID);

    // fused QKV projection (fp16 mma, fp32->tf32-rounded output for flash)
    gemm_h<<<dim3(QKV_N / 256, M / 128), 256, GEMM_SMEM>>>(hsp, wqkvp, qkvp, QKV_LD, 1);

    // RoPE on q+k heads (fused)
    int tot = BATCH * SEQ * (NH + NKV) * 64;
    rope_kernel<<<(tot + 255) / 256, 256>>>(qkvp, cosb, sinb);

    flash_kernel<<<dim3(SEQ / FBQ, NH, BATCH), 256, FLASH_SMEM>>>();

    // output projection: out = attn(packed fp16) @ Wo(packed fp16), fp32 output
    gemm_h<<<dim3(HID / 256, M / 128), 256, GEMM_SMEM>>>(ap, wop, out, HID, 0);
}

// round 8
// speedup vs baseline: 2.7984x; 1.1876x over previous
#include <cuda_runtime.h>
#include <cuda_fp16.h>
#include <cstdint>

#define BATCH 2
#define SEQ   1024
#define HID   4096
#define NH    32
#define NKV   8
#define HD    128
#define NREP  4
#define QKV_N (NH * HD + 2 * NKV * HD)   // 6144
#define KDIM  4096
#define KC    (KDIM / 64)                // 64 k-chunks of 64

// ---------------- scratch (device globals; no allocation allowed) ----------------
__device__ uint32_t g_hsp [16 * KC * 4096];        // packed fp16 A [M/128][KC][4096 u32]
__device__ uint32_t g_wqkv[48 * KC * 4096];        // packed fp16 B [48 ntiles][KC][4096]
__device__ uint32_t g_wo  [32 * KC * 4096];        // packed fp16 B for O-proj
__device__ __half   g_qkvh[BATCH * SEQ * QKV_N];   // fp16 row-major: q|k|v
__device__ __half   g_vt  [BATCH * NKV * HD * SEQ];// V^T: [b][kh][d][s] fp16
__device__ uint32_t g_attn[16 * KC * 4096];        // packed fp16 A for O-proj

// ---------------- helpers ----------------
__device__ __forceinline__ uint32_t fp2h2(float lo, float hi) {
    __half2 h = __floats2half2_rn(lo, hi);
    return *reinterpret_cast<uint32_t*>(&h);
}
__device__ __forceinline__ uint32_t smem_u32(const void* p) {
    uint32_t a;
    asm("{ .reg .u64 t; cvta.to.shared.u64 t, %1; cvt.u32.u64 %0, t; }" : "=r"(a) : "l"(p));
    return a;
}
__device__ __forceinline__ void cp16(uint32_t dst, const void* src) {
    asm volatile("cp.async.cg.shared.global [%0], [%1], 16;" :: "r"(dst), "l"(src));
}
#define CP_COMMIT() asm volatile("cp.async.commit_group;" ::: "memory")
#define CP_WAIT(n)  asm volatile("cp.async.wait_group %0;" :: "n"(n) : "memory")

// fp16 mma m16n8k16, fp32 accum
__device__ __forceinline__ void mma16h(float* d, const uint32_t* a, const uint32_t* b) {
    asm volatile(
        "mma.sync.aligned.m16n8k16.row.col.f32.f16.f16.f32 "
        "{%0,%1,%2,%3}, {%4,%5,%6,%7}, {%8,%9}, {%0,%1,%2,%3};\n"
        : "+f"(d[0]), "+f"(d[1]), "+f"(d[2]), "+f"(d[3])
        : "r"(a[0]), "r"(a[1]), "r"(a[2]), "r"(a[3]), "r"(b[0]), "r"(b[1]));
}

// ---------------- prep: pack A (activations) into fp16 fragment order ------------
__global__ __launch_bounds__(256)
void pack_a_h(const float* __restrict__ src, uint32_t* __restrict__ dst, int K)
{
    __shared__ float sm[128][68];
    const int tid = threadIdx.x;
    const int kc = blockIdx.x, mt = blockIdx.y;
    const float* S = src + (size_t)(mt * 128) * K + kc * 64;
#pragma unroll
    for (int i = 0; i < 8; i++) {
        int idx = i * 256 + tid;
        int r = idx >> 4, c4 = (idx & 15) << 2;
        float4 v = *reinterpret_cast<const float4*>(S + (size_t)r * K + c4);
        *reinterpret_cast<float4*>(&sm[r][c4]) = v;
    }
    __syncthreads();
    uint32_t* D = dst + ((size_t)(mt * KC) + kc) * 4096;
#pragma unroll
    for (int i = 0; i < 4; i++) {
        int p = i * 256 + tid;
        int mg = p >> 7, ks = (p >> 5) & 3, ln = p & 31;
        int g = ln >> 2, t = ln & 3;
        int r = mg * 16 + g, k0 = ks * 16 + 2 * t;
        uint4 v;
        v.x = fp2h2(sm[r][k0],         sm[r][k0 + 1]);
        v.y = fp2h2(sm[r + 8][k0],     sm[r + 8][k0 + 1]);
        v.z = fp2h2(sm[r][k0 + 8],     sm[r][k0 + 9]);
        v.w = fp2h2(sm[r + 8][k0 + 8], sm[r + 8][k0 + 9]);
        *reinterpret_cast<uint4*>(D + p * 4) = v;
    }
}

// ---------------- prep: pack W [K][N] into fp16 fragment order -------------------
__global__ __launch_bounds__(256)
void pack_w_h(const float* __restrict__ W, uint32_t* __restrict__ dst, int N)
{
    __shared__ float sm[64][132];
    const int tid = threadIdx.x;
    const int kc = blockIdx.x, nt = blockIdx.y;
    const float* S = W + (size_t)(kc * 64) * N + nt * 128;
#pragma unroll
    for (int i = 0; i < 8; i++) {
        int idx = i * 256 + tid;
        int r = idx >> 5, c4 = (idx & 31) << 2;
        float4 v = *reinterpret_cast<const float4*>(S + (size_t)r * N + c4);
        *reinterpret_cast<float4*>(&sm[r][c4]) = v;
    }
    __syncthreads();
    uint32_t* D = dst + ((size_t)(nt * KC) + kc) * 4096;
#pragma unroll
    for (int i = 0; i < 8; i++) {
        int p = i * 256 + tid;
        int ng = p >> 7, ks = (p >> 5) & 3, ln = p & 31;
        int g = ln >> 2, t = ln & 3;
        int n = ng * 8 + g, k0 = ks * 16 + 2 * t;
        uint2 v;
        v.x = fp2h2(sm[k0][n],     sm[k0 + 1][n]);
        v.y = fp2h2(sm[k0 + 8][n], sm[k0 + 9][n]);
        *reinterpret_cast<uint2*>(D + p * 2) = v;
    }
}

// ---------------- fp16 GEMM: block 128x256, warp 64x64, 3-stage cp.async ---------
#define STG_U 12288
#define NSTAGE 3
#define GEMM_SMEM (NSTAGE * STG_U * 4)

__global__ __launch_bounds__(256, 1)
void gemm_h(const uint32_t* __restrict__ Ap, const uint32_t* __restrict__ Bp,
            void* __restrict__ Cv, int ldc, int half_out)
{
    extern __shared__ uint32_t sm[];
    const int tid  = threadIdx.x;
    const int lane = tid & 31, warp = tid >> 5;
    const int wm = warp >> 2, wn = warp & 3;
    const int g = lane >> 2, t = lane & 3;

    float acc[4][8][4];
#pragma unroll
    for (int i = 0; i < 4; i++)
#pragma unroll
        for (int j = 0; j < 8; j++)
#pragma unroll
            for (int r = 0; r < 4; r++) acc[i][j][r] = 0.f;

    auto loadChunk = [&](int st, int kt) {
        uint32_t* As = sm + st * STG_U;
        uint32_t* Bs = As + 4096;
        const uint32_t* Ag = Ap + ((size_t)(blockIdx.y * KC) + kt) * 4096;
#pragma unroll
        for (int i = 0; i < 4; i++) {
            int off = (i * 256 + tid) * 4;
            cp16(smem_u32(As + off), Ag + off);
        }
        const uint32_t* Bg0 = Bp + ((size_t)((2 * blockIdx.x) * KC) + kt) * 4096;
        const uint32_t* Bg1 = Bp + ((size_t)((2 * blockIdx.x + 1) * KC) + kt) * 4096;
#pragma unroll
        for (int i = 0; i < 4; i++) {
            int off = (i * 256 + tid) * 4;
            cp16(smem_u32(Bs + off), Bg0 + off);
        }
#pragma unroll
        for (int i = 0; i < 4; i++) {
            int off = (i * 256 + tid) * 4;
            cp16(smem_u32(Bs + 4096 + off), Bg1 + off);
        }
    };

    loadChunk(0, 0); CP_COMMIT();
    loadChunk(1, 1); CP_COMMIT();

    for (int c = 0; c < KC; c++) {
        CP_WAIT(1);
        __syncthreads();
        if (c + 2 < KC) loadChunk((c + 2) % NSTAGE, c + 2);
        CP_COMMIT();

        const uint32_t* As = sm + (c % NSTAGE) * STG_U;
        const uint32_t* Bs = As + 4096 + (wn >> 1) * 4096;
        const int nsub = (wn & 1) * 8;
#pragma unroll
        for (int ks = 0; ks < 4; ks++) {
            uint32_t af[4][4];
#pragma unroll
            for (int mi = 0; mi < 4; mi++) {
                const uint4 v = *reinterpret_cast<const uint4*>(
                    As + ((wm * 4 + mi) * 4 + ks) * 128 + lane * 4);
                af[mi][0] = v.x; af[mi][1] = v.y; af[mi][2] = v.z; af[mi][3] = v.w;
            }
            uint32_t bf[8][2];
#pragma unroll
            for (int ni = 0; ni < 8; ni++) {
                const uint2 v = *reinterpret_cast<const uint2*>(
                    Bs + ((nsub + ni) * 4 + ks) * 64 + lane * 2);
                bf[ni][0] = v.x; bf[ni][1] = v.y;
            }
#pragma unroll
            for (int mi = 0; mi < 4; mi++)
#pragma unroll
                for (int ni = 0; ni < 8; ni++)
                    mma16h(acc[mi][ni], af[mi], bf[ni]);
        }
    }

    const int m0 = blockIdx.y * 128, n0 = blockIdx.x * 256;
    if (half_out) {
        __half* C = (__half*)Cv;
#pragma unroll
        for (int mi = 0; mi < 4; mi++) {
            int row = m0 + wm * 64 + mi * 16 + g;
#pragma unroll
            for (int ni = 0; ni < 8; ni++) {
                int col = n0 + wn * 64 + ni * 8 + t * 2;
                *reinterpret_cast<uint32_t*>(&C[(size_t)row * ldc + col]) =
                    fp2h2(acc[mi][ni][0], acc[mi][ni][1]);
                *reinterpret_cast<uint32_t*>(&C[(size_t)(row + 8) * ldc + col]) =
                    fp2h2(acc[mi][ni][2], acc[mi][ni][3]);
            }
        }
    } else {
        float* C = (float*)Cv;
#pragma unroll
        for (int mi = 0; mi < 4; mi++) {
            int row = m0 + wm * 64 + mi * 16 + g;
#pragma unroll
            for (int ni = 0; ni < 8; ni++) {
                int col = n0 + wn * 64 + ni * 8 + t * 2;
                *reinterpret_cast<float2*>(&C[(size_t)row * ldc + col]) =
                    make_float2(acc[mi][ni][0], acc[mi][ni][1]);
                *reinterpret_cast<float2*>(&C[(size_t)(row + 8) * ldc + col]) =
                    make_float2(acc[mi][ni][2], acc[mi][ni][3]);
            }
        }
    }
}

// ---------------- RoPE (fused q+k, in place on fp16 g_qkvh) ----------------------
__global__ void rope_kernel(const float* __restrict__ cosb, const float* __restrict__ sinb)
{
    int i = blockIdx.x * blockDim.x + threadIdx.x;
    const int total = BATCH * SEQ * (NH + NKV) * 64;
    if (i >= total) return;
    int dh = i & 63;
    int h  = (i >> 6) % (NH + NKV);
    int bs = (i >> 6) / (NH + NKV);
    __half* p = g_qkvh + (size_t)bs * QKV_N + h * HD + dh;
    float x1 = __half2float(p[0]), x2 = __half2float(p[64]);
    const float* cb = cosb + (size_t)bs * HD;
    const float* sb = sinb + (size_t)bs * HD;
    p[0]  = __float2half_rn(x1 * cb[dh]      - x2 * sb[dh]);
    p[64] = __float2half_rn(x2 * cb[dh + 64] + x1 * sb[dh + 64]);
}

// ---------------- V transpose: g_qkvh v-region [s][d] -> g_vt [b][kh][d][s] ------
__global__ __launch_bounds__(256)
void v_transpose()
{
    __shared__ __half ts[64][72];
    const int tid = threadIdx.x;
    const int st = blockIdx.x;               // s tile (0..15)
    const int yy = blockIdx.y;               // 0..31
    const int bkh = yy >> 1, dt = yy & 1;
    const int b = bkh / NKV;
    const __half* src = g_qkvh + ((size_t)(b * SEQ + st * 64)) * QKV_N
                      + NH * HD + NKV * HD + (bkh % NKV) * HD + dt * 64;
#pragma unroll
    for (int i = 0; i < 16; i++) {
        int e = i * 256 + tid;
        int si = e >> 6, di = e & 63;
        ts[si][di] = src[(size_t)si * QKV_N + di];
    }
    __syncthreads();
    __half* dst = g_vt + ((size_t)(bkh * HD + dt * 64)) * SEQ + st * 64;
#pragma unroll
    for (int i = 0; i < 16; i++) {
        int e = i * 256 + tid;
        int di = e >> 6, si = e & 63;
        dst[(size_t)di * SEQ + si] = ts[si][di];
    }
}

// ---------------- flash attention (fp16 mma, causal, GQA, online softmax) --------
#define FBQ 128
#define FBK 64
#define QSH 136                               // halves per Q row (272 B, 16B-aligned)
#define VSH 72                                // halves per V^T row (144 B)
#define FLASH_SMEM ((128 * QSH + 64 * 128 + 128 * VSH) * 2)   // 69632 B

__global__ __launch_bounds__(256)
void flash_kernel()
{
    extern __shared__ __half smh[];
    __half* Qs = smh;                   // [128][QSH]
    __half* Ks = Qs + 128 * QSH;        // [64][128], chunk-swizzled
    __half* Vs = Ks + 64 * 128;         // [128][VSH]  (V^T: d rows, k inner)

    const int tid  = threadIdx.x;
    const int lane = tid & 31, warp = tid >> 5;
    const int g = lane >> 2, t = lane & 3;
    const int qt = blockIdx.x, h = blockIdx.y, b = blockIdx.z;
    const int q0 = qt * FBQ;
    const int kh = h / NREP;
    const int r0 = warp * 16;

    const __half* Qg  = g_qkvh + ((size_t)(b * SEQ + q0)) * QKV_N + h * HD;
    const __half* Kb  = g_qkvh + (size_t)b * SEQ * QKV_N + NH * HD + kh * HD;
    const __half* Vtb = g_vt + ((size_t)(b * NKV + kh)) * HD * SEQ;

    auto issueKV = [&](int kt) {
        const __half* Kg = Kb + (size_t)(kt * FBK) * QKV_N;
#pragma unroll
        for (int i = 0; i < 4; i++) {          // K: 64 rows x 128 halves, swizzled chunks
            int l = i * 256 + tid;
            int r = l >> 4, cs = l & 15;
            cp16(smem_u32(Ks + r * 128 + ((cs ^ (r & 7)) << 3)), Kg + (size_t)r * QKV_N + cs * 8);
        }
        const __half* Vg = Vtb + kt * FBK;
#pragma unroll
        for (int i = 0; i < 4; i++) {          // V^T: 128 d-rows x 64 halves
            int l = i * 256 + tid;
            int r = l >> 3, c = (l & 7) << 3;
            cp16(smem_u32(Vs + r * VSH + c), Vg + (size_t)r * SEQ + c);
        }
    };

#pragma unroll
    for (int i = 0; i < 8; i++) {              // Q: 128 rows x 128 halves
        int l = i * 256 + tid;
        int r = l >> 4, c = (l & 15) << 3;
        cp16(smem_u32(Qs + r * QSH + c), Qg + (size_t)r * QKV_N + c);
    }
    issueKV(0);
    CP_COMMIT();

    float o[16][4];
#pragma unroll
    for (int n = 0; n < 16; n++)
#pragma unroll
        for (int r = 0; r < 4; r++) o[n][r] = 0.f;
    float mrow[2] = {-1e30f, -1e30f};
    float lrow[2] = {0.f, 0.f};

    const int nkt = qt * 2 + 2;
    for (int kt = 0; kt < nkt; kt++) {
        const int k0 = kt * FBK;
        CP_WAIT(0);
        __syncthreads();

        // S = Q @ K^T  (warp: 16 x 64, k = 128 -> 8 k16 steps)
        float s[8][4];
#pragma unroll
        for (int j = 0; j < 8; j++)
#pragma unroll
            for (int r = 0; r < 4; r++) s[j][r] = 0.f;
#pragma unroll
        for (int ks = 0; ks < 8; ks++) {
            uint32_t af[4];
            const int rr = r0 + g, cc = ks * 16 + 2 * t;
            af[0] = *reinterpret_cast<const uint32_t*>(&Qs[rr * QSH + cc]);
            af[1] = *reinterpret_cast<const uint32_t*>(&Qs[(rr + 8) * QSH + cc]);
            af[2] = *reinterpret_cast<const uint32_t*>(&Qs[rr * QSH + cc + 8]);
            af[3] = *reinterpret_cast<const uint32_t*>(&Qs[(rr + 8) * QSH + cc + 8]);
#pragma unroll
            for (int j = 0; j < 8; j++) {
                const int kr = j * 8 + g;
                const int base = kr * 128 + 2 * t;
                uint32_t bf[2];
                bf[0] = *reinterpret_cast<const uint32_t*>(&Ks[base + (((2 * ks)     ^ g) << 3)]);
                bf[1] = *reinterpret_cast<const uint32_t*>(&Ks[base + (((2 * ks + 1) ^ g) << 3)]);
                mma16h(s[j], af, bf);
            }
        }

        // online softmax (rows warp-local; reduce over 4 lanes sharing a row)
        const float SCALE = 0.08838834764831845f;   // 1/sqrt(128)
        const int row_lo = q0 + r0 + g;
        float nm[2] = {mrow[0], mrow[1]};
#pragma unroll
        for (int j = 0; j < 8; j++) {
            int col = k0 + j * 8 + 2 * t;
            s[j][0] = (col     <= row_lo)     ? s[j][0] * SCALE : -1e30f;
            s[j][1] = (col + 1 <= row_lo)     ? s[j][1] * SCALE : -1e30f;
            s[j][2] = (col     <= row_lo + 8) ? s[j][2] * SCALE : -1e30f;
            s[j][3] = (col + 1 <= row_lo + 8) ? s[j][3] * SCALE : -1e30f;
            nm[0] = fmaxf(nm[0], fmaxf(s[j][0], s[j][1]));
            nm[1] = fmaxf(nm[1], fmaxf(s[j][2], s[j][3]));
        }
#pragma unroll
        for (int d = 1; d < 4; d <<= 1) {
            nm[0] = fmaxf(nm[0], __shfl_xor_sync(0xffffffffu, nm[0], d));
            nm[1] = fmaxf(nm[1], __shfl_xor_sync(0xffffffffu, nm[1], d));
        }
        float alpha0 = __expf(mrow[0] - nm[0]);
        float alpha1 = __expf(mrow[1] - nm[1]);
        mrow[0] = nm[0]; mrow[1] = nm[1];
        float rs0 = 0.f, rs1 = 0.f;
        uint32_t ph[8][2];      // P fragments: [j] = {half2(row g), half2(row g+8)}
#pragma unroll
        for (int j = 0; j < 8; j++) {
            s[j][0] = __expf(s[j][0] - nm[0]);
            s[j][1] = __expf(s[j][1] - nm[0]);
            s[j][2] = __expf(s[j][2] - nm[1]);
            s[j][3] = __expf(s[j][3] - nm[1]);
            rs0 += s[j][0] + s[j][1];
            rs1 += s[j][2] + s[j][3];
            ph[j][0] = fp2h2(s[j][0], s[j][1]);
            ph[j][1] = fp2h2(s[j][2], s[j][3]);
        }
#pragma unroll
        for (int d = 1; d < 4; d <<= 1) {
            rs0 += __shfl_xor_sync(0xffffffffu, rs0, d);
            rs1 += __shfl_xor_sync(0xffffffffu, rs1, d);
        }
        lrow[0] = lrow[0] * alpha0 + rs0;
        lrow[1] = lrow[1] * alpha1 + rs1;
#pragma unroll
        for (int n = 0; n < 16; n++) {
            o[n][0] *= alpha0; o[n][1] *= alpha0;
            o[n][2] *= alpha1; o[n][3] *= alpha1;
        }

        // O += P @ V  (k = 64 -> 4 k16 steps; P fragments register-resident)
#pragma unroll
        for (int ks = 0; ks < 4; ks++) {
            uint32_t af[4] = { ph[2 * ks][0], ph[2 * ks][1], ph[2 * ks + 1][0], ph[2 * ks + 1][1] };
            const int cc = ks * 16 + 2 * t;
#pragma unroll
            for (int n = 0; n < 16; n++) {
                const int d = n * 8 + g;
                uint32_t bf[2];
                bf[0] = *reinterpret_cast<const uint32_t*>(&Vs[d * VSH + cc]);
                bf[1] = *reinterpret_cast<const uint32_t*>(&Vs[d * VSH + cc + 8]);
                mma16h(o[n], af, bf);
            }
        }

        __syncthreads();
        if (kt + 1 < nkt) issueKV(kt + 1);
        CP_COMMIT();
    }

    // normalize + write g_attn as packed fp16 fragments for the fp16 O-proj GEMM.
    float inv0 = 1.f / lrow[0], inv1 = 1.f / lrow[1];
    const int mtile = b * 8 + qt;
    uint32_t* base_mt = g_attn + (size_t)mtile * KC * 4096;
#pragma unroll
    for (int n = 0; n < 16; n++) {
        int kchunk = h * 2 + (n >> 3);
        int kstep = (((n & 7) * 4) + t) >> 3;
        uint32_t* e = base_mt + (size_t)kchunk * 4096 + ((warp * 4 + kstep) * 32 + lane) * 4;
        int rb = (n & 1) * 2;
        e[rb]     = fp2h2(o[n][0] * inv0, o[n][1] * inv0);
        e[rb + 1] = fp2h2(o[n][2] * inv1, o[n][3] * inv1);
    }
}

// ---------------- launch ----------------
extern "C" void kernel_launch(void* const* d_in, const int* in_sizes, int n_in,
                              void* d_out, int out_size)
{
    const float* hs   = (const float*)d_in[0];
    const float* cosb = (const float*)d_in[1];
    const float* sinb = (const float*)d_in[2];
    // d_in[3] = attention_mask (pure causal; applied analytically in-kernel)
    const float* Wq = (const float*)d_in[4];
    const float* Wk = (const float*)d_in[5];
    const float* Wv = (const float*)d_in[6];
    const float* Wo = (const float*)d_in[7];
    float* out = (float*)d_out;

    uint32_t *hsp, *wqkvp, *wop, *ap;
    __half *qkvh;
    cudaGetSymbolAddress((void**)&hsp,   g_hsp);
    cudaGetSymbolAddress((void**)&wqkvp, g_wqkv);
    cudaGetSymbolAddress((void**)&wop,   g_wo);
    cudaGetSymbolAddress((void**)&qkvh,  g_qkvh);
    cudaGetSymbolAddress((void**)&ap,    g_attn);

    cudaFuncSetAttribute(gemm_h, cudaFuncAttributeMaxDynamicSharedMemorySize, GEMM_SMEM);
    cudaFuncSetAttribute(flash_kernel, cudaFuncAttributeMaxDynamicSharedMemorySize, FLASH_SMEM);

    const int M = BATCH * SEQ;

    // prep: pack activations + weights into fp16 fragment order
    pack_a_h<<<dim3(KC, M / 128), 256>>>(hs, hsp, KDIM);
    pack_w_h<<<dim3(KC, (NH * HD) / 128), 256>>>(Wq, wqkvp, NH * HD);
    pack_w_h<<<dim3(KC, (NKV * HD) / 128), 256>>>(Wk, wqkvp + (size_t)32 * KC * 4096, NKV * HD);
    pack_w_h<<<dim3(KC, (NKV * HD) / 128), 256>>>(Wv, wqkvp + (size_t)40 * KC * 4096, NKV * HD);
    pack_w_h<<<dim3(KC, HID / 128), 256>>>(Wo, wop, HID);

    // fused QKV projection -> fp16 g_qkvh
    gemm_h<<<dim3(QKV_N / 256, M / 128), 256, GEMM_SMEM>>>(hsp, wqkvp, qkvh, QKV_N, 1);

    // RoPE on q+k heads (in place, fp16)
    int tot = BATCH * SEQ * (NH + NKV) * 64;
    rope_kernel<<<(tot + 255) / 256, 256>>>(cosb, sinb);

    // V^T for flash P@V fragment layout
    v_transpose<<<dim3(SEQ / 64, BATCH * NKV * 2), 256>>>();

    flash_kernel<<<dim3(SEQ / FBQ, NH, BATCH), 256, FLASH_SMEM>>>();

    // output projection: out = attn(packed fp16) @ Wo(packed fp16), fp32 output
    gemm_h<<<dim3(HID / 256, M / 128), 256, GEMM_SMEM>>>(ap, wop, out, HID, 0);
}

// round 9
// speedup vs baseline: 2.8933x; 1.0339x over previous
#include <cuda_runtime.h>
#include <cuda_fp16.h>
#include <cstdint>

#define BATCH 2
#define SEQ   1024
#define HID   4096
#define NH    32
#define NKV   8
#define HD    128
#define NREP  4
#define QKV_N (NH * HD + 2 * NKV * HD)   // 6144
#define KDIM  4096
#define KC    (KDIM / 64)                // 64 k-chunks of 64

// ---------------- scratch (device globals; no allocation allowed) ----------------
__device__ uint32_t g_hsp [16 * KC * 4096];        // packed fp16 A [M/128][KC][4096 u32]
__device__ uint32_t g_wqkv[48 * KC * 4096];        // packed fp16 B [48 ntiles][KC][4096]
__device__ uint32_t g_wo  [32 * KC * 4096];        // packed fp16 B for O-proj
__device__ __half   g_qkvh[BATCH * SEQ * QKV_N];   // fp16 row-major: q|k|v
__device__ __half   g_vt  [BATCH * NKV * HD * SEQ];// V^T: [b][kh][d][s] fp16
__device__ uint32_t g_attn[16 * KC * 4096];        // packed fp16 A for O-proj

// ---------------- helpers ----------------
__device__ __forceinline__ uint32_t fp2h2(float lo, float hi) {
    __half2 h = __floats2half2_rn(lo, hi);
    return *reinterpret_cast<uint32_t*>(&h);
}
__device__ __forceinline__ uint32_t smem_u32(const void* p) {
    uint32_t a;
    asm("{ .reg .u64 t; cvta.to.shared.u64 t, %1; cvt.u32.u64 %0, t; }" : "=r"(a) : "l"(p));
    return a;
}
__device__ __forceinline__ void cp16(uint32_t dst, const void* src) {
    asm volatile("cp.async.cg.shared.global [%0], [%1], 16;" :: "r"(dst), "l"(src));
}
#define CP_COMMIT() asm volatile("cp.async.commit_group;" ::: "memory")
#define CP_WAIT(n)  asm volatile("cp.async.wait_group %0;" :: "n"(n) : "memory")

// fp16 mma m16n8k16, fp32 accum
__device__ __forceinline__ void mma16h(float* d, const uint32_t* a, const uint32_t* b) {
    asm volatile(
        "mma.sync.aligned.m16n8k16.row.col.f32.f16.f16.f32 "
        "{%0,%1,%2,%3}, {%4,%5,%6,%7}, {%8,%9}, {%0,%1,%2,%3};\n"
        : "+f"(d[0]), "+f"(d[1]), "+f"(d[2]), "+f"(d[3])
        : "r"(a[0]), "r"(a[1]), "r"(a[2]), "r"(a[3]), "r"(b[0]), "r"(b[1]));
}

// ---------------- prep: pack A (activations) into fp16 fragment order ------------
__global__ __launch_bounds__(256)
void pack_a_h(const float* __restrict__ src, uint32_t* __restrict__ dst, int K)
{
    __shared__ float sm[128][68];
    const int tid = threadIdx.x;
    const int kc = blockIdx.x, mt = blockIdx.y;
    const float* S = src + (size_t)(mt * 128) * K + kc * 64;
#pragma unroll
    for (int i = 0; i < 8; i++) {
        int idx = i * 256 + tid;
        int r = idx >> 4, c4 = (idx & 15) << 2;
        float4 v = *reinterpret_cast<const float4*>(S + (size_t)r * K + c4);
        *reinterpret_cast<float4*>(&sm[r][c4]) = v;
    }
    __syncthreads();
    uint32_t* D = dst + ((size_t)(mt * KC) + kc) * 4096;
#pragma unroll
    for (int i = 0; i < 4; i++) {
        int p = i * 256 + tid;
        int mg = p >> 7, ks = (p >> 5) & 3, ln = p & 31;
        int g = ln >> 2, t = ln & 3;
        int r = mg * 16 + g, k0 = ks * 16 + 2 * t;
        uint4 v;
        v.x = fp2h2(sm[r][k0],         sm[r][k0 + 1]);
        v.y = fp2h2(sm[r + 8][k0],     sm[r + 8][k0 + 1]);
        v.z = fp2h2(sm[r][k0 + 8],     sm[r][k0 + 9]);
        v.w = fp2h2(sm[r + 8][k0 + 8], sm[r + 8][k0 + 9]);
        *reinterpret_cast<uint4*>(D + p * 4) = v;
    }
}

// ---------------- prep: pack ALL weights into fp16 fragment order (one launch) ---
// grid.y = 80 ntile slots: [0,32)=Wq, [32,40)=Wk, [40,48)=Wv -> g_wqkv; [48,80)=Wo -> g_wo
__global__ __launch_bounds__(256)
void pack_w_all(const float* __restrict__ Wq, const float* __restrict__ Wk,
                const float* __restrict__ Wv, const float* __restrict__ Wo)
{
    __shared__ float sm[64][132];
    const int tid = threadIdx.x;
    const int kc = blockIdx.x, yy = blockIdx.y;
    const float* W; int N; uint32_t* D0; int ntl, ntg;
    if (yy < 32)       { W = Wq; N = NH * HD;  D0 = g_wqkv; ntl = yy;      ntg = yy; }
    else if (yy < 40)  { W = Wk; N = NKV * HD; D0 = g_wqkv; ntl = yy - 32; ntg = yy; }
    else if (yy < 48)  { W = Wv; N = NKV * HD; D0 = g_wqkv; ntl = yy - 40; ntg = yy; }
    else               { W = Wo; N = HID;      D0 = g_wo;   ntl = yy - 48; ntg = yy - 48; }

    const float* S = W + (size_t)(kc * 64) * N + ntl * 128;
#pragma unroll
    for (int i = 0; i < 8; i++) {
        int idx = i * 256 + tid;
        int r = idx >> 5, c4 = (idx & 31) << 2;
        float4 v = *reinterpret_cast<const float4*>(S + (size_t)r * N + c4);
        *reinterpret_cast<float4*>(&sm[r][c4]) = v;
    }
    __syncthreads();
    uint32_t* D = D0 + ((size_t)(ntg * KC) + kc) * 4096;
#pragma unroll
    for (int i = 0; i < 8; i++) {
        int p = i * 256 + tid;
        int ng = p >> 7, ks = (p >> 5) & 3, ln = p & 31;
        int g = ln >> 2, t = ln & 3;
        int n = ng * 8 + g, k0 = ks * 16 + 2 * t;
        uint2 v;
        v.x = fp2h2(sm[k0][n],     sm[k0 + 1][n]);
        v.y = fp2h2(sm[k0 + 8][n], sm[k0 + 9][n]);
        *reinterpret_cast<uint2*>(D + p * 2) = v;
    }
}

// ---------------- fp16 GEMM: block 128x256, warp 64x64, 4-stage cp.async ---------
#define STG_U 12288
#define NSTAGE 4
#define GEMM_SMEM (NSTAGE * STG_U * 4)      // 196608 B

__global__ __launch_bounds__(256, 1)
void gemm_h(const uint32_t* __restrict__ Ap, const uint32_t* __restrict__ Bp,
            void* __restrict__ Cv, int ldc, int half_out)
{
    extern __shared__ uint32_t sm[];
    const int tid  = threadIdx.x;
    const int lane = tid & 31, warp = tid >> 5;
    const int wm = warp >> 2, wn = warp & 3;
    const int g = lane >> 2, t = lane & 3;

    float acc[4][8][4];
#pragma unroll
    for (int i = 0; i < 4; i++)
#pragma unroll
        for (int j = 0; j < 8; j++)
#pragma unroll
            for (int r = 0; r < 4; r++) acc[i][j][r] = 0.f;

    auto loadChunk = [&](int st, int kt) {
        uint32_t* As = sm + st * STG_U;
        uint32_t* Bs = As + 4096;
        const uint32_t* Ag = Ap + ((size_t)(blockIdx.y * KC) + kt) * 4096;
#pragma unroll
        for (int i = 0; i < 4; i++) {
            int off = (i * 256 + tid) * 4;
            cp16(smem_u32(As + off), Ag + off);
        }
        const uint32_t* Bg0 = Bp + ((size_t)((2 * blockIdx.x) * KC) + kt) * 4096;
        const uint32_t* Bg1 = Bp + ((size_t)((2 * blockIdx.x + 1) * KC) + kt) * 4096;
#pragma unroll
        for (int i = 0; i < 4; i++) {
            int off = (i * 256 + tid) * 4;
            cp16(smem_u32(Bs + off), Bg0 + off);
        }
#pragma unroll
        for (int i = 0; i < 4; i++) {
            int off = (i * 256 + tid) * 4;
            cp16(smem_u32(Bs + 4096 + off), Bg1 + off);
        }
    };

    loadChunk(0, 0); CP_COMMIT();
    loadChunk(1, 1); CP_COMMIT();
    loadChunk(2, 2); CP_COMMIT();

    for (int c = 0; c < KC; c++) {
        CP_WAIT(2);
        __syncthreads();   // stage c ready; buffer (c+3)%4 == (c-1)%4 drained
        if (c + 3 < KC) loadChunk((c + 3) % NSTAGE, c + 3);
        CP_COMMIT();

        const uint32_t* As = sm + (c % NSTAGE) * STG_U;
        const uint32_t* Bs = As + 4096 + (wn >> 1) * 4096;
        const int nsub = (wn & 1) * 8;
#pragma unroll
        for (int ks = 0; ks < 4; ks++) {
            uint32_t af[4][4];
#pragma unroll
            for (int mi = 0; mi < 4; mi++) {
                const uint4 v = *reinterpret_cast<const uint4*>(
                    As + ((wm * 4 + mi) * 4 + ks) * 128 + lane * 4);
                af[mi][0] = v.x; af[mi][1] = v.y; af[mi][2] = v.z; af[mi][3] = v.w;
            }
            uint32_t bf[8][2];
#pragma unroll
            for (int ni = 0; ni < 8; ni++) {
                const uint2 v = *reinterpret_cast<const uint2*>(
                    Bs + ((nsub + ni) * 4 + ks) * 64 + lane * 2);
                bf[ni][0] = v.x; bf[ni][1] = v.y;
            }
#pragma unroll
            for (int mi = 0; mi < 4; mi++)
#pragma unroll
                for (int ni = 0; ni < 8; ni++)
                    mma16h(acc[mi][ni], af[mi], bf[ni]);
        }
    }

    const int m0 = blockIdx.y * 128, n0 = blockIdx.x * 256;
    if (half_out) {
        __half* C = (__half*)Cv;
#pragma unroll
        for (int mi = 0; mi < 4; mi++) {
            int row = m0 + wm * 64 + mi * 16 + g;
#pragma unroll
            for (int ni = 0; ni < 8; ni++) {
                int col = n0 + wn * 64 + ni * 8 + t * 2;
                *reinterpret_cast<uint32_t*>(&C[(size_t)row * ldc + col]) =
                    fp2h2(acc[mi][ni][0], acc[mi][ni][1]);
                *reinterpret_cast<uint32_t*>(&C[(size_t)(row + 8) * ldc + col]) =
                    fp2h2(acc[mi][ni][2], acc[mi][ni][3]);
            }
        }
    } else {
        float* C = (float*)Cv;
#pragma unroll
        for (int mi = 0; mi < 4; mi++) {
            int row = m0 + wm * 64 + mi * 16 + g;
#pragma unroll
            for (int ni = 0; ni < 8; ni++) {
                int col = n0 + wn * 64 + ni * 8 + t * 2;
                *reinterpret_cast<float2*>(&C[(size_t)row * ldc + col]) =
                    make_float2(acc[mi][ni][0], acc[mi][ni][1]);
                *reinterpret_cast<float2*>(&C[(size_t)(row + 8) * ldc + col]) =
                    make_float2(acc[mi][ni][2], acc[mi][ni][3]);
            }
        }
    }
}

// ---------------- RoPE (fused q+k; q heads also folded by 1/sqrt(d)) -------------
__global__ void rope_kernel(const float* __restrict__ cosb, const float* __restrict__ sinb)
{
    int i = blockIdx.x * blockDim.x + threadIdx.x;
    const int total = BATCH * SEQ * (NH + NKV) * 64;
    if (i >= total) return;
    int dh = i & 63;
    int h  = (i >> 6) % (NH + NKV);
    int bs = (i >> 6) / (NH + NKV);
    __half* p = g_qkvh + (size_t)bs * QKV_N + h * HD + dh;
    float x1 = __half2float(p[0]), x2 = __half2float(p[64]);
    const float* cb = cosb + (size_t)bs * HD;
    const float* sb = sinb + (size_t)bs * HD;
    const float sc = (h < NH) ? 0.08838834764831845f : 1.0f;   // fold 1/sqrt(128) into q
    p[0]  = __float2half_rn((x1 * cb[dh]      - x2 * sb[dh])      * sc);
    p[64] = __float2half_rn((x2 * cb[dh + 64] + x1 * sb[dh + 64]) * sc);
}

// ---------------- V transpose: g_qkvh v-region [s][d] -> g_vt [b][kh][d][s] ------
__global__ __launch_bounds__(256)
void v_transpose()
{
    __shared__ __half ts[64][72];
    const int tid = threadIdx.x;
    const int st = blockIdx.x;
    const int yy = blockIdx.y;
    const int bkh = yy >> 1, dt = yy & 1;
    const int b = bkh / NKV;
    const __half* src = g_qkvh + ((size_t)(b * SEQ + st * 64)) * QKV_N
                      + NH * HD + NKV * HD + (bkh % NKV) * HD + dt * 64;
#pragma unroll
    for (int i = 0; i < 16; i++) {
        int e = i * 256 + tid;
        int si = e >> 6, di = e & 63;
        ts[si][di] = src[(size_t)si * QKV_N + di];
    }
    __syncthreads();
    __half* dst = g_vt + ((size_t)(bkh * HD + dt * 64)) * SEQ + st * 64;
#pragma unroll
    for (int i = 0; i < 16; i++) {
        int e = i * 256 + tid;
        int di = e >> 6, si = e & 63;
        dst[(size_t)di * SEQ + si] = ts[si][di];
    }
}

// ---------------- flash attention (fp16 mma, causal, GQA, online softmax) --------
#define FBQ 128
#define FBK 64
#define QSH 136
#define VSH 72
#define FLASH_SMEM ((128 * QSH + 64 * 128 + 128 * VSH) * 2)   // 69632 B

__global__ __launch_bounds__(256)
void flash_kernel()
{
    extern __shared__ __half smh[];
    __half* Qs = smh;                   // [128][QSH]
    __half* Ks = Qs + 128 * QSH;        // [64][128], chunk-swizzled
    __half* Vs = Ks + 64 * 128;         // [128][VSH]  (V^T: d rows, k inner)

    const int tid  = threadIdx.x;
    const int lane = tid & 31, warp = tid >> 5;
    const int g = lane >> 2, t = lane & 3;
    const int qt = blockIdx.x, h = blockIdx.y, b = blockIdx.z;
    const int q0 = qt * FBQ;
    const int kh = h / NREP;
    const int r0 = warp * 16;

    const __half* Qg  = g_qkvh + ((size_t)(b * SEQ + q0)) * QKV_N + h * HD;
    const __half* Kb  = g_qkvh + (size_t)b * SEQ * QKV_N + NH * HD + kh * HD;
    const __half* Vtb = g_vt + ((size_t)(b * NKV + kh)) * HD * SEQ;

    auto issueKV = [&](int kt) {
        const __half* Kg = Kb + (size_t)(kt * FBK) * QKV_N;
#pragma unroll
        for (int i = 0; i < 4; i++) {
            int l = i * 256 + tid;
            int r = l >> 4, cs = l & 15;
            cp16(smem_u32(Ks + r * 128 + ((cs ^ (r & 7)) << 3)), Kg + (size_t)r * QKV_N + cs * 8);
        }
        const __half* Vg = Vtb + kt * FBK;
#pragma unroll
        for (int i = 0; i < 4; i++) {
            int l = i * 256 + tid;
            int r = l >> 3, c = (l & 7) << 3;
            cp16(smem_u32(Vs + r * VSH + c), Vg + (size_t)r * SEQ + c);
        }
    };

#pragma unroll
    for (int i = 0; i < 8; i++) {
        int l = i * 256 + tid;
        int r = l >> 4, c = (l & 15) << 3;
        cp16(smem_u32(Qs + r * QSH + c), Qg + (size_t)r * QKV_N + c);
    }
    issueKV(0);
    CP_COMMIT();

    float o[16][4];
#pragma unroll
    for (int n = 0; n < 16; n++)
#pragma unroll
        for (int r = 0; r < 4; r++) o[n][r] = 0.f;
    float mrow[2] = {-1e30f, -1e30f};
    float lrow[2] = {0.f, 0.f};

    const int nkt = qt * 2 + 2;
    for (int kt = 0; kt < nkt; kt++) {
        const int k0 = kt * FBK;
        CP_WAIT(0);
        __syncthreads();

        // S = Q @ K^T  (Q pre-scaled by 1/sqrt(d) in rope)
        float s[8][4];
#pragma unroll
        for (int j = 0; j < 8; j++)
#pragma unroll
            for (int r = 0; r < 4; r++) s[j][r] = 0.f;
#pragma unroll
        for (int ks = 0; ks < 8; ks++) {
            uint32_t af[4];
            const int rr = r0 + g, cc = ks * 16 + 2 * t;
            af[0] = *reinterpret_cast<const uint32_t*>(&Qs[rr * QSH + cc]);
            af[1] = *reinterpret_cast<const uint32_t*>(&Qs[(rr + 8) * QSH + cc]);
            af[2] = *reinterpret_cast<const uint32_t*>(&Qs[rr * QSH + cc + 8]);
            af[3] = *reinterpret_cast<const uint32_t*>(&Qs[(rr + 8) * QSH + cc + 8]);
#pragma unroll
            for (int j = 0; j < 8; j++) {
                const int kr = j * 8 + g;
                const int base = kr * 128 + 2 * t;
                uint32_t bf[2];
                bf[0] = *reinterpret_cast<const uint32_t*>(&Ks[base + (((2 * ks)     ^ g) << 3)]);
                bf[1] = *reinterpret_cast<const uint32_t*>(&Ks[base + (((2 * ks + 1) ^ g) << 3)]);
                mma16h(s[j], af, bf);
            }
        }

        // online softmax; causal mask only on the (<=2) diagonal tiles
        const int row_lo = q0 + r0 + g;
        float nm[2] = {mrow[0], mrow[1]};
        if (kt >= 2 * qt) {   // diagonal tile: apply mask
#pragma unroll
            for (int j = 0; j < 8; j++) {
                int col = k0 + j * 8 + 2 * t;
                s[j][0] = (col     <= row_lo)     ? s[j][0] : -1e30f;
                s[j][1] = (col + 1 <= row_lo)     ? s[j][1] : -1e30f;
                s[j][2] = (col     <= row_lo + 8) ? s[j][2] : -1e30f;
                s[j][3] = (col + 1 <= row_lo + 8) ? s[j][3] : -1e30f;
            }
        }
#pragma unroll
        for (int j = 0; j < 8; j++) {
            nm[0] = fmaxf(nm[0], fmaxf(s[j][0], s[j][1]));
            nm[1] = fmaxf(nm[1], fmaxf(s[j][2], s[j][3]));
        }
#pragma unroll
        for (int d = 1; d < 4; d <<= 1) {
            nm[0] = fmaxf(nm[0], __shfl_xor_sync(0xffffffffu, nm[0], d));
            nm[1] = fmaxf(nm[1], __shfl_xor_sync(0xffffffffu, nm[1], d));
        }
        float alpha0 = __expf(mrow[0] - nm[0]);
        float alpha1 = __expf(mrow[1] - nm[1]);
        mrow[0] = nm[0]; mrow[1] = nm[1];
        float rs0 = 0.f, rs1 = 0.f;
        uint32_t ph[8][2];
#pragma unroll
        for (int j = 0; j < 8; j++) {
            s[j][0] = __expf(s[j][0] - nm[0]);
            s[j][1] = __expf(s[j][1] - nm[0]);
            s[j][2] = __expf(s[j][2] - nm[1]);
            s[j][3] = __expf(s[j][3] - nm[1]);
            rs0 += s[j][0] + s[j][1];
            rs1 += s[j][2] + s[j][3];
            ph[j][0] = fp2h2(s[j][0], s[j][1]);
            ph[j][1] = fp2h2(s[j][2], s[j][3]);
        }
#pragma unroll
        for (int d = 1; d < 4; d <<= 1) {
            rs0 += __shfl_xor_sync(0xffffffffu, rs0, d);
            rs1 += __shfl_xor_sync(0xffffffffu, rs1, d);
        }
        lrow[0] = lrow[0] * alpha0 + rs0;
        lrow[1] = lrow[1] * alpha1 + rs1;
#pragma unroll
        for (int n = 0; n < 16; n++) {
            o[n][0] *= alpha0; o[n][1] *= alpha0;
            o[n][2] *= alpha1; o[n][3] *= alpha1;
        }

        // O += P @ V  (P fragments register-resident)
#pragma unroll
        for (int ks = 0; ks < 4; ks++) {
            uint32_t af[4] = { ph[2 * ks][0], ph[2 * ks][1], ph[2 * ks + 1][0], ph[2 * ks + 1][1] };
            const int cc = ks * 16 + 2 * t;
#pragma unroll
            for (int n = 0; n < 16; n++) {
                const int d = n * 8 + g;
                uint32_t bf[2];
                bf[0] = *reinterpret_cast<const uint32_t*>(&Vs[d * VSH + cc]);
                bf[1] = *reinterpret_cast<const uint32_t*>(&Vs[d * VSH + cc + 8]);
                mma16h(o[n], af, bf);
            }
        }

        __syncthreads();
        if (kt + 1 < nkt) issueKV(kt + 1);
        CP_COMMIT();
    }

    // normalize + write g_attn as packed fp16 fragments for the fp16 O-proj GEMM
    float inv0 = 1.f / lrow[0], inv1 = 1.f / lrow[1];
    const int mtile = b * 8 + qt;
    uint32_t* base_mt = g_attn + (size_t)mtile * KC * 4096;
#pragma unroll
    for (int n = 0; n < 16; n++) {
        int kchunk = h * 2 + (n >> 3);
        int kstep = (((n & 7) * 4) + t) >> 3;
        uint32_t* e = base_mt + (size_t)kchunk * 4096 + ((warp * 4 + kstep) * 32 + lane) * 4;
        int rb = (n & 1) * 2;
        e[rb]     = fp2h2(o[n][0] * inv0, o[n][1] * inv0);
        e[rb + 1] = fp2h2(o[n][2] * inv1, o[n][3] * inv1);
    }
}

// ---------------- launch ----------------
extern "C" void kernel_launch(void* const* d_in, const int* in_sizes, int n_in,
                              void* d_out, int out_size)
{
    const float* hs   = (const float*)d_in[0];
    const float* cosb = (const float*)d_in[1];
    const float* sinb = (const float*)d_in[2];
    // d_in[3] = attention_mask (pure causal; applied analytically in-kernel)
    const float* Wq = (const float*)d_in[4];
    const float* Wk = (const float*)d_in[5];
    const float* Wv = (const float*)d_in[6];
    const float* Wo = (const float*)d_in[7];
    float* out = (float*)d_out;

    uint32_t *hsp, *wqkvp, *wop, *ap;
    __half *qkvh;
    cudaGetSymbolAddress((void**)&hsp,   g_hsp);
    cudaGetSymbolAddress((void**)&wqkvp, g_wqkv);
    cudaGetSymbolAddress((void**)&wop,   g_wo);
    cudaGetSymbolAddress((void**)&qkvh,  g_qkvh);
    cudaGetSymbolAddress((void**)&ap,    g_attn);

    cudaFuncSetAttribute(gemm_h, cudaFuncAttributeMaxDynamicSharedMemorySize, GEMM_SMEM);
    cudaFuncSetAttribute(flash_kernel, cudaFuncAttributeMaxDynamicSharedMemorySize, FLASH_SMEM);

    const int M = BATCH * SEQ;

    // prep: pack activations + all weights (single weight launch)
    pack_a_h<<<dim3(KC, M / 128), 256>>>(hs, hsp, KDIM);
    pack_w_all<<<dim3(KC, 80), 256>>>(Wq, Wk, Wv, Wo);

    // fused QKV projection -> fp16 g_qkvh
    gemm_h<<<dim3(QKV_N / 256, M / 128), 256, GEMM_SMEM>>>(hsp, wqkvp, qkvh, QKV_N, 1);

    // RoPE on q+k heads (in place, fp16; q also scaled by 1/sqrt(d))
    int tot = BATCH * SEQ * (NH + NKV) * 64;
    rope_kernel<<<(tot + 255) / 256, 256>>>(cosb, sinb);

    // V^T for flash P@V fragment layout
    v_transpose<<<dim3(SEQ / 64, BATCH * NKV * 2), 256>>>();

    flash_kernel<<<dim3(SEQ / FBQ, NH, BATCH), 256, FLASH_SMEM>>>();

    // output projection: out = attn(packed fp16) @ Wo(packed fp16), fp32 output
    gemm_h<<<dim3(HID / 256, M / 128), 256, GEMM_SMEM>>>(ap, wop, out, HID, 0);
}

// round 10
// speedup vs baseline: 3.0043x; 1.0384x over previous
#include <cuda_runtime.h>
#include <cuda_fp16.h>
#include <cstdint>

#define BATCH 2
#define SEQ   1024
#define HID   4096
#define NH    32
#define NKV   8
#define HD    128
#define NREP  4
#define QKV_N (NH * HD + 2 * NKV * HD)   // 6144
#define KDIM  4096
#define KC    (KDIM / 64)                // 64 k-chunks of 64

// ---------------- scratch (device globals; no allocation allowed) ----------------
__device__ uint32_t g_hsp [16 * KC * 4096];        // packed fp16 A [M/128][KC][4096 u32]
__device__ uint32_t g_wqkv[48 * KC * 4096];        // packed fp16 B [48 ntiles][KC][4096]
__device__ uint32_t g_wo  [32 * KC * 4096];        // packed fp16 B for O-proj
__device__ __half   g_qkvh[BATCH * SEQ * QKV_N];   // fp16 row-major: q|k|v
__device__ __half   g_vt  [BATCH * NKV * HD * SEQ];// V^T: [b][kh][d][s] fp16
__device__ uint32_t g_attn[16 * KC * 4096];        // packed fp16 A for O-proj

// ---------------- helpers ----------------
__device__ __forceinline__ uint32_t fp2h2(float lo, float hi) {
    __half2 h = __floats2half2_rn(lo, hi);
    return *reinterpret_cast<uint32_t*>(&h);
}
__device__ __forceinline__ uint32_t smem_u32(const void* p) {
    uint32_t a;
    asm("{ .reg .u64 t; cvta.to.shared.u64 t, %1; cvt.u32.u64 %0, t; }" : "=r"(a) : "l"(p));
    return a;
}
__device__ __forceinline__ void cp16(uint32_t dst, const void* src) {
    asm volatile("cp.async.cg.shared.global [%0], [%1], 16;" :: "r"(dst), "l"(src));
}
#define CP_COMMIT() asm volatile("cp.async.commit_group;" ::: "memory")
#define CP_WAIT(n)  asm volatile("cp.async.wait_group %0;" :: "n"(n) : "memory")

// fp16 mma m16n8k16, fp32 accum
__device__ __forceinline__ void mma16h(float* d, const uint32_t* a, const uint32_t* b) {
    asm volatile(
        "mma.sync.aligned.m16n8k16.row.col.f32.f16.f16.f32 "
        "{%0,%1,%2,%3}, {%4,%5,%6,%7}, {%8,%9}, {%0,%1,%2,%3};\n"
        : "+f"(d[0]), "+f"(d[1]), "+f"(d[2]), "+f"(d[3])
        : "r"(a[0]), "r"(a[1]), "r"(a[2]), "r"(a[3]), "r"(b[0]), "r"(b[1]));
}

// ---------------- prep: pack A (hs) + ALL weights, ONE launch --------------------
// grid: (KC, 96). y<16: pack_a tile mt=y. y>=16: pack_w slot yy=y-16 (0..79):
// [0,32)=Wq, [32,40)=Wk, [40,48)=Wv -> g_wqkv; [48,80)=Wo -> g_wo
__global__ __launch_bounds__(256)
void pack_all(const float* __restrict__ hs,
              const float* __restrict__ Wq, const float* __restrict__ Wk,
              const float* __restrict__ Wv, const float* __restrict__ Wo)
{
    __shared__ float smf[8704];                   // max(128*68, 64*132) floats
    const int tid = threadIdx.x;
    const int kc = blockIdx.x, y = blockIdx.y;

    if (y < 16) {
        // ---- pack A (activations) ----
        float (*sm)[68] = reinterpret_cast<float (*)[68]>(smf);
        const int mt = y;
        const float* S = hs + (size_t)(mt * 128) * KDIM + kc * 64;
#pragma unroll
        for (int i = 0; i < 8; i++) {
            int idx = i * 256 + tid;
            int r = idx >> 4, c4 = (idx & 15) << 2;
            float4 v = *reinterpret_cast<const float4*>(S + (size_t)r * KDIM + c4);
            *reinterpret_cast<float4*>(&sm[r][c4]) = v;
        }
        __syncthreads();
        uint32_t* D = g_hsp + ((size_t)(mt * KC) + kc) * 4096;
#pragma unroll
        for (int i = 0; i < 4; i++) {
            int p = i * 256 + tid;
            int mg = p >> 7, ks = (p >> 5) & 3, ln = p & 31;
            int g = ln >> 2, t = ln & 3;
            int r = mg * 16 + g, k0 = ks * 16 + 2 * t;
            uint4 v;
            v.x = fp2h2(sm[r][k0],         sm[r][k0 + 1]);
            v.y = fp2h2(sm[r + 8][k0],     sm[r + 8][k0 + 1]);
            v.z = fp2h2(sm[r][k0 + 8],     sm[r][k0 + 9]);
            v.w = fp2h2(sm[r + 8][k0 + 8], sm[r + 8][k0 + 9]);
            *reinterpret_cast<uint4*>(D + p * 4) = v;
        }
    } else {
        // ---- pack W ----
        float (*sm)[132] = reinterpret_cast<float (*)[132]>(smf);
        const int yy = y - 16;
        const float* W; int N; uint32_t* D0; int ntl, ntg;
        if (yy < 32)      { W = Wq; N = NH * HD;  D0 = g_wqkv; ntl = yy;      ntg = yy; }
        else if (yy < 40) { W = Wk; N = NKV * HD; D0 = g_wqkv; ntl = yy - 32; ntg = yy; }
        else if (yy < 48) { W = Wv; N = NKV * HD; D0 = g_wqkv; ntl = yy - 40; ntg = yy; }
        else              { W = Wo; N = HID;      D0 = g_wo;   ntl = yy - 48; ntg = yy - 48; }

        const float* S = W + (size_t)(kc * 64) * N + ntl * 128;
#pragma unroll
        for (int i = 0; i < 8; i++) {
            int idx = i * 256 + tid;
            int r = idx >> 5, c4 = (idx & 31) << 2;
            float4 v = *reinterpret_cast<const float4*>(S + (size_t)r * N + c4);
            *reinterpret_cast<float4*>(&sm[r][c4]) = v;
        }
        __syncthreads();
        uint32_t* D = D0 + ((size_t)(ntg * KC) + kc) * 4096;
#pragma unroll
        for (int i = 0; i < 8; i++) {
            int p = i * 256 + tid;
            int ng = p >> 7, ks = (p >> 5) & 3, ln = p & 31;
            int g = ln >> 2, t = ln & 3;
            int n = ng * 8 + g, k0 = ks * 16 + 2 * t;
            uint2 v;
            v.x = fp2h2(sm[k0][n],     sm[k0 + 1][n]);
            v.y = fp2h2(sm[k0 + 8][n], sm[k0 + 9][n]);
            *reinterpret_cast<uint2*>(D + p * 2) = v;
        }
    }
}

// ---------------- fp16 GEMM: block 128x256, warp 64x64, 4-stage cp.async ---------
#define STG_U 12288
#define NSTAGE 4
#define GEMM_SMEM (NSTAGE * STG_U * 4)      // 196608 B

__global__ __launch_bounds__(256, 1)
void gemm_h(const uint32_t* __restrict__ Ap, const uint32_t* __restrict__ Bp,
            void* __restrict__ Cv, int ldc, int half_out)
{
    extern __shared__ uint32_t sm[];
    const int tid  = threadIdx.x;
    const int lane = tid & 31, warp = tid >> 5;
    const int wm = warp >> 2, wn = warp & 3;
    const int g = lane >> 2, t = lane & 3;

    float acc[4][8][4];
#pragma unroll
    for (int i = 0; i < 4; i++)
#pragma unroll
        for (int j = 0; j < 8; j++)
#pragma unroll
            for (int r = 0; r < 4; r++) acc[i][j][r] = 0.f;

    auto loadChunk = [&](int st, int kt) {
        uint32_t* As = sm + st * STG_U;
        uint32_t* Bs = As + 4096;
        const uint32_t* Ag = Ap + ((size_t)(blockIdx.y * KC) + kt) * 4096;
#pragma unroll
        for (int i = 0; i < 4; i++) {
            int off = (i * 256 + tid) * 4;
            cp16(smem_u32(As + off), Ag + off);
        }
        const uint32_t* Bg0 = Bp + ((size_t)((2 * blockIdx.x) * KC) + kt) * 4096;
        const uint32_t* Bg1 = Bp + ((size_t)((2 * blockIdx.x + 1) * KC) + kt) * 4096;
#pragma unroll
        for (int i = 0; i < 4; i++) {
            int off = (i * 256 + tid) * 4;
            cp16(smem_u32(Bs + off), Bg0 + off);
        }
#pragma unroll
        for (int i = 0; i < 4; i++) {
            int off = (i * 256 + tid) * 4;
            cp16(smem_u32(Bs + 4096 + off), Bg1 + off);
        }
    };

    loadChunk(0, 0); CP_COMMIT();
    loadChunk(1, 1); CP_COMMIT();
    loadChunk(2, 2); CP_COMMIT();

    for (int c = 0; c < KC; c++) {
        CP_WAIT(2);
        __syncthreads();
        if (c + 3 < KC) loadChunk((c + 3) % NSTAGE, c + 3);
        CP_COMMIT();

        const uint32_t* As = sm + (c % NSTAGE) * STG_U;
        const uint32_t* Bs = As + 4096 + (wn >> 1) * 4096;
        const int nsub = (wn & 1) * 8;
#pragma unroll
        for (int ks = 0; ks < 4; ks++) {
            uint32_t af[4][4];
#pragma unroll
            for (int mi = 0; mi < 4; mi++) {
                const uint4 v = *reinterpret_cast<const uint4*>(
                    As + ((wm * 4 + mi) * 4 + ks) * 128 + lane * 4);
                af[mi][0] = v.x; af[mi][1] = v.y; af[mi][2] = v.z; af[mi][3] = v.w;
            }
            uint32_t bf[8][2];
#pragma unroll
            for (int ni = 0; ni < 8; ni++) {
                const uint2 v = *reinterpret_cast<const uint2*>(
                    Bs + ((nsub + ni) * 4 + ks) * 64 + lane * 2);
                bf[ni][0] = v.x; bf[ni][1] = v.y;
            }
#pragma unroll
            for (int mi = 0; mi < 4; mi++)
#pragma unroll
                for (int ni = 0; ni < 8; ni++)
                    mma16h(acc[mi][ni], af[mi], bf[ni]);
        }
    }

    const int m0 = blockIdx.y * 128, n0 = blockIdx.x * 256;
    if (half_out) {
        __half* C = (__half*)Cv;
#pragma unroll
        for (int mi = 0; mi < 4; mi++) {
            int row = m0 + wm * 64 + mi * 16 + g;
#pragma unroll
            for (int ni = 0; ni < 8; ni++) {
                int col = n0 + wn * 64 + ni * 8 + t * 2;
                *reinterpret_cast<uint32_t*>(&C[(size_t)row * ldc + col]) =
                    fp2h2(acc[mi][ni][0], acc[mi][ni][1]);
                *reinterpret_cast<uint32_t*>(&C[(size_t)(row + 8) * ldc + col]) =
                    fp2h2(acc[mi][ni][2], acc[mi][ni][3]);
            }
        }
    } else {
        float* C = (float*)Cv;
#pragma unroll
        for (int mi = 0; mi < 4; mi++) {
            int row = m0 + wm * 64 + mi * 16 + g;
#pragma unroll
            for (int ni = 0; ni < 8; ni++) {
                int col = n0 + wn * 64 + ni * 8 + t * 2;
                *reinterpret_cast<float2*>(&C[(size_t)row * ldc + col]) =
                    make_float2(acc[mi][ni][0], acc[mi][ni][1]);
                *reinterpret_cast<float2*>(&C[(size_t)(row + 8) * ldc + col]) =
                    make_float2(acc[mi][ni][2], acc[mi][ni][3]);
            }
        }
    }
}

// ---------------- fused RoPE (vectorized) + V transpose --------------------------
#define ROPE_BLOCKS (BATCH * SEQ * (NH + NKV) * 32 / 256)   // 10240
__global__ __launch_bounds__(256)
void rope_vt(const float* __restrict__ cosb, const float* __restrict__ sinb)
{
    __shared__ __half ts[64][72];
    if (blockIdx.x < ROPE_BLOCKS) {
        int i = blockIdx.x * 256 + threadIdx.x;
        int dh2 = i & 31;
        int h  = (i >> 5) % (NH + NKV);
        int bs = (i >> 5) / (NH + NKV);
        uint32_t* p = reinterpret_cast<uint32_t*>(g_qkvh + (size_t)bs * QKV_N + h * HD) + dh2;
        float2 x1 = __half22float2(*reinterpret_cast<__half2*>(&p[0]));
        float2 x2 = __half22float2(*reinterpret_cast<__half2*>(&p[32]));
        const float2* cb = reinterpret_cast<const float2*>(cosb + (size_t)bs * HD);
        const float2* sb = reinterpret_cast<const float2*>(sinb + (size_t)bs * HD);
        float2 c0 = cb[dh2], c1 = cb[dh2 + 32];
        float2 s0 = sb[dh2], s1 = sb[dh2 + 32];
        const float sc = (h < NH) ? 0.08838834764831845f : 1.0f;   // fold 1/sqrt(d) into q
        p[0]  = fp2h2((x1.x * c0.x - x2.x * s0.x) * sc, (x1.y * c0.y - x2.y * s0.y) * sc);
        p[32] = fp2h2((x2.x * c1.x + x1.x * s1.x) * sc, (x2.y * c1.y + x1.y * s1.y) * sc);
    } else {
        int idx = blockIdx.x - ROPE_BLOCKS;      // 0..511
        const int tid = threadIdx.x;
        const int st = idx & 15, yy = idx >> 4;
        const int bkh = yy >> 1, dt = yy & 1;
        const int b = bkh / NKV;
        const __half* src = g_qkvh + ((size_t)(b * SEQ + st * 64)) * QKV_N
                          + NH * HD + NKV * HD + (bkh % NKV) * HD + dt * 64;
#pragma unroll
        for (int i = 0; i < 16; i++) {
            int e = i * 256 + tid;
            int si = e >> 6, di = e & 63;
            ts[si][di] = src[(size_t)si * QKV_N + di];
        }
        __syncthreads();
        __half* dst = g_vt + ((size_t)(bkh * HD + dt * 64)) * SEQ + st * 64;
#pragma unroll
        for (int i = 0; i < 16; i++) {
            int e = i * 256 + tid;
            int di = e >> 6, si = e & 63;
            dst[(size_t)di * SEQ + si] = ts[si][di];
        }
    }
}

// ---------------- flash attention: FBK=128, fp16 mma, causal, GQA ---------------
#define FBQ 128
#define FBK 128
#define QSH 136
#define VSH 136
#define FLASH_SMEM ((128 * QSH + 128 * 128 + 128 * VSH) * 2)   // 102400 B

__global__ __launch_bounds__(256)
void flash_kernel()
{
    extern __shared__ __half smh[];
    __half* Qs = smh;                   // [128][QSH]
    __half* Ks = Qs + 128 * QSH;        // [128][128], chunk-swizzled
    __half* Vs = Ks + 128 * 128;        // [128][VSH]  (V^T: d rows, s inner)

    const int tid  = threadIdx.x;
    const int lane = tid & 31, warp = tid >> 5;
    const int g = lane >> 2, t = lane & 3;
    const int qt = (int)gridDim.x - 1 - (int)blockIdx.x;   // longest CTAs first
    const int h = blockIdx.y, b = blockIdx.z;
    const int q0 = qt * FBQ;
    const int kh = h / NREP;
    const int r0 = warp * 16;

    const __half* Qg  = g_qkvh + ((size_t)(b * SEQ + q0)) * QKV_N + h * HD;
    const __half* Kb  = g_qkvh + (size_t)b * SEQ * QKV_N + NH * HD + kh * HD;
    const __half* Vtb = g_vt + ((size_t)(b * NKV + kh)) * HD * SEQ;

    auto issueKV = [&](int kt) {
        const __half* Kg = Kb + (size_t)(kt * FBK) * QKV_N;
#pragma unroll
        for (int i = 0; i < 8; i++) {          // K: 128 rows x 16 swizzled chunks
            int l = i * 256 + tid;
            int r = l >> 4, cs = l & 15;
            cp16(smem_u32(Ks + r * 128 + ((cs ^ (r & 7)) << 3)), Kg + (size_t)r * QKV_N + cs * 8);
        }
        const __half* Vg = Vtb + kt * FBK;
#pragma unroll
        for (int i = 0; i < 8; i++) {          // V^T: 128 d-rows x 128 s-cols
            int l = i * 256 + tid;
            int r = l >> 4, c = (l & 15) << 3;
            cp16(smem_u32(Vs + r * VSH + c), Vg + (size_t)r * SEQ + c);
        }
    };

#pragma unroll
    for (int i = 0; i < 8; i++) {              // Q: 128 rows x 128 halves
        int l = i * 256 + tid;
        int r = l >> 4, c = (l & 15) << 3;
        cp16(smem_u32(Qs + r * QSH + c), Qg + (size_t)r * QKV_N + c);
    }
    issueKV(0);
    CP_COMMIT();

    float o[16][4];
#pragma unroll
    for (int n = 0; n < 16; n++)
#pragma unroll
        for (int r = 0; r < 4; r++) o[n][r] = 0.f;
    float mrow[2] = {-1e30f, -1e30f};
    float lrow[2] = {0.f, 0.f};

    const int nkt = qt + 1;
    for (int kt = 0; kt < nkt; kt++) {
        CP_WAIT(0);
        __syncthreads();

        // S = Q @ K^T  (warp 16 x 128, k=128 -> 8 k16 steps; Q pre-scaled)
        float s[16][4];
#pragma unroll
        for (int j = 0; j < 16; j++)
#pragma unroll
            for (int r = 0; r < 4; r++) s[j][r] = 0.f;
#pragma unroll
        for (int ks = 0; ks < 8; ks++) {
            uint32_t af[4];
            const int rr = r0 + g, cc = ks * 16 + 2 * t;
            af[0] = *reinterpret_cast<const uint32_t*>(&Qs[rr * QSH + cc]);
            af[1] = *reinterpret_cast<const uint32_t*>(&Qs[(rr + 8) * QSH + cc]);
            af[2] = *reinterpret_cast<const uint32_t*>(&Qs[rr * QSH + cc + 8]);
            af[3] = *reinterpret_cast<const uint32_t*>(&Qs[(rr + 8) * QSH + cc + 8]);
#pragma unroll
            for (int j = 0; j < 16; j++) {
                const int kr = j * 8 + g;
                const int base = kr * 128 + 2 * t;
                uint32_t bf[2];
                bf[0] = *reinterpret_cast<const uint32_t*>(&Ks[base + (((2 * ks)     ^ g) << 3)]);
                bf[1] = *reinterpret_cast<const uint32_t*>(&Ks[base + (((2 * ks + 1) ^ g) << 3)]);
                mma16h(s[j], af, bf);
            }
        }

        // online softmax; mask only the single diagonal tile
        const int row_lo = q0 + r0 + g;
        float nm[2] = {mrow[0], mrow[1]};
        if (kt == qt) {
            const int k0 = kt * FBK;
#pragma unroll
            for (int j = 0; j < 16; j++) {
                int col = k0 + j * 8 + 2 * t;
                s[j][0] = (col     <= row_lo)     ? s[j][0] : -1e30f;
                s[j][1] = (col + 1 <= row_lo)     ? s[j][1] : -1e30f;
                s[j][2] = (col     <= row_lo + 8) ? s[j][2] : -1e30f;
                s[j][3] = (col + 1 <= row_lo + 8) ? s[j][3] : -1e30f;
            }
        }
#pragma unroll
        for (int j = 0; j < 16; j++) {
            nm[0] = fmaxf(nm[0], fmaxf(s[j][0], s[j][1]));
            nm[1] = fmaxf(nm[1], fmaxf(s[j][2], s[j][3]));
        }
#pragma unroll
        for (int d = 1; d < 4; d <<= 1) {
            nm[0] = fmaxf(nm[0], __shfl_xor_sync(0xffffffffu, nm[0], d));
            nm[1] = fmaxf(nm[1], __shfl_xor_sync(0xffffffffu, nm[1], d));
        }
        float alpha0 = __expf(mrow[0] - nm[0]);
        float alpha1 = __expf(mrow[1] - nm[1]);
        mrow[0] = nm[0]; mrow[1] = nm[1];
        float rs0 = 0.f, rs1 = 0.f;
#pragma unroll
        for (int j = 0; j < 16; j++) {
            s[j][0] = __expf(s[j][0] - nm[0]);
            s[j][1] = __expf(s[j][1] - nm[0]);
            s[j][2] = __expf(s[j][2] - nm[1]);
            s[j][3] = __expf(s[j][3] - nm[1]);
            rs0 += s[j][0] + s[j][1];
            rs1 += s[j][2] + s[j][3];
        }
#pragma unroll
        for (int d = 1; d < 4; d <<= 1) {
            rs0 += __shfl_xor_sync(0xffffffffu, rs0, d);
            rs1 += __shfl_xor_sync(0xffffffffu, rs1, d);
        }
        lrow[0] = lrow[0] * alpha0 + rs0;
        lrow[1] = lrow[1] * alpha1 + rs1;
#pragma unroll
        for (int n = 0; n < 16; n++) {
            o[n][0] *= alpha0; o[n][1] *= alpha0;
            o[n][2] *= alpha1; o[n][3] *= alpha1;
        }

        // O += P @ V  (k=128 -> 8 k16 steps; P converted to fp16 inline)
#pragma unroll
        for (int ks = 0; ks < 8; ks++) {
            uint32_t af[4];
            af[0] = fp2h2(s[2 * ks][0],     s[2 * ks][1]);
            af[1] = fp2h2(s[2 * ks][2],     s[2 * ks][3]);
            af[2] = fp2h2(s[2 * ks + 1][0], s[2 * ks + 1][1]);
            af[3] = fp2h2(s[2 * ks + 1][2], s[2 * ks + 1][3]);
            const int cc = ks * 16 + 2 * t;
#pragma unroll
            for (int n = 0; n < 16; n++) {
                const int d = n * 8 + g;
                uint32_t bf[2];
                bf[0] = *reinterpret_cast<const uint32_t*>(&Vs[d * VSH + cc]);
                bf[1] = *reinterpret_cast<const uint32_t*>(&Vs[d * VSH + cc + 8]);
                mma16h(o[n], af, bf);
            }
        }

        __syncthreads();
        if (kt + 1 < nkt) issueKV(kt + 1);
        CP_COMMIT();
    }

    // normalize + write g_attn as packed fp16 fragments for the fp16 O-proj GEMM
    float inv0 = 1.f / lrow[0], inv1 = 1.f / lrow[1];
    const int mtile = b * 8 + qt;
    uint32_t* base_mt = g_attn + (size_t)mtile * KC * 4096;
#pragma unroll
    for (int n = 0; n < 16; n++) {
        int kchunk = h * 2 + (n >> 3);
        int kstep = (((n & 7) * 4) + t) >> 3;
        uint32_t* e = base_mt + (size_t)kchunk * 4096 + ((warp * 4 + kstep) * 32 + lane) * 4;
        int rb = (n & 1) * 2;
        e[rb]     = fp2h2(o[n][0] * inv0, o[n][1] * inv0);
        e[rb + 1] = fp2h2(o[n][2] * inv1, o[n][3] * inv1);
    }
}

// ---------------- launch ----------------
extern "C" void kernel_launch(void* const* d_in, const int* in_sizes, int n_in,
                              void* d_out, int out_size)
{
    const float* hs   = (const float*)d_in[0];
    const float* cosb = (const float*)d_in[1];
    const float* sinb = (const float*)d_in[2];
    // d_in[3] = attention_mask (pure causal; applied analytically in-kernel)
    const float* Wq = (const float*)d_in[4];
    const float* Wk = (const float*)d_in[5];
    const float* Wv = (const float*)d_in[6];
    const float* Wo = (const float*)d_in[7];
    float* out = (float*)d_out;

    uint32_t *hsp, *wqkvp, *wop, *ap;
    __half *qkvh;
    cudaGetSymbolAddress((void**)&hsp,   g_hsp);
    cudaGetSymbolAddress((void**)&wqkvp, g_wqkv);
    cudaGetSymbolAddress((void**)&wop,   g_wo);
    cudaGetSymbolAddress((void**)&qkvh,  g_qkvh);
    cudaGetSymbolAddress((void**)&ap,    g_attn);

    cudaFuncSetAttribute(gemm_h, cudaFuncAttributeMaxDynamicSharedMemorySize, GEMM_SMEM);
    cudaFuncSetAttribute(flash_kernel, cudaFuncAttributeMaxDynamicSharedMemorySize, FLASH_SMEM);

    const int M = BATCH * SEQ;

    // prep: pack activations + all weights in ONE launch
    pack_all<<<dim3(KC, 96), 256>>>(hs, Wq, Wk, Wv, Wo);

    // fused QKV projection -> fp16 g_qkvh
    gemm_h<<<dim3(QKV_N / 256, M / 128), 256, GEMM_SMEM>>>(hsp, wqkvp, qkvh, QKV_N, 1);

    // fused vectorized RoPE (q scaled by 1/sqrt(d)) + V^T
    rope_vt<<<ROPE_BLOCKS + 512, 256>>>(cosb, sinb);

    flash_kernel<<<dim3(SEQ / FBQ, NH, BATCH), 256, FLASH_SMEM>>>();

    // output projection: out = attn(packed fp16) @ Wo(packed fp16), fp32 output
    gemm_h<<<dim3(HID / 256, M / 128), 256, GEMM_SMEM>>>(ap, wop, out, HID, 0);
}

// round 11
// speedup vs baseline: 3.0197x; 1.0051x over previous
#include <cuda_runtime.h>
#include <cuda_fp16.h>
#include <cstdint>

#define BATCH 2
#define SEQ   1024
#define HID   4096
#define NH    32
#define NKV   8
#define HD    128
#define NREP  4
#define QKV_N (NH * HD + 2 * NKV * HD)   // 6144
#define KDIM  4096
#define KC    (KDIM / 64)                // 64 k-chunks of 64

// ---------------- scratch (device globals; no allocation allowed) ----------------
__device__ __half g_hsh  [BATCH * SEQ * HID];        // hs fp16 [2048][4096]
__device__ __half g_wh   [KDIM * QKV_N];             // [Wq|Wk|Wv] fp16 [4096][6144]
__device__ __half g_woh  [KDIM * HID];               // Wo fp16 [4096][4096]
__device__ __half g_qkvh [BATCH * SEQ * QKV_N];      // fp16 row-major: q|k|v
__device__ __half g_vt   [BATCH * NKV * HD * SEQ];   // V^T: [b][kh][d][s]
__device__ __half g_attnh[BATCH * SEQ * NH * HD];    // attn fp16 [2048][4096]

// ---------------- helpers ----------------
__device__ __forceinline__ uint32_t fp2h2(float lo, float hi) {
    __half2 h = __floats2half2_rn(lo, hi);
    return *reinterpret_cast<uint32_t*>(&h);
}
__device__ __forceinline__ uint32_t smem_u32(const void* p) {
    uint32_t a;
    asm("{ .reg .u64 t; cvta.to.shared.u64 t, %1; cvt.u32.u64 %0, t; }" : "=r"(a) : "l"(p));
    return a;
}
__device__ __forceinline__ void cp16(uint32_t dst, const void* src) {
    asm volatile("cp.async.cg.shared.global [%0], [%1], 16;" :: "r"(dst), "l"(src));
}
#define CP_COMMIT() asm volatile("cp.async.commit_group;" ::: "memory")
#define CP_WAIT(n)  asm volatile("cp.async.wait_group %0;" :: "n"(n) : "memory")

__device__ __forceinline__ void ldsm4(uint32_t* r, uint32_t a) {
    asm volatile("ldmatrix.sync.aligned.m8n8.x4.shared.b16 {%0,%1,%2,%3}, [%4];"
        : "=r"(r[0]), "=r"(r[1]), "=r"(r[2]), "=r"(r[3]) : "r"(a));
}
__device__ __forceinline__ void ldsm4t(uint32_t* r, uint32_t a) {
    asm volatile("ldmatrix.sync.aligned.m8n8.x4.trans.shared.b16 {%0,%1,%2,%3}, [%4];"
        : "=r"(r[0]), "=r"(r[1]), "=r"(r[2]), "=r"(r[3]) : "r"(a));
}

// fp16 mma m16n8k16, fp32 accum
__device__ __forceinline__ void mma16h(float* d, const uint32_t* a, const uint32_t* b) {
    asm volatile(
        "mma.sync.aligned.m16n8k16.row.col.f32.f16.f16.f32 "
        "{%0,%1,%2,%3}, {%4,%5,%6,%7}, {%8,%9}, {%0,%1,%2,%3};\n"
        : "+f"(d[0]), "+f"(d[1]), "+f"(d[2]), "+f"(d[3])
        : "r"(a[0]), "r"(a[1]), "r"(a[2]), "r"(a[3]), "r"(b[0]), "r"(b[1]));
}

// ---------------- prep: pure streaming fp32 -> fp16 conversion -------------------
#define HS_E (BATCH * SEQ * HID)        // 8388608
#define W_E  (KDIM * QKV_N)             // 25165824
#define WO_E (KDIM * HID)               // 16777216
#define CVT_BLOCKS ((HS_E + W_E + WO_E) / 8 / 256)   // 24576

__global__ __launch_bounds__(256)
void cvt_all(const float* __restrict__ hs,
             const float* __restrict__ Wq, const float* __restrict__ Wk,
             const float* __restrict__ Wv, const float* __restrict__ Wo)
{
    size_t i8 = ((size_t)blockIdx.x * 256 + threadIdx.x) * 8;
    const float* src;
    __half* dst;
    if (i8 < HS_E) {
        src = hs + i8;
        dst = g_hsh + i8;
    } else if (i8 < (size_t)HS_E + W_E) {
        size_t off = i8 - HS_E;
        int k = (int)(off / QKV_N), c = (int)(off % QKV_N);
        if (c < NH * HD)                 src = Wq + (size_t)k * (NH * HD) + c;
        else if (c < NH * HD + NKV * HD) src = Wk + (size_t)k * (NKV * HD) + (c - NH * HD);
        else                             src = Wv + (size_t)k * (NKV * HD) + (c - NH * HD - NKV * HD);
        dst = g_wh + off;
    } else {
        size_t off = i8 - HS_E - W_E;
        src = Wo + off;
        dst = g_woh + off;
    }
    float4 a = *reinterpret_cast<const float4*>(src);
    float4 b = *reinterpret_cast<const float4*>(src + 4);
    uint4 o;
    o.x = fp2h2(a.x, a.y); o.y = fp2h2(a.z, a.w);
    o.z = fp2h2(b.x, b.y); o.w = fp2h2(b.z, b.w);
    *reinterpret_cast<uint4*>(dst) = o;
}

// ---------------- fp16 GEMM via ldmatrix: block 128x256, warp 64x64, 4 stages ----
// A [M][4096] fp16 row-major; B [4096][ldb] fp16 row-major (n0 = col offset).
// smem/stage: A 128 rows x 8 16B-units (16KB, u^=r&7) + B 64 rows x 32 units (32KB, u^=r&7)
#define STG_B 49152
#define NSTAGE 4
#define GEMM_SMEM (NSTAGE * STG_B)      // 196608 B

__global__ __launch_bounds__(256, 1)
void gemm_h(const __half* __restrict__ Ap, const __half* __restrict__ Bp,
            void* __restrict__ Cv, int ldb, int ldc, int half_out)
{
    extern __shared__ char smc[];
    const uint32_t sb = smem_u32(smc);
    const int tid  = threadIdx.x;
    const int lane = tid & 31, warp = tid >> 5;
    const int wm = warp >> 2, wn = warp & 3;   // 2(m) x 4(n), warp tile 64x64
    const int g = lane >> 2, t = lane & 3;
    const int m0 = blockIdx.y * 128, n0 = blockIdx.x * 256;

    float acc[4][8][4];
#pragma unroll
    for (int i = 0; i < 4; i++)
#pragma unroll
        for (int j = 0; j < 8; j++)
#pragma unroll
            for (int r = 0; r < 4; r++) acc[i][j][r] = 0.f;

    auto loadChunk = [&](int st, int kt) {
        uint32_t As = sb + st * STG_B;
        uint32_t Bs = As + 16384;
        const __half* Ag = Ap + (size_t)m0 * KDIM + kt * 64;
#pragma unroll
        for (int i = 0; i < 4; i++) {               // A: 128 rows x 8 units
            int l = i * 256 + tid;
            int r = l >> 3, u = l & 7;
            cp16(As + r * 128 + ((u ^ (r & 7)) << 4), Ag + (size_t)r * KDIM + u * 8);
        }
        const __half* Bg = Bp + (size_t)(kt * 64) * ldb + n0;
#pragma unroll
        for (int i = 0; i < 8; i++) {               // B: 64 rows x 32 units
            int l = i * 256 + tid;
            int r = l >> 5, u = l & 31;
            cp16(Bs + r * 512 + ((u ^ (r & 7)) << 4), Bg + (size_t)r * ldb + u * 8);
        }
    };

    // per-lane ldmatrix address constants
    const int jA  = lane >> 3;                       // which 8x8 mat this lane feeds (A)
    const int rAl = (lane & 7) + (jA & 1) * 8;       // m-offset within warp block
    const int uhA = jA >> 1;                         // k-unit half (0/1)
    const int e7a = rAl & 7;                         // (wm*64 + mi*16 + rAl) & 7 == rAl & 7
    uint32_t aoff[4];
#pragma unroll
    for (int mi = 0; mi < 4; mi++) aoff[mi] = (uint32_t)(wm * 64 + mi * 16 + rAl) * 128;
    const int kbB = (lane & 7) + ((lane >> 3) & 1) * 8;   // k-offset within k16 (B)
    const uint32_t bro = (uint32_t)kbB * 512;
    const int e7b = lane & 7;
    const int nhB = (lane >> 4) & 1;                 // n8 half (B mats 2,3)
    uint32_t ub[4];
#pragma unroll
    for (int nip = 0; nip < 4; nip++)
        ub[nip] = (uint32_t)(((wn * 8 + nip * 2 + nhB) ^ e7b) << 4);

    loadChunk(0, 0); CP_COMMIT();
    loadChunk(1, 1); CP_COMMIT();
    loadChunk(2, 2); CP_COMMIT();

    for (int c = 0; c < KC; c++) {
        CP_WAIT(2);
        __syncthreads();   // stage c ready; buffer (c+3)%4 == (c-1)%4 drained
        if (c + 3 < KC) loadChunk((c + 3) % NSTAGE, c + 3);
        CP_COMMIT();

        const uint32_t As = sb + (c % NSTAGE) * STG_B;
        const uint32_t Bs = As + 16384;
#pragma unroll
        for (int ks = 0; ks < 4; ks++) {
            const uint32_t axor = (uint32_t)(((2 * ks + uhA) ^ e7a) << 4);
            uint32_t af[4][4];
#pragma unroll
            for (int mi = 0; mi < 4; mi++)
                ldsm4(af[mi], As + aoff[mi] + axor);
            uint32_t bf[8][2];
#pragma unroll
            for (int nip = 0; nip < 4; nip++) {
                uint32_t r4[4];
                ldsm4t(r4, Bs + (uint32_t)(ks * 8192) + bro + ub[nip]);
                bf[2 * nip][0]     = r4[0]; bf[2 * nip][1]     = r4[1];
                bf[2 * nip + 1][0] = r4[2]; bf[2 * nip + 1][1] = r4[3];
            }
#pragma unroll
            for (int mi = 0; mi < 4; mi++)
#pragma unroll
                for (int ni = 0; ni < 8; ni++)
                    mma16h(acc[mi][ni], af[mi], bf[ni]);
        }
    }

    if (half_out) {
        __half* C = (__half*)Cv;
#pragma unroll
        for (int mi = 0; mi < 4; mi++) {
            int row = m0 + wm * 64 + mi * 16 + g;
#pragma unroll
            for (int ni = 0; ni < 8; ni++) {
                int col = n0 + wn * 64 + ni * 8 + t * 2;
                *reinterpret_cast<uint32_t*>(&C[(size_t)row * ldc + col]) =
                    fp2h2(acc[mi][ni][0], acc[mi][ni][1]);
                *reinterpret_cast<uint32_t*>(&C[(size_t)(row + 8) * ldc + col]) =
                    fp2h2(acc[mi][ni][2], acc[mi][ni][3]);
            }
        }
    } else {
        float* C = (float*)Cv;
#pragma unroll
        for (int mi = 0; mi < 4; mi++) {
            int row = m0 + wm * 64 + mi * 16 + g;
#pragma unroll
            for (int ni = 0; ni < 8; ni++) {
                int col = n0 + wn * 64 + ni * 8 + t * 2;
                *reinterpret_cast<float2*>(&C[(size_t)row * ldc + col]) =
                    make_float2(acc[mi][ni][0], acc[mi][ni][1]);
                *reinterpret_cast<float2*>(&C[(size_t)(row + 8) * ldc + col]) =
                    make_float2(acc[mi][ni][2], acc[mi][ni][3]);
            }
        }
    }
}

// ---------------- fused RoPE (vectorized) + V transpose --------------------------
#define ROPE_BLOCKS (BATCH * SEQ * (NH + NKV) * 32 / 256)   // 10240
__global__ __launch_bounds__(256)
void rope_vt(const float* __restrict__ cosb, const float* __restrict__ sinb)
{
    __shared__ __half ts[64][72];
    if (blockIdx.x < ROPE_BLOCKS) {
        int i = blockIdx.x * 256 + threadIdx.x;
        int dh2 = i & 31;
        int h  = (i >> 5) % (NH + NKV);
        int bs = (i >> 5) / (NH + NKV);
        uint32_t* p = reinterpret_cast<uint32_t*>(g_qkvh + (size_t)bs * QKV_N + h * HD) + dh2;
        float2 x1 = __half22float2(*reinterpret_cast<__half2*>(&p[0]));
        float2 x2 = __half22float2(*reinterpret_cast<__half2*>(&p[32]));
        const float2* cb = reinterpret_cast<const float2*>(cosb + (size_t)bs * HD);
        const float2* sb = reinterpret_cast<const float2*>(sinb + (size_t)bs * HD);
        float2 c0 = cb[dh2], c1 = cb[dh2 + 32];
        float2 s0 = sb[dh2], s1 = sb[dh2 + 32];
        const float sc = (h < NH) ? 0.08838834764831845f : 1.0f;   // fold 1/sqrt(d) into q
        p[0]  = fp2h2((x1.x * c0.x - x2.x * s0.x) * sc, (x1.y * c0.y - x2.y * s0.y) * sc);
        p[32] = fp2h2((x2.x * c1.x + x1.x * s1.x) * sc, (x2.y * c1.y + x1.y * s1.y) * sc);
    } else {
        int idx = blockIdx.x - ROPE_BLOCKS;      // 0..511
        const int tid = threadIdx.x;
        const int st = idx & 15, yy = idx >> 4;
        const int bkh = yy >> 1, dt = yy & 1;
        const int b = bkh / NKV;
        const __half* src = g_qkvh + ((size_t)(b * SEQ + st * 64)) * QKV_N
                          + NH * HD + NKV * HD + (bkh % NKV) * HD + dt * 64;
#pragma unroll
        for (int i = 0; i < 16; i++) {
            int e = i * 256 + tid;
            int si = e >> 6, di = e & 63;
            ts[si][di] = src[(size_t)si * QKV_N + di];
        }
        __syncthreads();
        __half* dst = g_vt + ((size_t)(bkh * HD + dt * 64)) * SEQ + st * 64;
#pragma unroll
        for (int i = 0; i < 16; i++) {
            int e = i * 256 + tid;
            int di = e >> 6, si = e & 63;
            dst[(size_t)di * SEQ + si] = ts[si][di];
        }
    }
}

// ---------------- flash attention: FBK=128, fp16 mma, causal, GQA ---------------
#define FBQ 128
#define FBK 128
#define QSH 136
#define VSH 136
#define FLASH_SMEM ((128 * QSH + 128 * 128 + 128 * VSH) * 2)   // 102400 B

__global__ __launch_bounds__(256)
void flash_kernel()
{
    extern __shared__ __half smh[];
    __half* Qs = smh;                   // [128][QSH]
    __half* Ks = Qs + 128 * QSH;        // [128][128], chunk-swizzled
    __half* Vs = Ks + 128 * 128;        // [128][VSH]  (V^T: d rows, s inner)

    const int tid  = threadIdx.x;
    const int lane = tid & 31, warp = tid >> 5;
    const int g = lane >> 2, t = lane & 3;
    const int qt = (int)gridDim.x - 1 - (int)blockIdx.x;   // longest CTAs first
    const int h = blockIdx.y, b = blockIdx.z;
    const int q0 = qt * FBQ;
    const int kh = h / NREP;
    const int r0 = warp * 16;

    const __half* Qg  = g_qkvh + ((size_t)(b * SEQ + q0)) * QKV_N + h * HD;
    const __half* Kb  = g_qkvh + (size_t)b * SEQ * QKV_N + NH * HD + kh * HD;
    const __half* Vtb = g_vt + ((size_t)(b * NKV + kh)) * HD * SEQ;

    auto issueKV = [&](int kt) {
        const __half* Kg = Kb + (size_t)(kt * FBK) * QKV_N;
#pragma unroll
        for (int i = 0; i < 8; i++) {
            int l = i * 256 + tid;
            int r = l >> 4, cs = l & 15;
            cp16(smem_u32(Ks + r * 128 + ((cs ^ (r & 7)) << 3)), Kg + (size_t)r * QKV_N + cs * 8);
        }
        const __half* Vg = Vtb + kt * FBK;
#pragma unroll
        for (int i = 0; i < 8; i++) {
            int l = i * 256 + tid;
            int r = l >> 4, c = (l & 15) << 3;
            cp16(smem_u32(Vs + r * VSH + c), Vg + (size_t)r * SEQ + c);
        }
    };

#pragma unroll
    for (int i = 0; i < 8; i++) {
        int l = i * 256 + tid;
        int r = l >> 4, c = (l & 15) << 3;
        cp16(smem_u32(Qs + r * QSH + c), Qg + (size_t)r * QKV_N + c);
    }
    issueKV(0);
    CP_COMMIT();

    float o[16][4];
#pragma unroll
    for (int n = 0; n < 16; n++)
#pragma unroll
        for (int r = 0; r < 4; r++) o[n][r] = 0.f;
    float mrow[2] = {-1e30f, -1e30f};
    float lrow[2] = {0.f, 0.f};

    const int nkt = qt + 1;
    for (int kt = 0; kt < nkt; kt++) {
        CP_WAIT(0);
        __syncthreads();

        // S = Q @ K^T  (Q pre-scaled by 1/sqrt(d))
        float s[16][4];
#pragma unroll
        for (int j = 0; j < 16; j++)
#pragma unroll
            for (int r = 0; r < 4; r++) s[j][r] = 0.f;
#pragma unroll
        for (int ks = 0; ks < 8; ks++) {
            uint32_t af[4];
            const int rr = r0 + g, cc = ks * 16 + 2 * t;
            af[0] = *reinterpret_cast<const uint32_t*>(&Qs[rr * QSH + cc]);
            af[1] = *reinterpret_cast<const uint32_t*>(&Qs[(rr + 8) * QSH + cc]);
            af[2] = *reinterpret_cast<const uint32_t*>(&Qs[rr * QSH + cc + 8]);
            af[3] = *reinterpret_cast<const uint32_t*>(&Qs[(rr + 8) * QSH + cc + 8]);
#pragma unroll
            for (int j = 0; j < 16; j++) {
                const int kr = j * 8 + g;
                const int base = kr * 128 + 2 * t;
                uint32_t bf[2];
                bf[0] = *reinterpret_cast<const uint32_t*>(&Ks[base + (((2 * ks)     ^ g) << 3)]);
                bf[1] = *reinterpret_cast<const uint32_t*>(&Ks[base + (((2 * ks + 1) ^ g) << 3)]);
                mma16h(s[j], af, bf);
            }
        }

        // online softmax; mask only the single diagonal tile
        const int row_lo = q0 + r0 + g;
        float nm[2] = {mrow[0], mrow[1]};
        if (kt == qt) {
            const int k0 = kt * FBK;
#pragma unroll
            for (int j = 0; j < 16; j++) {
                int col = k0 + j * 8 + 2 * t;
                s[j][0] = (col     <= row_lo)     ? s[j][0] : -1e30f;
                s[j][1] = (col + 1 <= row_lo)     ? s[j][1] : -1e30f;
                s[j][2] = (col     <= row_lo + 8) ? s[j][2] : -1e30f;
                s[j][3] = (col + 1 <= row_lo + 8) ? s[j][3] : -1e30f;
            }
        }
#pragma unroll
        for (int j = 0; j < 16; j++) {
            nm[0] = fmaxf(nm[0], fmaxf(s[j][0], s[j][1]));
            nm[1] = fmaxf(nm[1], fmaxf(s[j][2], s[j][3]));
        }
#pragma unroll
        for (int d = 1; d < 4; d <<= 1) {
            nm[0] = fmaxf(nm[0], __shfl_xor_sync(0xffffffffu, nm[0], d));
            nm[1] = fmaxf(nm[1], __shfl_xor_sync(0xffffffffu, nm[1], d));
        }
        float alpha0 = __expf(mrow[0] - nm[0]);
        float alpha1 = __expf(mrow[1] - nm[1]);
        mrow[0] = nm[0]; mrow[1] = nm[1];
        float rs0 = 0.f, rs1 = 0.f;
#pragma unroll
        for (int j = 0; j < 16; j++) {
            s[j][0] = __expf(s[j][0] - nm[0]);
            s[j][1] = __expf(s[j][1] - nm[0]);
            s[j][2] = __expf(s[j][2] - nm[1]);
            s[j][3] = __expf(s[j][3] - nm[1]);
            rs0 += s[j][0] + s[j][1];
            rs1 += s[j][2] + s[j][3];
        }
#pragma unroll
        for (int d = 1; d < 4; d <<= 1) {
            rs0 += __shfl_xor_sync(0xffffffffu, rs0, d);
            rs1 += __shfl_xor_sync(0xffffffffu, rs1, d);
        }
        lrow[0] = lrow[0] * alpha0 + rs0;
        lrow[1] = lrow[1] * alpha1 + rs1;
#pragma unroll
        for (int n = 0; n < 16; n++) {
            o[n][0] *= alpha0; o[n][1] *= alpha0;
            o[n][2] *= alpha1; o[n][3] *= alpha1;
        }

        // O += P @ V  (P converted to fp16 inline)
#pragma unroll
        for (int ks = 0; ks < 8; ks++) {
            uint32_t af[4];
            af[0] = fp2h2(s[2 * ks][0],     s[2 * ks][1]);
            af[1] = fp2h2(s[2 * ks][2],     s[2 * ks][3]);
            af[2] = fp2h2(s[2 * ks + 1][0], s[2 * ks + 1][1]);
            af[3] = fp2h2(s[2 * ks + 1][2], s[2 * ks + 1][3]);
            const int cc = ks * 16 + 2 * t;
#pragma unroll
            for (int n = 0; n < 16; n++) {
                const int d = n * 8 + g;
                uint32_t bf[2];
                bf[0] = *reinterpret_cast<const uint32_t*>(&Vs[d * VSH + cc]);
                bf[1] = *reinterpret_cast<const uint32_t*>(&Vs[d * VSH + cc + 8]);
                mma16h(o[n], af, bf);
            }
        }

        __syncthreads();
        if (kt + 1 < nkt) issueKV(kt + 1);
        CP_COMMIT();
    }

    // normalize + write g_attnh row-major fp16 (A operand of the O-proj GEMM)
    float inv0 = 1.f / lrow[0], inv1 = 1.f / lrow[1];
    __half* Og = g_attnh + (size_t)(b * SEQ + q0 + r0 + g) * (NH * HD) + h * HD;
#pragma unroll
    for (int n = 0; n < 16; n++) {
        int col = n * 8 + 2 * t;
        *reinterpret_cast<uint32_t*>(&Og[col]) = fp2h2(o[n][0] * inv0, o[n][1] * inv0);
        *reinterpret_cast<uint32_t*>(&Og[(size_t)8 * NH * HD + col]) =
            fp2h2(o[n][2] * inv1, o[n][3] * inv1);
    }
}

// ---------------- launch ----------------
extern "C" void kernel_launch(void* const* d_in, const int* in_sizes, int n_in,
                              void* d_out, int out_size)
{
    const float* hs   = (const float*)d_in[0];
    const float* cosb = (const float*)d_in[1];
    const float* sinb = (const float*)d_in[2];
    // d_in[3] = attention_mask (pure causal; applied analytically in-kernel)
    const float* Wq = (const float*)d_in[4];
    const float* Wk = (const float*)d_in[5];
    const float* Wv = (const float*)d_in[6];
    const float* Wo = (const float*)d_in[7];
    float* out = (float*)d_out;

    __half *hshp, *whp, *wohp, *qkvh, *attnp;
    cudaGetSymbolAddress((void**)&hshp,  g_hsh);
    cudaGetSymbolAddress((void**)&whp,   g_wh);
    cudaGetSymbolAddress((void**)&wohp,  g_woh);
    cudaGetSymbolAddress((void**)&qkvh,  g_qkvh);
    cudaGetSymbolAddress((void**)&attnp, g_attnh);

    cudaFuncSetAttribute(gemm_h, cudaFuncAttributeMaxDynamicSharedMemorySize, GEMM_SMEM);
    cudaFuncSetAttribute(flash_kernel, cudaFuncAttributeMaxDynamicSharedMemorySize, FLASH_SMEM);

    const int M = BATCH * SEQ;

    // prep: pure streaming fp32->fp16
    cvt_all<<<CVT_BLOCKS, 256>>>(hs, Wq, Wk, Wv, Wo);

    // fused QKV projection -> fp16 g_qkvh
    gemm_h<<<dim3(QKV_N / 256, M / 128), 256, GEMM_SMEM>>>(hshp, whp, qkvh, QKV_N, QKV_N, 1);

    // fused vectorized RoPE (q scaled by 1/sqrt(d)) + V^T
    rope_vt<<<ROPE_BLOCKS + 512, 256>>>(cosb, sinb);

    flash_kernel<<<dim3(SEQ / FBQ, NH, BATCH), 256, FLASH_SMEM>>>();

    // output projection: out = attn @ Wo, fp32 output
    gemm_h<<<dim3(HID / 256, M / 128), 256, GEMM_SMEM>>>(attnp, wohp, out, HID, HID, 0);
}

// round 12
// speedup vs baseline: 3.0370x; 1.0057x over previous
#include <cuda_runtime.h>
#include <cuda_fp16.h>
#include <cstdint>

#define BATCH 2
#define SEQ   1024
#define HID   4096
#define NH    32
#define NKV   8
#define HD    128
#define NREP  4
#define QKV_N (NH * HD + 2 * NKV * HD)   // 6144
#define KDIM  4096
#define KC    (KDIM / 64)                // 64 k-chunks of 64

// ---------------- scratch (device globals; no allocation allowed) ----------------
__device__ __half g_hsh  [BATCH * SEQ * HID];        // hs fp16 [2048][4096]
__device__ __half g_wh   [KDIM * QKV_N];             // [Wq|Wk|Wv] fp16 [4096][6144]
__device__ __half g_woh  [KDIM * HID];               // Wo fp16 [4096][4096]
__device__ __half g_qkvh [BATCH * SEQ * QKV_N];      // fp16 row-major: q|k|v
__device__ __half g_vt   [BATCH * NKV * HD * SEQ];   // V^T: [b][kh][d][s]
__device__ __half g_attnh[BATCH * SEQ * NH * HD];    // attn fp16 [2048][4096]

// ---------------- helpers ----------------
__device__ __forceinline__ uint32_t fp2h2(float lo, float hi) {
    __half2 h = __floats2half2_rn(lo, hi);
    return *reinterpret_cast<uint32_t*>(&h);
}
__device__ __forceinline__ uint32_t smem_u32(const void* p) {
    uint32_t a;
    asm("{ .reg .u64 t; cvta.to.shared.u64 t, %1; cvt.u32.u64 %0, t; }" : "=r"(a) : "l"(p));
    return a;
}
__device__ __forceinline__ void cp16(uint32_t dst, const void* src) {
    asm volatile("cp.async.cg.shared.global [%0], [%1], 16;" :: "r"(dst), "l"(src));
}
#define CP_COMMIT() asm volatile("cp.async.commit_group;" ::: "memory")
#define CP_WAIT(n)  asm volatile("cp.async.wait_group %0;" :: "n"(n) : "memory")

__device__ __forceinline__ void ldsm4(uint32_t* r, uint32_t a) {
    asm volatile("ldmatrix.sync.aligned.m8n8.x4.shared.b16 {%0,%1,%2,%3}, [%4];"
        : "=r"(r[0]), "=r"(r[1]), "=r"(r[2]), "=r"(r[3]) : "r"(a));
}
__device__ __forceinline__ void ldsm4t(uint32_t* r, uint32_t a) {
    asm volatile("ldmatrix.sync.aligned.m8n8.x4.trans.shared.b16 {%0,%1,%2,%3}, [%4];"
        : "=r"(r[0]), "=r"(r[1]), "=r"(r[2]), "=r"(r[3]) : "r"(a));
}

// fp16 mma m16n8k16, fp32 accum
__device__ __forceinline__ void mma16h(float* d, const uint32_t* a, const uint32_t* b) {
    asm volatile(
        "mma.sync.aligned.m16n8k16.row.col.f32.f16.f16.f32 "
        "{%0,%1,%2,%3}, {%4,%5,%6,%7}, {%8,%9}, {%0,%1,%2,%3};\n"
        : "+f"(d[0]), "+f"(d[1]), "+f"(d[2]), "+f"(d[3])
        : "r"(a[0]), "r"(a[1]), "r"(a[2]), "r"(a[3]), "r"(b[0]), "r"(b[1]));
}

// ---------------- prep: pure streaming fp32 -> fp16 conversion -------------------
#define HS_E (BATCH * SEQ * HID)        // 8388608
#define W_E  (KDIM * QKV_N)             // 25165824
#define WO_E (KDIM * HID)               // 16777216
#define CVT_BLOCKS ((HS_E + W_E + WO_E) / 8 / 256)   // 24576

__global__ __launch_bounds__(256)
void cvt_all(const float* __restrict__ hs,
             const float* __restrict__ Wq, const float* __restrict__ Wk,
             const float* __restrict__ Wv, const float* __restrict__ Wo)
{
    size_t i8 = ((size_t)blockIdx.x * 256 + threadIdx.x) * 8;
    const float* src;
    __half* dst;
    if (i8 < HS_E) {
        src = hs + i8;
        dst = g_hsh + i8;
    } else if (i8 < (size_t)HS_E + W_E) {
        size_t off = i8 - HS_E;
        int k = (int)(off / QKV_N), c = (int)(off % QKV_N);
        if (c < NH * HD)                 src = Wq + (size_t)k * (NH * HD) + c;
        else if (c < NH * HD + NKV * HD) src = Wk + (size_t)k * (NKV * HD) + (c - NH * HD);
        else                             src = Wv + (size_t)k * (NKV * HD) + (c - NH * HD - NKV * HD);
        dst = g_wh + off;
    } else {
        size_t off = i8 - HS_E - W_E;
        src = Wo + off;
        dst = g_woh + off;
    }
    float4 a = *reinterpret_cast<const float4*>(src);
    float4 b = *reinterpret_cast<const float4*>(src + 4);
    uint4 o;
    o.x = fp2h2(a.x, a.y); o.y = fp2h2(a.z, a.w);
    o.z = fp2h2(b.x, b.y); o.w = fp2h2(b.z, b.w);
    *reinterpret_cast<uint4*>(dst) = o;
}

// ---------------- fp16 GEMM via ldmatrix: block 128x256, warp 64x64, 4 stages ----
#define STG_B 49152
#define NSTAGE 4
#define GEMM_SMEM (NSTAGE * STG_B)      // 196608 B

__global__ __launch_bounds__(256, 1)
void gemm_h(const __half* __restrict__ Ap, const __half* __restrict__ Bp,
            void* __restrict__ Cv, int ldb, int ldc, int half_out)
{
    extern __shared__ char smc[];
    const uint32_t sb = smem_u32(smc);
    const int tid  = threadIdx.x;
    const int lane = tid & 31, warp = tid >> 5;
    const int wm = warp >> 2, wn = warp & 3;
    const int g = lane >> 2, t = lane & 3;
    const int m0 = blockIdx.y * 128, n0 = blockIdx.x * 256;

    float acc[4][8][4];
#pragma unroll
    for (int i = 0; i < 4; i++)
#pragma unroll
        for (int j = 0; j < 8; j++)
#pragma unroll
            for (int r = 0; r < 4; r++) acc[i][j][r] = 0.f;

    auto loadChunk = [&](int st, int kt) {
        uint32_t As = sb + st * STG_B;
        uint32_t Bs = As + 16384;
        const __half* Ag = Ap + (size_t)m0 * KDIM + kt * 64;
#pragma unroll
        for (int i = 0; i < 4; i++) {
            int l = i * 256 + tid;
            int r = l >> 3, u = l & 7;
            cp16(As + r * 128 + ((u ^ (r & 7)) << 4), Ag + (size_t)r * KDIM + u * 8);
        }
        const __half* Bg = Bp + (size_t)(kt * 64) * ldb + n0;
#pragma unroll
        for (int i = 0; i < 8; i++) {
            int l = i * 256 + tid;
            int r = l >> 5, u = l & 31;
            cp16(Bs + r * 512 + ((u ^ (r & 7)) << 4), Bg + (size_t)r * ldb + u * 8);
        }
    };

    const int jA  = lane >> 3;
    const int rAl = (lane & 7) + (jA & 1) * 8;
    const int uhA = jA >> 1;
    const int e7a = rAl & 7;
    uint32_t aoff[4];
#pragma unroll
    for (int mi = 0; mi < 4; mi++) aoff[mi] = (uint32_t)(wm * 64 + mi * 16 + rAl) * 128;
    const int kbB = (lane & 7) + ((lane >> 3) & 1) * 8;
    const uint32_t bro = (uint32_t)kbB * 512;
    const int e7b = lane & 7;
    const int nhB = (lane >> 4) & 1;
    uint32_t ub[4];
#pragma unroll
    for (int nip = 0; nip < 4; nip++)
        ub[nip] = (uint32_t)(((wn * 8 + nip * 2 + nhB) ^ e7b) << 4);

    loadChunk(0, 0); CP_COMMIT();
    loadChunk(1, 1); CP_COMMIT();
    loadChunk(2, 2); CP_COMMIT();

    for (int c = 0; c < KC; c++) {
        CP_WAIT(2);
        __syncthreads();
        if (c + 3 < KC) loadChunk((c + 3) % NSTAGE, c + 3);
        CP_COMMIT();

        const uint32_t As = sb + (c % NSTAGE) * STG_B;
        const uint32_t Bs = As + 16384;
#pragma unroll
        for (int ks = 0; ks < 4; ks++) {
            const uint32_t axor = (uint32_t)(((2 * ks + uhA) ^ e7a) << 4);
            uint32_t af[4][4];
#pragma unroll
            for (int mi = 0; mi < 4; mi++)
                ldsm4(af[mi], As + aoff[mi] + axor);
            uint32_t bf[8][2];
#pragma unroll
            for (int nip = 0; nip < 4; nip++) {
                uint32_t r4[4];
                ldsm4t(r4, Bs + (uint32_t)(ks * 8192) + bro + ub[nip]);
                bf[2 * nip][0]     = r4[0]; bf[2 * nip][1]     = r4[1];
                bf[2 * nip + 1][0] = r4[2]; bf[2 * nip + 1][1] = r4[3];
            }
#pragma unroll
            for (int mi = 0; mi < 4; mi++)
#pragma unroll
                for (int ni = 0; ni < 8; ni++)
                    mma16h(acc[mi][ni], af[mi], bf[ni]);
        }
    }

    if (half_out) {
        __half* C = (__half*)Cv;
#pragma unroll
        for (int mi = 0; mi < 4; mi++) {
            int row = m0 + wm * 64 + mi * 16 + g;
#pragma unroll
            for (int ni = 0; ni < 8; ni++) {
                int col = n0 + wn * 64 + ni * 8 + t * 2;
                *reinterpret_cast<uint32_t*>(&C[(size_t)row * ldc + col]) =
                    fp2h2(acc[mi][ni][0], acc[mi][ni][1]);
                *reinterpret_cast<uint32_t*>(&C[(size_t)(row + 8) * ldc + col]) =
                    fp2h2(acc[mi][ni][2], acc[mi][ni][3]);
            }
        }
    } else {
        float* C = (float*)Cv;
#pragma unroll
        for (int mi = 0; mi < 4; mi++) {
            int row = m0 + wm * 64 + mi * 16 + g;
#pragma unroll
            for (int ni = 0; ni < 8; ni++) {
                int col = n0 + wn * 64 + ni * 8 + t * 2;
                *reinterpret_cast<float2*>(&C[(size_t)row * ldc + col]) =
                    make_float2(acc[mi][ni][0], acc[mi][ni][1]);
                *reinterpret_cast<float2*>(&C[(size_t)(row + 8) * ldc + col]) =
                    make_float2(acc[mi][ni][2], acc[mi][ni][3]);
            }
        }
    }
}

// ---------------- fused RoPE (vectorized) + V transpose --------------------------
// q heads folded by (1/sqrt(d)) * log2(e) so flash can use exp2f directly.
#define ROPE_BLOCKS (BATCH * SEQ * (NH + NKV) * 32 / 256)   // 10240
__global__ __launch_bounds__(256)
void rope_vt(const float* __restrict__ cosb, const float* __restrict__ sinb)
{
    __shared__ __half ts[64][72];
    if (blockIdx.x < ROPE_BLOCKS) {
        int i = blockIdx.x * 256 + threadIdx.x;
        int dh2 = i & 31;
        int h  = (i >> 5) % (NH + NKV);
        int bs = (i >> 5) / (NH + NKV);
        uint32_t* p = reinterpret_cast<uint32_t*>(g_qkvh + (size_t)bs * QKV_N + h * HD) + dh2;
        float2 x1 = __half22float2(*reinterpret_cast<__half2*>(&p[0]));
        float2 x2 = __half22float2(*reinterpret_cast<__half2*>(&p[32]));
        const float2* cb = reinterpret_cast<const float2*>(cosb + (size_t)bs * HD);
        const float2* sb = reinterpret_cast<const float2*>(sinb + (size_t)bs * HD);
        float2 c0 = cb[dh2], c1 = cb[dh2 + 32];
        float2 s0 = sb[dh2], s1 = sb[dh2 + 32];
        const float sc = (h < NH) ? 0.08838834764831845f * 1.44269504088896f : 1.0f;
        p[0]  = fp2h2((x1.x * c0.x - x2.x * s0.x) * sc, (x1.y * c0.y - x2.y * s0.y) * sc);
        p[32] = fp2h2((x2.x * c1.x + x1.x * s1.x) * sc, (x2.y * c1.y + x1.y * s1.y) * sc);
    } else {
        int idx = blockIdx.x - ROPE_BLOCKS;      // 0..511
        const int tid = threadIdx.x;
        const int st = idx & 15, yy = idx >> 4;
        const int bkh = yy >> 1, dt = yy & 1;
        const int b = bkh / NKV;
        const __half* src = g_qkvh + ((size_t)(b * SEQ + st * 64)) * QKV_N
                          + NH * HD + NKV * HD + (bkh % NKV) * HD + dt * 64;
#pragma unroll
        for (int i = 0; i < 16; i++) {
            int e = i * 256 + tid;
            int si = e >> 6, di = e & 63;
            ts[si][di] = src[(size_t)si * QKV_N + di];
        }
        __syncthreads();
        __half* dst = g_vt + ((size_t)(bkh * HD + dt * 64)) * SEQ + st * 64;
#pragma unroll
        for (int i = 0; i < 16; i++) {
            int e = i * 256 + tid;
            int di = e >> 6, si = e & 63;
            dst[(size_t)di * SEQ + si] = ts[si][di];
        }
    }
}

// ---------------- flash attention: FBQ=64, FBK=128, 128 thr, 2 CTA/SM ------------
#define FBQ 64
#define FBK 128
#define QSH 136
#define VSH 136
#define FLASH_SMEM ((64 * QSH + 128 * 128 + 128 * VSH) * 2)   // 84992 B

__global__ __launch_bounds__(128)
void flash_kernel()
{
    extern __shared__ __half smh[];
    __half* Qs = smh;                   // [64][QSH]
    __half* Ks = Qs + 64 * QSH;         // [128][128], chunk-swizzled
    __half* Vs = Ks + 128 * 128;        // [128][VSH]  (V^T: d rows, s inner)

    const int tid  = threadIdx.x;
    const int lane = tid & 31, warp = tid >> 5;
    const int g = lane >> 2, t = lane & 3;
    const int qt = (int)gridDim.x - 1 - (int)blockIdx.x;   // longest CTAs first
    const int h = blockIdx.y, b = blockIdx.z;
    const int q0 = qt * FBQ;
    const int kh = h / NREP;
    const int r0 = warp * 16;

    const __half* Qg  = g_qkvh + ((size_t)(b * SEQ + q0)) * QKV_N + h * HD;
    const __half* Kb  = g_qkvh + (size_t)b * SEQ * QKV_N + NH * HD + kh * HD;
    const __half* Vtb = g_vt + ((size_t)(b * NKV + kh)) * HD * SEQ;

    auto issueKV = [&](int kt) {
        const __half* Kg = Kb + (size_t)(kt * FBK) * QKV_N;
#pragma unroll
        for (int i = 0; i < 16; i++) {         // K: 128 rows x 16 swizzled units
            int l = i * 128 + tid;
            int r = l >> 4, cs = l & 15;
            cp16(smem_u32(Ks + r * 128 + ((cs ^ (r & 7)) << 3)), Kg + (size_t)r * QKV_N + cs * 8);
        }
        const __half* Vg = Vtb + kt * FBK;
#pragma unroll
        for (int i = 0; i < 16; i++) {         // V^T: 128 d-rows x 128 s-cols
            int l = i * 128 + tid;
            int r = l >> 4, c = (l & 15) << 3;
            cp16(smem_u32(Vs + r * VSH + c), Vg + (size_t)r * SEQ + c);
        }
    };

#pragma unroll
    for (int i = 0; i < 8; i++) {              // Q: 64 rows x 128 halves
        int l = i * 128 + tid;
        int r = l >> 4, c = (l & 15) << 3;
        cp16(smem_u32(Qs + r * QSH + c), Qg + (size_t)r * QKV_N + c);
    }
    issueKV(0);
    CP_COMMIT();

    float o[16][4];
#pragma unroll
    for (int n = 0; n < 16; n++)
#pragma unroll
        for (int r = 0; r < 4; r++) o[n][r] = 0.f;
    float mrow[2] = {-1e30f, -1e30f};
    float lrow[2] = {0.f, 0.f};

    const int nkt = (qt >> 1) + 1;
    for (int kt = 0; kt < nkt; kt++) {
        CP_WAIT(0);
        __syncthreads();

        // S = Q @ K^T  (Q pre-scaled by log2e/sqrt(d))
        float s[16][4];
#pragma unroll
        for (int j = 0; j < 16; j++)
#pragma unroll
            for (int r = 0; r < 4; r++) s[j][r] = 0.f;
#pragma unroll
        for (int ks = 0; ks < 8; ks++) {
            uint32_t af[4];
            const int rr = r0 + g, cc = ks * 16 + 2 * t;
            af[0] = *reinterpret_cast<const uint32_t*>(&Qs[rr * QSH + cc]);
            af[1] = *reinterpret_cast<const uint32_t*>(&Qs[(rr + 8) * QSH + cc]);
            af[2] = *reinterpret_cast<const uint32_t*>(&Qs[rr * QSH + cc + 8]);
            af[3] = *reinterpret_cast<const uint32_t*>(&Qs[(rr + 8) * QSH + cc + 8]);
#pragma unroll
            for (int j = 0; j < 16; j++) {
                const int kr = j * 8 + g;
                const int base = kr * 128 + 2 * t;
                uint32_t bf[2];
                bf[0] = *reinterpret_cast<const uint32_t*>(&Ks[base + (((2 * ks)     ^ g) << 3)]);
                bf[1] = *reinterpret_cast<const uint32_t*>(&Ks[base + (((2 * ks + 1) ^ g) << 3)]);
                mma16h(s[j], af, bf);
            }
        }

        // online softmax (base-2); mask only the diagonal k-tile
        const int row_lo = q0 + r0 + g;
        float nm[2] = {mrow[0], mrow[1]};
        if (kt == (qt >> 1)) {
            const int k0 = kt * FBK;
#pragma unroll
            for (int j = 0; j < 16; j++) {
                int col = k0 + j * 8 + 2 * t;
                s[j][0] = (col     <= row_lo)     ? s[j][0] : -1e30f;
                s[j][1] = (col + 1 <= row_lo)     ? s[j][1] : -1e30f;
                s[j][2] = (col     <= row_lo + 8) ? s[j][2] : -1e30f;
                s[j][3] = (col + 1 <= row_lo + 8) ? s[j][3] : -1e30f;
            }
        }
#pragma unroll
        for (int j = 0; j < 16; j++) {
            nm[0] = fmaxf(nm[0], fmaxf(s[j][0], s[j][1]));
            nm[1] = fmaxf(nm[1], fmaxf(s[j][2], s[j][3]));
        }
#pragma unroll
        for (int d = 1; d < 4; d <<= 1) {
            nm[0] = fmaxf(nm[0], __shfl_xor_sync(0xffffffffu, nm[0], d));
            nm[1] = fmaxf(nm[1], __shfl_xor_sync(0xffffffffu, nm[1], d));
        }
        float alpha0 = exp2f(mrow[0] - nm[0]);
        float alpha1 = exp2f(mrow[1] - nm[1]);
        mrow[0] = nm[0]; mrow[1] = nm[1];
        float rs0 = 0.f, rs1 = 0.f;
#pragma unroll
        for (int j = 0; j < 16; j++) {
            s[j][0] = exp2f(s[j][0] - nm[0]);
            s[j][1] = exp2f(s[j][1] - nm[0]);
            s[j][2] = exp2f(s[j][2] - nm[1]);
            s[j][3] = exp2f(s[j][3] - nm[1]);
            rs0 += s[j][0] + s[j][1];
            rs1 += s[j][2] + s[j][3];
        }
#pragma unroll
        for (int d = 1; d < 4; d <<= 1) {
            rs0 += __shfl_xor_sync(0xffffffffu, rs0, d);
            rs1 += __shfl_xor_sync(0xffffffffu, rs1, d);
        }
        lrow[0] = lrow[0] * alpha0 + rs0;
        lrow[1] = lrow[1] * alpha1 + rs1;
#pragma unroll
        for (int n = 0; n < 16; n++) {
            o[n][0] *= alpha0; o[n][1] *= alpha0;
            o[n][2] *= alpha1; o[n][3] *= alpha1;
        }

        // O += P @ V  (P converted to fp16 inline)
#pragma unroll
        for (int ks = 0; ks < 8; ks++) {
            uint32_t af[4];
            af[0] = fp2h2(s[2 * ks][0],     s[2 * ks][1]);
            af[1] = fp2h2(s[2 * ks][2],     s[2 * ks][3]);
            af[2] = fp2h2(s[2 * ks + 1][0], s[2 * ks + 1][1]);
            af[3] = fp2h2(s[2 * ks + 1][2], s[2 * ks + 1][3]);
            const int cc = ks * 16 + 2 * t;
#pragma unroll
            for (int n = 0; n < 16; n++) {
                const int d = n * 8 + g;
                uint32_t bf[2];
                bf[0] = *reinterpret_cast<const uint32_t*>(&Vs[d * VSH + cc]);
                bf[1] = *reinterpret_cast<const uint32_t*>(&Vs[d * VSH + cc + 8]);
                mma16h(o[n], af, bf);
            }
        }

        __syncthreads();
        if (kt + 1 < nkt) issueKV(kt + 1);
        CP_COMMIT();
    }

    // normalize + write g_attnh row-major fp16 (A operand of the O-proj GEMM)
    float inv0 = 1.f / lrow[0], inv1 = 1.f / lrow[1];
    __half* Og = g_attnh + (size_t)(b * SEQ + q0 + r0 + g) * (NH * HD) + h * HD;
#pragma unroll
    for (int n = 0; n < 16; n++) {
        int col = n * 8 + 2 * t;
        *reinterpret_cast<uint32_t*>(&Og[col]) = fp2h2(o[n][0] * inv0, o[n][1] * inv0);
        *reinterpret_cast<uint32_t*>(&Og[(size_t)8 * NH * HD + col]) =
            fp2h2(o[n][2] * inv1, o[n][3] * inv1);
    }
}

// ---------------- launch ----------------
extern "C" void kernel_launch(void* const* d_in, const int* in_sizes, int n_in,
                              void* d_out, int out_size)
{
    const float* hs   = (const float*)d_in[0];
    const float* cosb = (const float*)d_in[1];
    const float* sinb = (const float*)d_in[2];
    // d_in[3] = attention_mask (pure causal; applied analytically in-kernel)
    const float* Wq = (const float*)d_in[4];
    const float* Wk = (const float*)d_in[5];
    const float* Wv = (const float*)d_in[6];
    const float* Wo = (const float*)d_in[7];
    float* out = (float*)d_out;

    __half *hshp, *whp, *wohp, *qkvh, *attnp;
    cudaGetSymbolAddress((void**)&hshp,  g_hsh);
    cudaGetSymbolAddress((void**)&whp,   g_wh);
    cudaGetSymbolAddress((void**)&wohp,  g_woh);
    cudaGetSymbolAddress((void**)&qkvh,  g_qkvh);
    cudaGetSymbolAddress((void**)&attnp, g_attnh);

    cudaFuncSetAttribute(gemm_h, cudaFuncAttributeMaxDynamicSharedMemorySize, GEMM_SMEM);
    cudaFuncSetAttribute(flash_kernel, cudaFuncAttributeMaxDynamicSharedMemorySize, FLASH_SMEM);

    const int M = BATCH * SEQ;

    // prep: pure streaming fp32->fp16
    cvt_all<<<CVT_BLOCKS, 256>>>(hs, Wq, Wk, Wv, Wo);

    // fused QKV projection -> fp16 g_qkvh
    gemm_h<<<dim3(QKV_N / 256, M / 128), 256, GEMM_SMEM>>>(hshp, whp, qkvh, QKV_N, QKV_N, 1);

    // fused vectorized RoPE (q scaled by log2e/sqrt(d)) + V^T
    rope_vt<<<ROPE_BLOCKS + 512, 256>>>(cosb, sinb);

    // flash: 64-row q tiles, 128 threads, 2 CTAs/SM
    flash_kernel<<<dim3(SEQ / FBQ, NH, BATCH), 128, FLASH_SMEM>>>();

    // output projection: out = attn @ Wo, fp32 output
    gemm_h<<<dim3(HID / 256, M / 128), 256, GEMM_SMEM>>>(attnp, wohp, out, HID, HID, 0);
}

// round 13
// speedup vs baseline: 3.1799x; 1.0471x over previous
#include <cuda_runtime.h>
#include <cuda_fp16.h>
#include <cstdint>

#define BATCH 2
#define SEQ   1024
#define HID   4096
#define NH    32
#define NKV   8
#define HD    128
#define NREP  4
#define QKV_N (NH * HD + 2 * NKV * HD)   // 6144
#define KDIM  4096
#define KC    (KDIM / 64)                // 64 k-chunks of 64

// ---------------- scratch (device globals; no allocation allowed) ----------------
__device__ __half g_hsh  [BATCH * SEQ * HID];        // hs fp16 [2048][4096]
__device__ __half g_wh   [KDIM * QKV_N];             // [Wq|Wk|Wv] fp16 [4096][6144]
__device__ __half g_woh  [KDIM * HID];               // Wo fp16 [4096][4096]
__device__ __half g_qkvh [BATCH * SEQ * QKV_N];      // fp16 row-major: q|k|v
__device__ __half g_vt   [BATCH * NKV * HD * SEQ];   // V^T: [b][kh][d][s]
__device__ __half g_attnh[BATCH * SEQ * NH * HD];    // attn fp16 [2048][4096]

// ---------------- helpers ----------------
__device__ __forceinline__ uint32_t fp2h2(float lo, float hi) {
    __half2 h = __floats2half2_rn(lo, hi);
    return *reinterpret_cast<uint32_t*>(&h);
}
__device__ __forceinline__ uint32_t smem_u32(const void* p) {
    uint32_t a;
    asm("{ .reg .u64 t; cvta.to.shared.u64 t, %1; cvt.u32.u64 %0, t; }" : "=r"(a) : "l"(p));
    return a;
}
__device__ __forceinline__ void cp16(uint32_t dst, const void* src) {
    asm volatile("cp.async.cg.shared.global [%0], [%1], 16;" :: "r"(dst), "l"(src));
}
#define CP_COMMIT() asm volatile("cp.async.commit_group;" ::: "memory")
#define CP_WAIT(n)  asm volatile("cp.async.wait_group %0;" :: "n"(n) : "memory")

__device__ __forceinline__ void ldsm4(uint32_t* r, uint32_t a) {
    asm volatile("ldmatrix.sync.aligned.m8n8.x4.shared.b16 {%0,%1,%2,%3}, [%4];"
        : "=r"(r[0]), "=r"(r[1]), "=r"(r[2]), "=r"(r[3]) : "r"(a));
}
__device__ __forceinline__ void ldsm4t(uint32_t* r, uint32_t a) {
    asm volatile("ldmatrix.sync.aligned.m8n8.x4.trans.shared.b16 {%0,%1,%2,%3}, [%4];"
        : "=r"(r[0]), "=r"(r[1]), "=r"(r[2]), "=r"(r[3]) : "r"(a));
}

// fp16 mma m16n8k16, fp32 accum
__device__ __forceinline__ void mma16h(float* d, const uint32_t* a, const uint32_t* b) {
    asm volatile(
        "mma.sync.aligned.m16n8k16.row.col.f32.f16.f16.f32 "
        "{%0,%1,%2,%3}, {%4,%5,%6,%7}, {%8,%9}, {%0,%1,%2,%3};\n"
        : "+f"(d[0]), "+f"(d[1]), "+f"(d[2]), "+f"(d[3])
        : "r"(a[0]), "r"(a[1]), "r"(a[2]), "r"(a[3]), "r"(b[0]), "r"(b[1]));
}

// ---------------- prep: pure streaming fp32 -> fp16 conversion -------------------
#define HS_E (BATCH * SEQ * HID)        // 8388608
#define W_E  (KDIM * QKV_N)             // 25165824
#define WO_E (KDIM * HID)               // 16777216
#define CVT_BLOCKS ((HS_E + W_E + WO_E) / 8 / 256)   // 24576

__global__ __launch_bounds__(256)
void cvt_all(const float* __restrict__ hs,
             const float* __restrict__ Wq, const float* __restrict__ Wk,
             const float* __restrict__ Wv, const float* __restrict__ Wo)
{
    size_t i8 = ((size_t)blockIdx.x * 256 + threadIdx.x) * 8;
    const float* src;
    __half* dst;
    if (i8 < HS_E) {
        src = hs + i8;
        dst = g_hsh + i8;
    } else if (i8 < (size_t)HS_E + W_E) {
        size_t off = i8 - HS_E;
        int k = (int)(off / QKV_N), c = (int)(off % QKV_N);
        if (c < NH * HD)                 src = Wq + (size_t)k * (NH * HD) + c;
        else if (c < NH * HD + NKV * HD) src = Wk + (size_t)k * (NKV * HD) + (c - NH * HD);
        else                             src = Wv + (size_t)k * (NKV * HD) + (c - NH * HD - NKV * HD);
        dst = g_wh + off;
    } else {
        size_t off = i8 - HS_E - W_E;
        src = Wo + off;
        dst = g_woh + off;
    }
    float4 a = *reinterpret_cast<const float4*>(src);
    float4 b = *reinterpret_cast<const float4*>(src + 4);
    uint4 o;
    o.x = fp2h2(a.x, a.y); o.y = fp2h2(a.z, a.w);
    o.z = fp2h2(b.x, b.y); o.w = fp2h2(b.z, b.w);
    *reinterpret_cast<uint4*>(dst) = o;
}

// ---------------- fp16 GEMM: block 128x128, warp 64x32, 3 stages, 2 CTA/SM -------
#define STG_B 32768                     // A 16KB + B 16KB per stage
#define NSTAGE 3
#define GEMM_SMEM (NSTAGE * STG_B)      // 98304 B

__global__ __launch_bounds__(256, 2)
void gemm_h(const __half* __restrict__ Ap, const __half* __restrict__ Bp,
            void* __restrict__ Cv, int ldb, int ldc, int half_out)
{
    extern __shared__ char smc[];
    const uint32_t sb = smem_u32(smc);
    const int tid  = threadIdx.x;
    const int lane = tid & 31, warp = tid >> 5;
    const int wm = warp >> 2, wn = warp & 3;   // 2(m) x 4(n), warp tile 64x32
    const int g = lane >> 2, t = lane & 3;
    const int m0 = blockIdx.y * 128, n0 = blockIdx.x * 128;

    float acc[4][4][4];
#pragma unroll
    for (int i = 0; i < 4; i++)
#pragma unroll
        for (int j = 0; j < 4; j++)
#pragma unroll
            for (int r = 0; r < 4; r++) acc[i][j][r] = 0.f;

    auto loadChunk = [&](int st, int kt) {
        uint32_t As = sb + st * STG_B;
        uint32_t Bs = As + 16384;
        const __half* Ag = Ap + (size_t)m0 * KDIM + kt * 64;
#pragma unroll
        for (int i = 0; i < 4; i++) {               // A: 128 rows x 8 units
            int l = i * 256 + tid;
            int r = l >> 3, u = l & 7;
            cp16(As + r * 128 + ((u ^ (r & 7)) << 4), Ag + (size_t)r * KDIM + u * 8);
        }
        const __half* Bg = Bp + (size_t)(kt * 64) * ldb + n0;
#pragma unroll
        for (int i = 0; i < 4; i++) {               // B: 64 rows x 16 units
            int l = i * 256 + tid;
            int r = l >> 4, u = l & 15;
            cp16(Bs + r * 256 + ((u ^ (r & 7)) << 4), Bg + (size_t)r * ldb + u * 8);
        }
    };

    // per-lane ldmatrix constants
    const int jA  = lane >> 3;
    const int rAl = (lane & 7) + (jA & 1) * 8;
    const int uhA = jA >> 1;
    const int e7a = rAl & 7;
    uint32_t aoff[4];
#pragma unroll
    for (int mi = 0; mi < 4; mi++) aoff[mi] = (uint32_t)(wm * 64 + mi * 16 + rAl) * 128;
    const int kbB = (lane & 7) + ((lane >> 3) & 1) * 8;
    const uint32_t bro = (uint32_t)kbB * 256;
    const int e7b = lane & 7;
    const int nhB = (lane >> 4) & 1;
    uint32_t ub[2];
#pragma unroll
    for (int nip = 0; nip < 2; nip++)
        ub[nip] = (uint32_t)(((wn * 4 + nip * 2 + nhB) ^ e7b) << 4);

    loadChunk(0, 0); CP_COMMIT();
    loadChunk(1, 1); CP_COMMIT();

    for (int c = 0; c < KC; c++) {
        CP_WAIT(1);
        __syncthreads();
        if (c + 2 < KC) loadChunk((c + 2) % NSTAGE, c + 2);
        CP_COMMIT();

        const uint32_t As = sb + (c % NSTAGE) * STG_B;
        const uint32_t Bs = As + 16384;
#pragma unroll
        for (int ks = 0; ks < 4; ks++) {
            const uint32_t axor = (uint32_t)(((2 * ks + uhA) ^ e7a) << 4);
            uint32_t af[4][4];
#pragma unroll
            for (int mi = 0; mi < 4; mi++)
                ldsm4(af[mi], As + aoff[mi] + axor);
            uint32_t bf[4][2];
#pragma unroll
            for (int nip = 0; nip < 2; nip++) {
                uint32_t r4[4];
                ldsm4t(r4, Bs + (uint32_t)(ks * 4096) + bro + ub[nip]);
                bf[2 * nip][0]     = r4[0]; bf[2 * nip][1]     = r4[1];
                bf[2 * nip + 1][0] = r4[2]; bf[2 * nip + 1][1] = r4[3];
            }
#pragma unroll
            for (int mi = 0; mi < 4; mi++)
#pragma unroll
                for (int ni = 0; ni < 4; ni++)
                    mma16h(acc[mi][ni], af[mi], bf[ni]);
        }
    }

    if (half_out) {
        __half* C = (__half*)Cv;
#pragma unroll
        for (int mi = 0; mi < 4; mi++) {
            int row = m0 + wm * 64 + mi * 16 + g;
#pragma unroll
            for (int ni = 0; ni < 4; ni++) {
                int col = n0 + wn * 32 + ni * 8 + t * 2;
                *reinterpret_cast<uint32_t*>(&C[(size_t)row * ldc + col]) =
                    fp2h2(acc[mi][ni][0], acc[mi][ni][1]);
                *reinterpret_cast<uint32_t*>(&C[(size_t)(row + 8) * ldc + col]) =
                    fp2h2(acc[mi][ni][2], acc[mi][ni][3]);
            }
        }
    } else {
        float* C = (float*)Cv;
#pragma unroll
        for (int mi = 0; mi < 4; mi++) {
            int row = m0 + wm * 64 + mi * 16 + g;
#pragma unroll
            for (int ni = 0; ni < 4; ni++) {
                int col = n0 + wn * 32 + ni * 8 + t * 2;
                *reinterpret_cast<float2*>(&C[(size_t)row * ldc + col]) =
                    make_float2(acc[mi][ni][0], acc[mi][ni][1]);
                *reinterpret_cast<float2*>(&C[(size_t)(row + 8) * ldc + col]) =
                    make_float2(acc[mi][ni][2], acc[mi][ni][3]);
            }
        }
    }
}

// ---------------- fused RoPE (vectorized) + V transpose --------------------------
// q heads folded by (1/sqrt(d)) * log2(e) so flash can use exp2f directly.
#define ROPE_BLOCKS (BATCH * SEQ * (NH + NKV) * 32 / 256)   // 10240
__global__ __launch_bounds__(256)
void rope_vt(const float* __restrict__ cosb, const float* __restrict__ sinb)
{
    __shared__ __half ts[64][72];
    if (blockIdx.x < ROPE_BLOCKS) {
        int i = blockIdx.x * 256 + threadIdx.x;
        int dh2 = i & 31;
        int h  = (i >> 5) % (NH + NKV);
        int bs = (i >> 5) / (NH + NKV);
        uint32_t* p = reinterpret_cast<uint32_t*>(g_qkvh + (size_t)bs * QKV_N + h * HD) + dh2;
        float2 x1 = __half22float2(*reinterpret_cast<__half2*>(&p[0]));
        float2 x2 = __half22float2(*reinterpret_cast<__half2*>(&p[32]));
        const float2* cb = reinterpret_cast<const float2*>(cosb + (size_t)bs * HD);
        const float2* sb = reinterpret_cast<const float2*>(sinb + (size_t)bs * HD);
        float2 c0 = cb[dh2], c1 = cb[dh2 + 32];
        float2 s0 = sb[dh2], s1 = sb[dh2 + 32];
        const float sc = (h < NH) ? 0.08838834764831845f * 1.44269504088896f : 1.0f;
        p[0]  = fp2h2((x1.x * c0.x - x2.x * s0.x) * sc, (x1.y * c0.y - x2.y * s0.y) * sc);
        p[32] = fp2h2((x2.x * c1.x + x1.x * s1.x) * sc, (x2.y * c1.y + x1.y * s1.y) * sc);
    } else {
        int idx = blockIdx.x - ROPE_BLOCKS;      // 0..511
        const int tid = threadIdx.x;
        const int st = idx & 15, yy = idx >> 4;
        const int bkh = yy >> 1, dt = yy & 1;
        const int b = bkh / NKV;
        const __half* src = g_qkvh + ((size_t)(b * SEQ + st * 64)) * QKV_N
                          + NH * HD + NKV * HD + (bkh % NKV) * HD + dt * 64;
#pragma unroll
        for (int i = 0; i < 16; i++) {
            int e = i * 256 + tid;
            int si = e >> 6, di = e & 63;
            ts[si][di] = src[(size_t)si * QKV_N + di];
        }
        __syncthreads();
        __half* dst = g_vt + ((size_t)(bkh * HD + dt * 64)) * SEQ + st * 64;
#pragma unroll
        for (int i = 0; i < 16; i++) {
            int e = i * 256 + tid;
            int di = e >> 6, si = e & 63;
            dst[(size_t)di * SEQ + si] = ts[si][di];
        }
    }
}

// ---------------- flash attention: FBQ=64, FBK=128, 128 thr, ldmatrix ------------
#define FBQ 64
#define FBK 128
#define QSH 136
#define VSH 136
#define FLASH_SMEM ((64 * QSH + 128 * 128 + 128 * VSH) * 2)   // 84992 B

__global__ __launch_bounds__(128)
void flash_kernel()
{
    extern __shared__ __half smh[];
    __half* Qs = smh;                   // [64][QSH]
    __half* Ks = Qs + 64 * QSH;         // [128][128], unit-swizzled
    __half* Vs = Ks + 128 * 128;        // [128][VSH]  (V^T: d rows, s inner)

    const int tid  = threadIdx.x;
    const int lane = tid & 31, warp = tid >> 5;
    const int g = lane >> 2, t = lane & 3;
    const int qt = (int)gridDim.x - 1 - (int)blockIdx.x;   // longest CTAs first
    const int h = blockIdx.y, b = blockIdx.z;
    const int q0 = qt * FBQ;
    const int kh = h / NREP;
    const int r0 = warp * 16;

    const __half* Qg  = g_qkvh + ((size_t)(b * SEQ + q0)) * QKV_N + h * HD;
    const __half* Kb  = g_qkvh + (size_t)b * SEQ * QKV_N + NH * HD + kh * HD;
    const __half* Vtb = g_vt + ((size_t)(b * NKV + kh)) * HD * SEQ;

    auto issueKV = [&](int kt) {
        const __half* Kg = Kb + (size_t)(kt * FBK) * QKV_N;
#pragma unroll
        for (int i = 0; i < 16; i++) {         // K: 128 rows x 16 swizzled units
            int l = i * 128 + tid;
            int r = l >> 4, cs = l & 15;
            cp16(smem_u32(Ks + r * 128 + ((cs ^ (r & 7)) << 3)), Kg + (size_t)r * QKV_N + cs * 8);
        }
        const __half* Vg = Vtb + kt * FBK;
#pragma unroll
        for (int i = 0; i < 16; i++) {         // V^T: 128 d-rows x 128 s-cols
            int l = i * 128 + tid;
            int r = l >> 4, c = (l & 15) << 3;
            cp16(smem_u32(Vs + r * VSH + c), Vg + (size_t)r * SEQ + c);
        }
    };

#pragma unroll
    for (int i = 0; i < 8; i++) {              // Q: 64 rows x 128 halves
        int l = i * 128 + tid;
        int r = l >> 4, c = (l & 15) << 3;
        cp16(smem_u32(Qs + r * QSH + c), Qg + (size_t)r * QKV_N + c);
    }
    issueKV(0);
    CP_COMMIT();

    // per-lane ldmatrix address constants
    const int e7  = lane & 7;
    const int kof = (lane >> 3) & 1;
    const uint32_t qb0 = smem_u32(Qs) + (uint32_t)(r0 + e7 + kof * 8) * (QSH * 2)
                       + (uint32_t)(lane >> 4) * 16;
    uint32_t kb[8], vb[8];
#pragma unroll
    for (int i = 0; i < 8; i++) {
        int n = i * 16 + ((lane >> 4) & 1) * 8 + e7;
        kb[i] = smem_u32(Ks) + (uint32_t)n * 256;
        vb[i] = smem_u32(Vs) + (uint32_t)n * (VSH * 2) + (uint32_t)kof * 16;
    }

    float o[16][4];
#pragma unroll
    for (int n = 0; n < 16; n++)
#pragma unroll
        for (int r = 0; r < 4; r++) o[n][r] = 0.f;
    float mrow[2] = {-1e30f, -1e30f};
    float lrow[2] = {0.f, 0.f};

    const int nkt = (qt >> 1) + 1;
    for (int kt = 0; kt < nkt; kt++) {
        CP_WAIT(0);
        __syncthreads();

        // S = Q @ K^T  (ldmatrix operand loads; Q pre-scaled by log2e/sqrt(d))
        float s[16][4];
#pragma unroll
        for (int j = 0; j < 16; j++)
#pragma unroll
            for (int r = 0; r < 4; r++) s[j][r] = 0.f;
#pragma unroll
        for (int ks = 0; ks < 8; ks++) {
            uint32_t af[4];
            ldsm4(af, qb0 + 32 * ks);
            const uint32_t kx = (uint32_t)(((2 * ks + kof) ^ e7) << 4);
#pragma unroll
            for (int i = 0; i < 8; i++) {
                uint32_t r4[4];
                ldsm4(r4, kb[i] + kx);
                mma16h(s[2 * i],     af, r4);
                mma16h(s[2 * i + 1], af, r4 + 2);
            }
        }

        // online softmax (base-2); mask only the diagonal k-tile
        const int row_lo = q0 + r0 + g;
        float nm[2] = {mrow[0], mrow[1]};
        if (kt == (qt >> 1)) {
            const int k0 = kt * FBK;
#pragma unroll
            for (int j = 0; j < 16; j++) {
                int col = k0 + j * 8 + 2 * t;
                s[j][0] = (col     <= row_lo)     ? s[j][0] : -1e30f;
                s[j][1] = (col + 1 <= row_lo)     ? s[j][1] : -1e30f;
                s[j][2] = (col     <= row_lo + 8) ? s[j][2] : -1e30f;
                s[j][3] = (col + 1 <= row_lo + 8) ? s[j][3] : -1e30f;
            }
        }
#pragma unroll
        for (int j = 0; j < 16; j++) {
            nm[0] = fmaxf(nm[0], fmaxf(s[j][0], s[j][1]));
            nm[1] = fmaxf(nm[1], fmaxf(s[j][2], s[j][3]));
        }
#pragma unroll
        for (int dd = 1; dd < 4; dd <<= 1) {
            nm[0] = fmaxf(nm[0], __shfl_xor_sync(0xffffffffu, nm[0], dd));
            nm[1] = fmaxf(nm[1], __shfl_xor_sync(0xffffffffu, nm[1], dd));
        }
        float alpha0 = exp2f(mrow[0] - nm[0]);
        float alpha1 = exp2f(mrow[1] - nm[1]);
        mrow[0] = nm[0]; mrow[1] = nm[1];
        float rs0 = 0.f, rs1 = 0.f;
#pragma unroll
        for (int j = 0; j < 16; j++) {
            s[j][0] = exp2f(s[j][0] - nm[0]);
            s[j][1] = exp2f(s[j][1] - nm[0]);
            s[j][2] = exp2f(s[j][2] - nm[1]);
            s[j][3] = exp2f(s[j][3] - nm[1]);
            rs0 += s[j][0] + s[j][1];
            rs1 += s[j][2] + s[j][3];
        }
#pragma unroll
        for (int dd = 1; dd < 4; dd <<= 1) {
            rs0 += __shfl_xor_sync(0xffffffffu, rs0, dd);
            rs1 += __shfl_xor_sync(0xffffffffu, rs1, dd);
        }
        lrow[0] = lrow[0] * alpha0 + rs0;
        lrow[1] = lrow[1] * alpha1 + rs1;
#pragma unroll
        for (int n = 0; n < 16; n++) {
            o[n][0] *= alpha0; o[n][1] *= alpha0;
            o[n][2] *= alpha1; o[n][3] *= alpha1;
        }

        // O += P @ V  (P fp16 inline; V via ldmatrix)
#pragma unroll
        for (int ks = 0; ks < 8; ks++) {
            uint32_t af[4];
            af[0] = fp2h2(s[2 * ks][0],     s[2 * ks][1]);
            af[1] = fp2h2(s[2 * ks][2],     s[2 * ks][3]);
            af[2] = fp2h2(s[2 * ks + 1][0], s[2 * ks + 1][1]);
            af[3] = fp2h2(s[2 * ks + 1][2], s[2 * ks + 1][3]);
#pragma unroll
            for (int i = 0; i < 8; i++) {
                uint32_t r4[4];
                ldsm4(r4, vb[i] + 32 * ks);
                mma16h(o[2 * i],     af, r4);
                mma16h(o[2 * i + 1], af, r4 + 2);
            }
        }

        __syncthreads();
        if (kt + 1 < nkt) issueKV(kt + 1);
        CP_COMMIT();
    }

    // normalize + write g_attnh row-major fp16 (A operand of the O-proj GEMM)
    float inv0 = 1.f / lrow[0], inv1 = 1.f / lrow[1];
    __half* Og = g_attnh + (size_t)(b * SEQ + q0 + r0 + g) * (NH * HD) + h * HD;
#pragma unroll
    for (int n = 0; n < 16; n++) {
        int col = n * 8 + 2 * t;
        *reinterpret_cast<uint32_t*>(&Og[col]) = fp2h2(o[n][0] * inv0, o[n][1] * inv0);
        *reinterpret_cast<uint32_t*>(&Og[(size_t)8 * NH * HD + col]) =
            fp2h2(o[n][2] * inv1, o[n][3] * inv1);
    }
}

// ---------------- launch ----------------
extern "C" void kernel_launch(void* const* d_in, const int* in_sizes, int n_in,
                              void* d_out, int out_size)
{
    const float* hs   = (const float*)d_in[0];
    const float* cosb = (const float*)d_in[1];
    const float* sinb = (const float*)d_in[2];
    // d_in[3] = attention_mask (pure causal; applied analytically in-kernel)
    const float* Wq = (const float*)d_in[4];
    const float* Wk = (const float*)d_in[5];
    const float* Wv = (const float*)d_in[6];
    const float* Wo = (const float*)d_in[7];
    float* out = (float*)d_out;

    __half *hshp, *whp, *wohp, *qkvh, *attnp;
    cudaGetSymbolAddress((void**)&hshp,  g_hsh);
    cudaGetSymbolAddress((void**)&whp,   g_wh);
    cudaGetSymbolAddress((void**)&wohp,  g_woh);
    cudaGetSymbolAddress((void**)&qkvh,  g_qkvh);
    cudaGetSymbolAddress((void**)&attnp, g_attnh);

    cudaFuncSetAttribute(gemm_h, cudaFuncAttributeMaxDynamicSharedMemorySize, GEMM_SMEM);
    cudaFuncSetAttribute(flash_kernel, cudaFuncAttributeMaxDynamicSharedMemorySize, FLASH_SMEM);

    const int M = BATCH * SEQ;

    // prep: pure streaming fp32->fp16
    cvt_all<<<CVT_BLOCKS, 256>>>(hs, Wq, Wk, Wv, Wo);

    // fused QKV projection -> fp16 g_qkvh
    gemm_h<<<dim3(QKV_N / 128, M / 128), 256, GEMM_SMEM>>>(hshp, whp, qkvh, QKV_N, QKV_N, 1);

    // fused vectorized RoPE (q scaled by log2e/sqrt(d)) + V^T
    rope_vt<<<ROPE_BLOCKS + 512, 256>>>(cosb, sinb);

    // flash: 64-row q tiles, 128 threads, ldmatrix operand loads
    flash_kernel<<<dim3(SEQ / FBQ, NH, BATCH), 128, FLASH_SMEM>>>();

    // output projection: out = attn @ Wo, fp32 output
    gemm_h<<<dim3(HID / 128, M / 128), 256, GEMM_SMEM>>>(attnp, wohp, out, HID, HID, 0);
}